// round 1
// baseline (speedup 1.0000x reference)
#include <cuda_runtime.h>
#include <math.h>

#define B_ 2
#define C_ 2048
#define M_ 1024
#define H_ 16
#define K_ 64
#define V_ 64

// Scratch (no cudaMalloc allowed): 4 x 16MB
__device__ float g_q[(size_t)B_ * H_ * C_ * K_];
__device__ float g_k[(size_t)B_ * H_ * C_ * K_];
__device__ float g_v[(size_t)B_ * H_ * C_ * V_];
__device__ float g_pre[(size_t)B_ * C_ * H_ * V_];

// ---------------------------------------------------------------------------
// Generic 128x64 output-tile fp32 GEMM: O[row][col] = sum_m A[row][m]*W[m][col]
// blockIdx.x -> row tile; blockIdx.y/z apply caller-provided pointer strides.
// 256 threads, each computes 8x4.
// ---------------------------------------------------------------------------
__global__ void __launch_bounds__(256, 4)
gemm128x64_kernel(const float* __restrict__ A, const float* __restrict__ W,
                  float* __restrict__ O,
                  int lda, int ldw, int ldo, int inner,
                  long aStrideZ, long wStrideY, long oStrideY, long oStrideZ)
{
    A += (long)blockIdx.z * aStrideZ;
    W += (long)blockIdx.y * wStrideY;
    O += (long)blockIdx.z * oStrideZ + (long)blockIdx.y * oStrideY;
    const int row0 = blockIdx.x * 128;

    __shared__ float As[16][132];  // [m][row], padded
    __shared__ float Bs[16][68];   // [m][col], padded

    const int tid = threadIdx.x;
    const int ty = tid >> 4;       // 0..15
    const int tx = tid & 15;       // 0..15
    const int rbase = ty * 8;
    const int cbase = tx * 4;

    float acc[8][4];
#pragma unroll
    for (int i = 0; i < 8; i++)
#pragma unroll
        for (int j = 0; j < 4; j++) acc[i][j] = 0.0f;

    for (int m0 = 0; m0 < inner; m0 += 16) {
        // A tile: 128 rows x 16 m = 512 float4, 2 per thread
#pragma unroll
        for (int l = 0; l < 2; l++) {
            int e  = tid + l * 256;      // 0..511
            int ar = e >> 2;             // 0..127
            int am = (e & 3) * 4;        // 0,4,8,12
            float4 v = *reinterpret_cast<const float4*>(
                A + (long)(row0 + ar) * lda + m0 + am);
            As[am + 0][ar] = v.x;
            As[am + 1][ar] = v.y;
            As[am + 2][ar] = v.z;
            As[am + 3][ar] = v.w;
        }
        // W tile: 16 m x 64 cols = 256 float4, 1 per thread
        {
            int mm  = tid >> 4;          // 0..15
            int kk4 = (tid & 15) * 4;    // 0..60
            float4 v = *reinterpret_cast<const float4*>(
                W + (long)(m0 + mm) * ldw + kk4);
            *reinterpret_cast<float4*>(&Bs[mm][kk4]) = v;
        }
        __syncthreads();

#pragma unroll
        for (int mm = 0; mm < 16; mm++) {
            float4 a0 = *reinterpret_cast<const float4*>(&As[mm][rbase]);
            float4 a1 = *reinterpret_cast<const float4*>(&As[mm][rbase + 4]);
            float4 b4 = *reinterpret_cast<const float4*>(&Bs[mm][cbase]);
            float a[8] = {a0.x, a0.y, a0.z, a0.w, a1.x, a1.y, a1.z, a1.w};
            float bv[4] = {b4.x, b4.y, b4.z, b4.w};
#pragma unroll
            for (int i = 0; i < 8; i++)
#pragma unroll
                for (int j = 0; j < 4; j++)
                    acc[i][j] = fmaf(a[i], bv[j], acc[i][j]);
        }
        __syncthreads();
    }

#pragma unroll
    for (int i = 0; i < 8; i++) {
        float4 v = make_float4(acc[i][0], acc[i][1], acc[i][2], acc[i][3]);
        *reinterpret_cast<float4*>(O + (long)(row0 + rbase + i) * ldo + cbase) = v;
    }
}

// ---------------------------------------------------------------------------
// Flash-style attention per (b, h): 64 queries per block, stream 64-key tiles.
// Reference semantics: S[d][c] = q_d . k_c ; mask: S += -100 where c <= d ;
// softmax over keys of S * 0.125 ; O[d][v] = sum_c P[d][c] * V[c][v].
// pre stored as [b][d][h*V+v] for the output GEMM.
// ---------------------------------------------------------------------------
__global__ void __launch_bounds__(256, 2)
attn_kernel()
{
    const int b  = blockIdx.z;
    const int h  = blockIdx.y;
    const int d0 = blockIdx.x * 64;

    extern __shared__ float smem[];
    float* Qts  = smem;             // [64 k][68]: Qts[k][d]
    float* Kts  = Qts + 64 * 68;    // [64 k][68]: Kts[k][c]
    float* Vs   = Kts + 64 * 68;    // [64 c][68]: Vs[c][v]
    float* Ss   = Vs  + 64 * 68;    // [64 d][65]: Ss[d][c] (stride 65 -> cf-free rows)
    float* sm_m = Ss  + 64 * 65;    // [64]
    float* sm_l = sm_m + 64;        // [64]
    float* sm_a = sm_l + 64;        // [64]

    const int tid = threadIdx.x;
    const int ty  = tid >> 4;       // 0..15
    const int tx  = tid & 15;       // 0..15
    const int dr  = ty * 4;         // query row base (0..60)
    const int cb  = tx * 4;         // key/value col base (0..60)

    const float* Qg = g_q + ((long)(b * H_ + h) * C_ + d0) * K_;
    const float* Kg = g_k + ((long)(b * H_ + h) * C_) * K_;
    const float* Vg = g_v + ((long)(b * H_ + h) * C_) * V_;

    // Load Q tile transposed (k-major)
#pragma unroll
    for (int l = 0; l < 4; l++) {
        int e  = tid + l * 256;      // 0..1023
        int r  = e >> 4;             // d 0..63
        int k4 = (e & 15) * 4;
        float4 v = *reinterpret_cast<const float4*>(Qg + (long)r * K_ + k4);
        Qts[(k4 + 0) * 68 + r] = v.x;
        Qts[(k4 + 1) * 68 + r] = v.y;
        Qts[(k4 + 2) * 68 + r] = v.z;
        Qts[(k4 + 3) * 68 + r] = v.w;
    }
    if (tid < 64) { sm_m[tid] = -1e30f; sm_l[tid] = 0.0f; }

    float acc[4][4];
#pragma unroll
    for (int i = 0; i < 4; i++)
#pragma unroll
        for (int j = 0; j < 4; j++) acc[i][j] = 0.0f;

    for (int c0 = 0; c0 < C_; c0 += 64) {
        __syncthreads();  // previous PV done before overwriting K/V/S tiles
        // Load K tile transposed (k-major) and V tile (c-major)
#pragma unroll
        for (int l = 0; l < 4; l++) {
            int e  = tid + l * 256;
            int r  = e >> 4;          // key row 0..63
            int k4 = (e & 15) * 4;
            float4 kv = *reinterpret_cast<const float4*>(Kg + (long)(c0 + r) * K_ + k4);
            Kts[(k4 + 0) * 68 + r] = kv.x;
            Kts[(k4 + 1) * 68 + r] = kv.y;
            Kts[(k4 + 2) * 68 + r] = kv.z;
            Kts[(k4 + 3) * 68 + r] = kv.w;
            float4 vv = *reinterpret_cast<const float4*>(Vg + (long)(c0 + r) * V_ + k4);
            *reinterpret_cast<float4*>(&Vs[r * 68 + k4]) = vv;
        }
        __syncthreads();

        // S = Q @ K^T (each thread 4x4)
        float s[4][4];
#pragma unroll
        for (int i = 0; i < 4; i++)
#pragma unroll
            for (int j = 0; j < 4; j++) s[i][j] = 0.0f;
#pragma unroll
        for (int kk = 0; kk < 64; kk++) {
            float4 a  = *reinterpret_cast<const float4*>(&Qts[kk * 68 + dr]);
            float4 b4 = *reinterpret_cast<const float4*>(&Kts[kk * 68 + cb]);
            float av[4] = {a.x, a.y, a.z, a.w};
            float bv[4] = {b4.x, b4.y, b4.z, b4.w};
#pragma unroll
            for (int i = 0; i < 4; i++)
#pragma unroll
                for (int j = 0; j < 4; j++)
                    s[i][j] = fmaf(av[i], bv[j], s[i][j]);
        }

        // Mask (before scale, like reference) then scale; write to Ss[d][c]
#pragma unroll
        for (int i = 0; i < 4; i++) {
            int d = d0 + dr + i;
#pragma unroll
            for (int j = 0; j < 4; j++) {
                int c = c0 + cb + j;
                float val = s[i][j];
                if (c <= d) val += -100.0f;
                Ss[(dr + i) * 65 + (cb + j)] = val * 0.125f;
            }
        }
        __syncthreads();

        // Online softmax: thread d (<64) scans its row
        if (tid < 64) {
            float* row = &Ss[tid * 65];
            float mt = row[0];
#pragma unroll 8
            for (int c = 1; c < 64; c++) mt = fmaxf(mt, row[c]);
            float mold = sm_m[tid];
            float mnew = fmaxf(mold, mt);
            float alpha = __expf(mold - mnew);
            float sum = 0.0f;
#pragma unroll 8
            for (int c = 0; c < 64; c++) {
                float p = __expf(row[c] - mnew);
                row[c] = p;
                sum += p;
            }
            sm_l[tid] = sm_l[tid] * alpha + sum;
            sm_m[tid] = mnew;
            sm_a[tid] = alpha;
        }
        __syncthreads();

        // Rescale accumulators + O += P @ V
        float al[4];
#pragma unroll
        for (int i = 0; i < 4; i++) al[i] = sm_a[dr + i];
#pragma unroll
        for (int i = 0; i < 4; i++)
#pragma unroll
            for (int j = 0; j < 4; j++) acc[i][j] *= al[i];

#pragma unroll
        for (int cc = 0; cc < 64; cc++) {
            float p[4];
#pragma unroll
            for (int i = 0; i < 4; i++) p[i] = Ss[(dr + i) * 65 + cc];
            float4 v4 = *reinterpret_cast<const float4*>(&Vs[cc * 68 + cb]);
            float vv[4] = {v4.x, v4.y, v4.z, v4.w};
#pragma unroll
            for (int i = 0; i < 4; i++)
#pragma unroll
                for (int j = 0; j < 4; j++)
                    acc[i][j] = fmaf(p[i], vv[j], acc[i][j]);
        }
    }

    // Finalize and write pre[b][d][h][v]
#pragma unroll
    for (int i = 0; i < 4; i++) {
        float invl = 1.0f / sm_l[dr + i];
        float4 v = make_float4(acc[i][0] * invl, acc[i][1] * invl,
                               acc[i][2] * invl, acc[i][3] * invl);
        long idx = (((long)(b * C_ + d0 + dr + i)) * H_ + h) * V_ + cb;
        *reinterpret_cast<float4*>(g_pre + idx) = v;
    }
}

// ---------------------------------------------------------------------------

extern "C" void kernel_launch(void* const* d_in, const int* in_sizes, int n_in,
                              void* d_out, int out_size)
{
    const float* kvinput = (const float*)d_in[0];
    const float* qinput  = (const float*)d_in[1];
    const float* wq      = (const float*)d_in[2];
    const float* wk      = (const float*)d_in[3];
    const float* wv      = (const float*)d_in[4];
    const float* wo      = (const float*)d_in[5];
    float* out = (float*)d_out;

    float *gq, *gk, *gv, *gpre;
    cudaGetSymbolAddress((void**)&gq,   g_q);
    cudaGetSymbolAddress((void**)&gk,   g_k);
    cudaGetSymbolAddress((void**)&gv,   g_v);
    cudaGetSymbolAddress((void**)&gpre, g_pre);

    const int attn_smem = (3 * 64 * 68 + 64 * 65 + 3 * 64) * (int)sizeof(float); // 69632
    cudaFuncSetAttribute(attn_kernel,
                         cudaFuncAttributeMaxDynamicSharedMemorySize, attn_smem);

    dim3 blk(256);

    // Projections: out[b][h][c][k] = X[b][c][:] @ W[h][:][k]
    dim3 pgrid(C_ / 128, H_, B_);
    // A: X (+ b*C*M), lda=M ; W: (+ h*M*K), ldw=K ; O: (+ (b*H+h)*C*K), ldo=K
    gemm128x64_kernel<<<pgrid, blk>>>(qinput,  wq, gq,
        M_, K_, K_, M_, (long)C_ * M_, (long)M_ * K_, (long)C_ * K_, (long)H_ * C_ * K_);
    gemm128x64_kernel<<<pgrid, blk>>>(kvinput, wk, gk,
        M_, K_, K_, M_, (long)C_ * M_, (long)M_ * K_, (long)C_ * K_, (long)H_ * C_ * K_);
    gemm128x64_kernel<<<pgrid, blk>>>(kvinput, wv, gv,
        M_, K_, V_, M_, (long)C_ * M_, (long)M_ * V_, (long)C_ * V_, (long)H_ * C_ * V_);

    // Attention
    dim3 agrid(C_ / 64, H_, B_);
    attn_kernel<<<agrid, blk, attn_smem>>>();

    // Output projection: out[4096][1024] = pre[4096][1024] @ wo_flat[1024][1024]
    dim3 ogrid((B_ * C_) / 128, M_ / 64, 1);
    gemm128x64_kernel<<<ogrid, blk>>>(gpre, wo, out,
        H_ * V_, M_, M_, H_ * V_, 0L, 64L, 64L, 0L);
}

// round 3
// speedup vs baseline: 1.6747x; 1.6747x over previous
#include <cuda_runtime.h>
#include <cuda_bf16.h>
#include <cstdint>
#include <math.h>

#define B_ 2
#define C_ 2048
#define M_ 1024
#define H_ 16
#define K_ 64
#define V_ 64

// ------------------------- scratch (no cudaMalloc) -------------------------
__device__ __nv_bfloat16 s_xq_hi [(size_t)B_ * C_ * M_];
__device__ __nv_bfloat16 s_xq_lo [(size_t)B_ * C_ * M_];
__device__ __nv_bfloat16 s_xkv_hi[(size_t)B_ * C_ * M_];
__device__ __nv_bfloat16 s_xkv_lo[(size_t)B_ * C_ * M_];

__device__ __nv_bfloat16 s_wqT_hi[(size_t)H_ * K_ * M_];
__device__ __nv_bfloat16 s_wqT_lo[(size_t)H_ * K_ * M_];
__device__ __nv_bfloat16 s_wkT_hi[(size_t)H_ * K_ * M_];
__device__ __nv_bfloat16 s_wkT_lo[(size_t)H_ * K_ * M_];
__device__ __nv_bfloat16 s_wvT_hi[(size_t)H_ * V_ * M_];
__device__ __nv_bfloat16 s_wvT_lo[(size_t)H_ * V_ * M_];
__device__ __nv_bfloat16 s_woT_hi[(size_t)M_ * (H_ * V_)];
__device__ __nv_bfloat16 s_woT_lo[(size_t)M_ * (H_ * V_)];

__device__ __nv_bfloat16 s_q_hi[(size_t)B_ * H_ * C_ * K_];
__device__ __nv_bfloat16 s_q_lo[(size_t)B_ * H_ * C_ * K_];
__device__ __nv_bfloat16 s_k_hi[(size_t)B_ * H_ * C_ * K_];
__device__ __nv_bfloat16 s_k_lo[(size_t)B_ * H_ * C_ * K_];
__device__ __nv_bfloat16 s_v_hi[(size_t)B_ * H_ * C_ * V_];
__device__ __nv_bfloat16 s_v_lo[(size_t)B_ * H_ * C_ * V_];

__device__ __nv_bfloat16 s_pre_hi[(size_t)B_ * C_ * (H_ * V_)];
__device__ __nv_bfloat16 s_pre_lo[(size_t)B_ * C_ * (H_ * V_)];

// ------------------------------ helpers ------------------------------------
__device__ __forceinline__ void split_pair(float x, float y,
                                           uint32_t& hi, uint32_t& lo) {
    __nv_bfloat162 h = __floats2bfloat162_rn(x, y);
    float hx = __bfloat162float(h.x);
    float hy = __bfloat162float(h.y);
    __nv_bfloat162 l = __floats2bfloat162_rn(x - hx, y - hy);
    hi = *reinterpret_cast<uint32_t*>(&h);
    lo = *reinterpret_cast<uint32_t*>(&l);
}

// D(16x8,f32) += A(16x16,bf16,row) * B(16x8,bf16,col)
__device__ __forceinline__ void mma16816(float* c, const uint32_t* a,
                                         const uint32_t* b) {
    asm volatile(
        "mma.sync.aligned.m16n8k16.row.col.f32.bf16.bf16.f32 "
        "{%0,%1,%2,%3}, {%4,%5,%6,%7}, {%8,%9}, {%0,%1,%2,%3};\n"
        : "+f"(c[0]), "+f"(c[1]), "+f"(c[2]), "+f"(c[3])
        : "r"(a[0]), "r"(a[1]), "r"(a[2]), "r"(a[3]), "r"(b[0]), "r"(b[1]));
}

// --------------------------- pre-pass kernels ------------------------------
// fp32 -> (hi,lo) bf16, elementwise (float4 per thread)
__global__ void split_kernel(const float* __restrict__ in,
                             __nv_bfloat16* __restrict__ oh,
                             __nv_bfloat16* __restrict__ ol, int n4) {
    int i = blockIdx.x * blockDim.x + threadIdx.x;
    if (i < n4) {
        float4 v = reinterpret_cast<const float4*>(in)[i];
        uint32_t h0, l0, h1, l1;
        split_pair(v.x, v.y, h0, l0);
        split_pair(v.z, v.w, h1, l1);
        reinterpret_cast<uint2*>(oh)[i] = make_uint2(h0, h1);
        reinterpret_cast<uint2*>(ol)[i] = make_uint2(l0, l1);
    }
}

// W[r][c] fp32 -> WT[c][r] (hi,lo) bf16, 32x32 smem tiles, block (32,8)
__global__ void transpose_split_kernel(const float* __restrict__ in,
                                       __nv_bfloat16* __restrict__ oh,
                                       __nv_bfloat16* __restrict__ ol,
                                       int R, int Cdim,
                                       long inStrideZ, long outStrideZ) {
    __shared__ float t[32][33];
    in += (long)blockIdx.z * inStrideZ;
    const long ob = (long)blockIdx.z * outStrideZ;
    const int c0 = blockIdx.x * 32, r0 = blockIdx.y * 32;
#pragma unroll
    for (int i = threadIdx.y; i < 32; i += 8)
        t[i][threadIdx.x] = in[(long)(r0 + i) * Cdim + c0 + threadIdx.x];
    __syncthreads();
#pragma unroll
    for (int i = threadIdx.y; i < 32; i += 8) {
        float v = t[threadIdx.x][i];
        __nv_bfloat16 h = __float2bfloat16(v);
        __nv_bfloat16 l = __float2bfloat16(v - __bfloat162float(h));
        long idx = ob + (long)(c0 + i) * R + r0 + threadIdx.x;
        oh[idx] = h;
        ol[idx] = l;
    }
}

// ---------------------------------------------------------------------------
// bf16x3 split-precision GEMM via mma.sync (HMMA), 128x64 tile per block.
// A (hi/lo) row-major [row][inner]; WT (hi/lo) row-major [n][inner];
// O fp32 (Ofp != null) or hi/lo bf16 outputs.
// ---------------------------------------------------------------------------
#define GEMM_SMEM (18432 * 2 + 9216 * 2)  // 55296
__global__ void __launch_bounds__(256, 2)
gemm_bf16_kernel(const __nv_bfloat16* __restrict__ Ah,
                 const __nv_bfloat16* __restrict__ Al,
                 const __nv_bfloat16* __restrict__ Wh,
                 const __nv_bfloat16* __restrict__ Wl,
                 float* __restrict__ Ofp,
                 __nv_bfloat16* __restrict__ Oh, __nv_bfloat16* __restrict__ Ol,
                 int lda, int ldo, int inner,
                 long aStrideZ, long wStrideY, long oStrideY, long oStrideZ)
{
    const long aOff = (long)blockIdx.z * aStrideZ;
    const long wOff = (long)blockIdx.y * wStrideY;
    const long oOff = (long)blockIdx.z * oStrideZ + (long)blockIdx.y * oStrideY;
    const int row0 = blockIdx.x * 128;

    extern __shared__ char smem[];
    __nv_bfloat16* sAh = (__nv_bfloat16*)(smem);           // [128][72]
    __nv_bfloat16* sAl = (__nv_bfloat16*)(smem + 18432);   // [128][72]
    __nv_bfloat16* sWh = (__nv_bfloat16*)(smem + 36864);   // [64][72]
    __nv_bfloat16* sWl = (__nv_bfloat16*)(smem + 46080);   // [64][72]

    const int tid = threadIdx.x;
    const int wid = tid >> 5, lane = tid & 31;
    const int lq = lane >> 2, lr = lane & 3;
    const int mrow = wid * 16;

    float acc[8][4];
#pragma unroll
    for (int i = 0; i < 8; i++)
#pragma unroll
        for (int j = 0; j < 4; j++) acc[i][j] = 0.0f;

    const int nchunks = inner >> 6;
    for (int it = 0; it < nchunks; it++) {
        const int m0 = it << 6;
        __syncthreads();
        // A tiles: 128 rows x 64 k bf16 -> 1024 uint4 per buffer
#pragma unroll
        for (int l = 0; l < 4; l++) {
            int e = tid + l * 256;
            int r = e >> 3, q = (e & 7) * 8;
            long g = aOff + (long)(row0 + r) * lda + m0 + q;
            *reinterpret_cast<uint4*>(&sAh[r * 72 + q]) =
                *reinterpret_cast<const uint4*>(&Ah[g]);
            *reinterpret_cast<uint4*>(&sAl[r * 72 + q]) =
                *reinterpret_cast<const uint4*>(&Al[g]);
        }
        // W tiles: 64 rows x 64 k
#pragma unroll
        for (int l = 0; l < 2; l++) {
            int e = tid + l * 256;
            int r = e >> 3, q = (e & 7) * 8;
            long g = wOff + (long)r * inner + m0 + q;
            *reinterpret_cast<uint4*>(&sWh[r * 72 + q]) =
                *reinterpret_cast<const uint4*>(&Wh[g]);
            *reinterpret_cast<uint4*>(&sWl[r * 72 + q]) =
                *reinterpret_cast<const uint4*>(&Wl[g]);
        }
        __syncthreads();

#pragma unroll
        for (int ks = 0; ks < 4; ks++) {
            const int k0 = ks * 16 + lr * 2;
            const int r0 = mrow + lq;
            uint32_t ah[4], al_[4];
            ah[0]  = *reinterpret_cast<const uint32_t*>(&sAh[r0 * 72 + k0]);
            ah[1]  = *reinterpret_cast<const uint32_t*>(&sAh[(r0 + 8) * 72 + k0]);
            ah[2]  = *reinterpret_cast<const uint32_t*>(&sAh[r0 * 72 + k0 + 8]);
            ah[3]  = *reinterpret_cast<const uint32_t*>(&sAh[(r0 + 8) * 72 + k0 + 8]);
            al_[0] = *reinterpret_cast<const uint32_t*>(&sAl[r0 * 72 + k0]);
            al_[1] = *reinterpret_cast<const uint32_t*>(&sAl[(r0 + 8) * 72 + k0]);
            al_[2] = *reinterpret_cast<const uint32_t*>(&sAl[r0 * 72 + k0 + 8]);
            al_[3] = *reinterpret_cast<const uint32_t*>(&sAl[(r0 + 8) * 72 + k0 + 8]);
#pragma unroll
            for (int nt = 0; nt < 8; nt++) {
                const int n0 = nt * 8 + lq;
                uint32_t bh[2], bl[2];
                bh[0] = *reinterpret_cast<const uint32_t*>(&sWh[n0 * 72 + k0]);
                bh[1] = *reinterpret_cast<const uint32_t*>(&sWh[n0 * 72 + k0 + 8]);
                bl[0] = *reinterpret_cast<const uint32_t*>(&sWl[n0 * 72 + k0]);
                bl[1] = *reinterpret_cast<const uint32_t*>(&sWl[n0 * 72 + k0 + 8]);
                mma16816(acc[nt], ah, bh);
                mma16816(acc[nt], ah, bl);
                mma16816(acc[nt], al_, bh);
            }
        }
    }

    // epilogue
    const int r0 = mrow + lq;
    const int cb = lr * 2;
#pragma unroll
    for (int nt = 0; nt < 8; nt++) {
        const int col = nt * 8 + cb;
        const long i0 = oOff + (long)(row0 + r0) * ldo + col;
        const long i1 = oOff + (long)(row0 + r0 + 8) * ldo + col;
        if (Ofp) {
            *reinterpret_cast<float2*>(&Ofp[i0]) = make_float2(acc[nt][0], acc[nt][1]);
            *reinterpret_cast<float2*>(&Ofp[i1]) = make_float2(acc[nt][2], acc[nt][3]);
        } else {
            uint32_t h0, l0, h1, l1;
            split_pair(acc[nt][0], acc[nt][1], h0, l0);
            split_pair(acc[nt][2], acc[nt][3], h1, l1);
            *reinterpret_cast<uint32_t*>(&Oh[i0]) = h0;
            *reinterpret_cast<uint32_t*>(&Ol[i0]) = l0;
            *reinterpret_cast<uint32_t*>(&Oh[i1]) = h1;
            *reinterpret_cast<uint32_t*>(&Ol[i1]) = l1;
        }
    }
}

// ---------------------------------------------------------------------------
// Flash attention on mma.sync, bf16x3 split. 64 queries x 64-key tiles.
// S[d][c] = q.k ; +(-100) where c<=d ; softmax over c of S*0.125 ; O = P@V.
// ---------------------------------------------------------------------------
#define AT_QH 0
#define AT_QL 9216
#define AT_KH 18432
#define AT_KL 27648
#define AT_VH 36864     // Vt [64][66] bf16 = 8448
#define AT_VL 45312
#define AT_SS 53760     // [64][66] fp32 = 16896
#define AT_SM 70656     // m,l,a : 3*64*4
#define AT_TOTAL 71424

__global__ void __launch_bounds__(256, 2)
attn_kernel(const __nv_bfloat16* __restrict__ qh_g, const __nv_bfloat16* __restrict__ ql_g,
            const __nv_bfloat16* __restrict__ kh_g, const __nv_bfloat16* __restrict__ kl_g,
            const __nv_bfloat16* __restrict__ vh_g, const __nv_bfloat16* __restrict__ vl_g,
            __nv_bfloat16* __restrict__ ph_g, __nv_bfloat16* __restrict__ pl_g)
{
    const int b = blockIdx.z, h = blockIdx.y, d0 = blockIdx.x * 64;
    const long bh = (long)(b * H_ + h) * C_;

    extern __shared__ char smem[];
    __nv_bfloat16* sQh = (__nv_bfloat16*)(smem + AT_QH);   // [64][72]
    __nv_bfloat16* sQl = (__nv_bfloat16*)(smem + AT_QL);
    __nv_bfloat16* sKh = (__nv_bfloat16*)(smem + AT_KH);   // [64][72]
    __nv_bfloat16* sKl = (__nv_bfloat16*)(smem + AT_KL);
    __nv_bfloat16* sVh = (__nv_bfloat16*)(smem + AT_VH);   // [64][66] (v-major)
    __nv_bfloat16* sVl = (__nv_bfloat16*)(smem + AT_VL);
    float* Ss   = (float*)(smem + AT_SS);                  // [64][66]
    float* sm_m = (float*)(smem + AT_SM);
    float* sm_l = sm_m + 64;
    float* sm_a = sm_m + 128;

    const int tid = threadIdx.x;
    const int wid = tid >> 5, lane = tid & 31;
    const int lq = lane >> 2, lr = lane & 3;
    const int dtile = (wid >> 1) * 16;
    const int half  = (wid & 1) * 32;
    const int r0 = dtile + lq;

    // load Q tile (hi/lo)
#pragma unroll
    for (int l = 0; l < 2; l++) {
        int e = tid + l * 256;
        int r = e >> 3, q = (e & 7) * 8;
        long g = (bh + d0 + r) * 64 + q;
        *reinterpret_cast<uint4*>(&sQh[r * 72 + q]) =
            *reinterpret_cast<const uint4*>(&qh_g[g]);
        *reinterpret_cast<uint4*>(&sQl[r * 72 + q]) =
            *reinterpret_cast<const uint4*>(&ql_g[g]);
    }
    if (tid < 64) { sm_m[tid] = -1e30f; sm_l[tid] = 0.0f; }
    __syncthreads();

    // persistent Q fragments (4 ksteps)
    uint32_t qh[4][4], ql[4][4];
#pragma unroll
    for (int ks = 0; ks < 4; ks++) {
        const int k0 = ks * 16 + lr * 2;
        qh[ks][0] = *reinterpret_cast<const uint32_t*>(&sQh[r0 * 72 + k0]);
        qh[ks][1] = *reinterpret_cast<const uint32_t*>(&sQh[(r0 + 8) * 72 + k0]);
        qh[ks][2] = *reinterpret_cast<const uint32_t*>(&sQh[r0 * 72 + k0 + 8]);
        qh[ks][3] = *reinterpret_cast<const uint32_t*>(&sQh[(r0 + 8) * 72 + k0 + 8]);
        ql[ks][0] = *reinterpret_cast<const uint32_t*>(&sQl[r0 * 72 + k0]);
        ql[ks][1] = *reinterpret_cast<const uint32_t*>(&sQl[(r0 + 8) * 72 + k0]);
        ql[ks][2] = *reinterpret_cast<const uint32_t*>(&sQl[r0 * 72 + k0 + 8]);
        ql[ks][3] = *reinterpret_cast<const uint32_t*>(&sQl[(r0 + 8) * 72 + k0 + 8]);
    }

    float oacc[4][4];
#pragma unroll
    for (int i = 0; i < 4; i++)
#pragma unroll
        for (int j = 0; j < 4; j++) oacc[i][j] = 0.0f;

    for (int c0 = 0; c0 < C_; c0 += 64) {
        __syncthreads();
        // K tile (hi/lo) straight copy
#pragma unroll
        for (int l = 0; l < 2; l++) {
            int e = tid + l * 256;
            int r = e >> 3, q = (e & 7) * 8;
            long g = (bh + c0 + r) * 64 + q;
            *reinterpret_cast<uint4*>(&sKh[r * 72 + q]) =
                *reinterpret_cast<const uint4*>(&kh_g[g]);
            *reinterpret_cast<uint4*>(&sKl[r * 72 + q]) =
                *reinterpret_cast<const uint4*>(&kl_g[g]);
        }
        // V tile transposed: sV[v][c]
#pragma unroll
        for (int l = 0; l < 4; l++) {
            int e = tid + l * 256;          // 0..1023, 4 elems each
            int r = e >> 4, v4 = (e & 15) * 4;
            long g = (bh + c0 + r) * 64 + v4;
            uint2 hv = *reinterpret_cast<const uint2*>(&vh_g[g]);
            uint2 lv = *reinterpret_cast<const uint2*>(&vl_g[g]);
            const __nv_bfloat16* hp = reinterpret_cast<const __nv_bfloat16*>(&hv);
            const __nv_bfloat16* lp = reinterpret_cast<const __nv_bfloat16*>(&lv);
#pragma unroll
            for (int j = 0; j < 4; j++) {
                sVh[(v4 + j) * 66 + r] = hp[j];
                sVl[(v4 + j) * 66 + r] = lp[j];
            }
        }
        __syncthreads();

        // ---- S = Q @ K^T ----
        float sacc[4][4];
#pragma unroll
        for (int i = 0; i < 4; i++)
#pragma unroll
            for (int j = 0; j < 4; j++) sacc[i][j] = 0.0f;
#pragma unroll
        for (int ks = 0; ks < 4; ks++) {
            const int k0 = ks * 16 + lr * 2;
#pragma unroll
            for (int nt = 0; nt < 4; nt++) {
                const int n0 = half + nt * 8 + lq;
                uint32_t bh2[2], bl2[2];
                bh2[0] = *reinterpret_cast<const uint32_t*>(&sKh[n0 * 72 + k0]);
                bh2[1] = *reinterpret_cast<const uint32_t*>(&sKh[n0 * 72 + k0 + 8]);
                bl2[0] = *reinterpret_cast<const uint32_t*>(&sKl[n0 * 72 + k0]);
                bl2[1] = *reinterpret_cast<const uint32_t*>(&sKl[n0 * 72 + k0 + 8]);
                mma16816(sacc[nt], qh[ks], bh2);
                mma16816(sacc[nt], qh[ks], bl2);
                mma16816(sacc[nt], ql[ks], bh2);
            }
        }
        // mask + scale -> Ss
        {
            const int dg0 = d0 + r0, dg1 = d0 + r0 + 8;
#pragma unroll
            for (int nt = 0; nt < 4; nt++) {
                const int col = half + nt * 8 + lr * 2;
                const int cg = c0 + col;
                float v0 = sacc[nt][0]; if (cg     <= dg0) v0 -= 100.0f;
                float v1 = sacc[nt][1]; if (cg + 1 <= dg0) v1 -= 100.0f;
                float v2 = sacc[nt][2]; if (cg     <= dg1) v2 -= 100.0f;
                float v3 = sacc[nt][3]; if (cg + 1 <= dg1) v3 -= 100.0f;
                Ss[r0 * 66 + col]           = v0 * 0.125f;
                Ss[r0 * 66 + col + 1]       = v1 * 0.125f;
                Ss[(r0 + 8) * 66 + col]     = v2 * 0.125f;
                Ss[(r0 + 8) * 66 + col + 1] = v3 * 0.125f;
            }
        }
        __syncthreads();

        // ---- online softmax (one thread per query row) ----
        if (tid < 64) {
            float* row = &Ss[tid * 66];
            float mt = row[0];
#pragma unroll 8
            for (int c = 1; c < 64; c++) mt = fmaxf(mt, row[c]);
            float mold = sm_m[tid];
            float mnew = fmaxf(mold, mt);
            float alpha = __expf(mold - mnew);
            float sum = 0.0f;
#pragma unroll 8
            for (int c = 0; c < 64; c++) {
                float p = __expf(row[c] - mnew);
                row[c] = p;
                sum += p;
            }
            sm_l[tid] = sm_l[tid] * alpha + sum;
            sm_m[tid] = mnew;
            sm_a[tid] = alpha;
        }
        __syncthreads();

        // ---- O = O*alpha + P @ V ----
        {
            const float al0 = sm_a[r0], al1 = sm_a[r0 + 8];
#pragma unroll
            for (int nt = 0; nt < 4; nt++) {
                oacc[nt][0] *= al0; oacc[nt][1] *= al0;
                oacc[nt][2] *= al1; oacc[nt][3] *= al1;
            }
        }
#pragma unroll
        for (int ks = 0; ks < 4; ks++) {
            const int kc = ks * 16 + lr * 2;
            uint32_t ph[4], pl[4];
            float2 p0 = *reinterpret_cast<const float2*>(&Ss[r0 * 66 + kc]);
            float2 p1 = *reinterpret_cast<const float2*>(&Ss[(r0 + 8) * 66 + kc]);
            float2 p2 = *reinterpret_cast<const float2*>(&Ss[r0 * 66 + kc + 8]);
            float2 p3 = *reinterpret_cast<const float2*>(&Ss[(r0 + 8) * 66 + kc + 8]);
            split_pair(p0.x, p0.y, ph[0], pl[0]);
            split_pair(p1.x, p1.y, ph[1], pl[1]);
            split_pair(p2.x, p2.y, ph[2], pl[2]);
            split_pair(p3.x, p3.y, ph[3], pl[3]);
#pragma unroll
            for (int nt = 0; nt < 4; nt++) {
                const int n0 = half + nt * 8 + lq;
                uint32_t bh2[2], bl2[2];
                bh2[0] = *reinterpret_cast<const uint32_t*>(&sVh[n0 * 66 + kc]);
                bh2[1] = *reinterpret_cast<const uint32_t*>(&sVh[n0 * 66 + kc + 8]);
                bl2[0] = *reinterpret_cast<const uint32_t*>(&sVl[n0 * 66 + kc]);
                bl2[1] = *reinterpret_cast<const uint32_t*>(&sVl[n0 * 66 + kc + 8]);
                mma16816(oacc[nt], ph, bh2);
                mma16816(oacc[nt], ph, bl2);
                mma16816(oacc[nt], pl, bh2);
            }
        }
    }

    // epilogue -> pre (hi/lo bf16), layout [b*C + d][h*64 + v]
    {
        const float il0 = 1.0f / sm_l[r0];
        const float il1 = 1.0f / sm_l[r0 + 8];
#pragma unroll
        for (int nt = 0; nt < 4; nt++) {
            const int col = h * 64 + half + nt * 8 + lr * 2;
            const long i0 = ((long)(b * C_ + d0 + r0)) * (H_ * V_) + col;
            const long i1 = ((long)(b * C_ + d0 + r0 + 8)) * (H_ * V_) + col;
            uint32_t h0, l0, h1, l1;
            split_pair(oacc[nt][0] * il0, oacc[nt][1] * il0, h0, l0);
            split_pair(oacc[nt][2] * il1, oacc[nt][3] * il1, h1, l1);
            *reinterpret_cast<uint32_t*>(&ph_g[i0]) = h0;
            *reinterpret_cast<uint32_t*>(&pl_g[i0]) = l0;
            *reinterpret_cast<uint32_t*>(&ph_g[i1]) = h1;
            *reinterpret_cast<uint32_t*>(&pl_g[i1]) = l1;
        }
    }
}

// ---------------------------------------------------------------------------

extern "C" void kernel_launch(void* const* d_in, const int* in_sizes, int n_in,
                              void* d_out, int out_size)
{
    const float* kvinput = (const float*)d_in[0];
    const float* qinput  = (const float*)d_in[1];
    const float* wq      = (const float*)d_in[2];
    const float* wk      = (const float*)d_in[3];
    const float* wv      = (const float*)d_in[4];
    const float* wo      = (const float*)d_in[5];
    float* out = (float*)d_out;

    __nv_bfloat16 *xqh, *xql, *xkh, *xkl;
    __nv_bfloat16 *wqh, *wql, *wkh, *wkl, *wvh, *wvl, *woh, *wol;
    __nv_bfloat16 *qh, *ql, *kh, *kl, *vh, *vl, *prh, *prl;
    cudaGetSymbolAddress((void**)&xqh, s_xq_hi);
    cudaGetSymbolAddress((void**)&xql, s_xq_lo);
    cudaGetSymbolAddress((void**)&xkh, s_xkv_hi);
    cudaGetSymbolAddress((void**)&xkl, s_xkv_lo);
    cudaGetSymbolAddress((void**)&wqh, s_wqT_hi);
    cudaGetSymbolAddress((void**)&wql, s_wqT_lo);
    cudaGetSymbolAddress((void**)&wkh, s_wkT_hi);
    cudaGetSymbolAddress((void**)&wkl, s_wkT_lo);
    cudaGetSymbolAddress((void**)&wvh, s_wvT_hi);
    cudaGetSymbolAddress((void**)&wvl, s_wvT_lo);
    cudaGetSymbolAddress((void**)&woh, s_woT_hi);
    cudaGetSymbolAddress((void**)&wol, s_woT_lo);
    cudaGetSymbolAddress((void**)&qh,  s_q_hi);
    cudaGetSymbolAddress((void**)&ql,  s_q_lo);
    cudaGetSymbolAddress((void**)&kh,  s_k_hi);
    cudaGetSymbolAddress((void**)&kl,  s_k_lo);
    cudaGetSymbolAddress((void**)&vh,  s_v_hi);
    cudaGetSymbolAddress((void**)&vl,  s_v_lo);
    cudaGetSymbolAddress((void**)&prh, s_pre_hi);
    cudaGetSymbolAddress((void**)&prl, s_pre_lo);

    cudaFuncSetAttribute(gemm_bf16_kernel,
                         cudaFuncAttributeMaxDynamicSharedMemorySize, GEMM_SMEM);
    cudaFuncSetAttribute(attn_kernel,
                         cudaFuncAttributeMaxDynamicSharedMemorySize, AT_TOTAL);

    // ---- pre-pass: split inputs, transpose+split weights ----
    {
        int n4 = B_ * C_ * M_ / 4;
        split_kernel<<<(n4 + 255) / 256, 256>>>(qinput,  xqh, xql, n4);
        split_kernel<<<(n4 + 255) / 256, 256>>>(kvinput, xkh, xkl, n4);
    }
    {
        dim3 tb(32, 8);
        dim3 gw(K_ / 32, M_ / 32, H_);   // (2, 32, 16)
        transpose_split_kernel<<<gw, tb>>>(wq, wqh, wql, M_, K_,
                                           (long)M_ * K_, (long)K_ * M_);
        transpose_split_kernel<<<gw, tb>>>(wk, wkh, wkl, M_, K_,
                                           (long)M_ * K_, (long)K_ * M_);
        transpose_split_kernel<<<gw, tb>>>(wv, wvh, wvl, M_, V_,
                                           (long)M_ * V_, (long)V_ * M_);
        dim3 go(M_ / 32, (H_ * V_) / 32, 1);  // wo flat [1024][1024]
        transpose_split_kernel<<<go, tb>>>(wo, woh, wol, H_ * V_, M_, 0L, 0L);
    }

    dim3 blk(256);

    // ---- projections: [b][h][c][k] = X[b][c][:] @ W[h][:][k] ----
    dim3 pgrid(C_ / 128, H_, B_);
    gemm_bf16_kernel<<<pgrid, blk, GEMM_SMEM>>>(xqh, xql, wqh, wql,
        nullptr, qh, ql, M_, K_, M_,
        (long)C_ * M_, (long)K_ * M_, (long)C_ * K_, (long)H_ * C_ * K_);
    gemm_bf16_kernel<<<pgrid, blk, GEMM_SMEM>>>(xkh, xkl, wkh, wkl,
        nullptr, kh, kl, M_, K_, M_,
        (long)C_ * M_, (long)K_ * M_, (long)C_ * K_, (long)H_ * C_ * K_);
    gemm_bf16_kernel<<<pgrid, blk, GEMM_SMEM>>>(xkh, xkl, wvh, wvl,
        nullptr, vh, vl, M_, V_, M_,
        (long)C_ * M_, (long)V_ * M_, (long)C_ * V_, (long)H_ * C_ * V_);

    // ---- attention ----
    dim3 agrid(C_ / 64, H_, B_);
    attn_kernel<<<agrid, blk, AT_TOTAL>>>(qh, ql, kh, kl, vh, vl, prh, prl);

    // ---- output projection: out[4096][1024] = pre @ wo_flat ----
    dim3 ogrid((B_ * C_) / 128, M_ / 64, 1);
    gemm_bf16_kernel<<<ogrid, blk, GEMM_SMEM>>>(prh, prl, woh, wol,
        out, nullptr, nullptr, H_ * V_, M_, H_ * V_,
        0L, (long)64 * (H_ * V_), 64L, 0L);
}

// round 4
// speedup vs baseline: 2.2384x; 1.3366x over previous
#include <cuda_runtime.h>
#include <cuda_bf16.h>
#include <cstdint>
#include <math.h>

#define B_ 2
#define C_ 2048
#define M_ 1024
#define H_ 16
#define K_ 64
#define V_ 64

// ------------------------- scratch (no cudaMalloc) -------------------------
__device__ __nv_bfloat16 s_xq_hi [(size_t)B_ * C_ * M_];
__device__ __nv_bfloat16 s_xq_lo [(size_t)B_ * C_ * M_];
__device__ __nv_bfloat16 s_xkv_hi[(size_t)B_ * C_ * M_];
__device__ __nv_bfloat16 s_xkv_lo[(size_t)B_ * C_ * M_];

__device__ __nv_bfloat16 s_wqT_hi[(size_t)H_ * K_ * M_];
__device__ __nv_bfloat16 s_wqT_lo[(size_t)H_ * K_ * M_];
__device__ __nv_bfloat16 s_wkT_hi[(size_t)H_ * K_ * M_];
__device__ __nv_bfloat16 s_wkT_lo[(size_t)H_ * K_ * M_];
__device__ __nv_bfloat16 s_wvT_hi[(size_t)H_ * V_ * M_];
__device__ __nv_bfloat16 s_wvT_lo[(size_t)H_ * V_ * M_];
__device__ __nv_bfloat16 s_woT_hi[(size_t)M_ * (H_ * V_)];
__device__ __nv_bfloat16 s_woT_lo[(size_t)M_ * (H_ * V_)];

__device__ __nv_bfloat16 s_q_hi[(size_t)B_ * H_ * C_ * K_];
__device__ __nv_bfloat16 s_q_lo[(size_t)B_ * H_ * C_ * K_];
__device__ __nv_bfloat16 s_k_hi[(size_t)B_ * H_ * C_ * K_];
__device__ __nv_bfloat16 s_k_lo[(size_t)B_ * H_ * C_ * K_];
__device__ __nv_bfloat16 s_v_hi[(size_t)B_ * H_ * C_ * V_];
__device__ __nv_bfloat16 s_v_lo[(size_t)B_ * H_ * C_ * V_];
__device__ __nv_bfloat16 s_vT_hi[(size_t)B_ * H_ * V_ * C_];
__device__ __nv_bfloat16 s_vT_lo[(size_t)B_ * H_ * V_ * C_];

__device__ __nv_bfloat16 s_pre_hi[(size_t)B_ * C_ * (H_ * V_)];
__device__ __nv_bfloat16 s_pre_lo[(size_t)B_ * C_ * (H_ * V_)];

// ------------------------------ helpers ------------------------------------
__device__ __forceinline__ void split_pair(float x, float y,
                                           uint32_t& hi, uint32_t& lo) {
    __nv_bfloat162 h = __floats2bfloat162_rn(x, y);
    float hx = __bfloat162float(h.x);
    float hy = __bfloat162float(h.y);
    __nv_bfloat162 l = __floats2bfloat162_rn(x - hx, y - hy);
    hi = *reinterpret_cast<uint32_t*>(&h);
    lo = *reinterpret_cast<uint32_t*>(&l);
}

__device__ __forceinline__ void mma16816(float* c, const uint32_t* a,
                                         const uint32_t* b) {
    asm volatile(
        "mma.sync.aligned.m16n8k16.row.col.f32.bf16.bf16.f32 "
        "{%0,%1,%2,%3}, {%4,%5,%6,%7}, {%8,%9}, {%0,%1,%2,%3};\n"
        : "+f"(c[0]), "+f"(c[1]), "+f"(c[2]), "+f"(c[3])
        : "r"(a[0]), "r"(a[1]), "r"(a[2]), "r"(a[3]), "r"(b[0]), "r"(b[1]));
}

__device__ __forceinline__ uint32_t smem_u32(const void* p) {
    uint32_t a;
    asm("{ .reg .u64 t; cvta.to.shared.u64 t, %1; cvt.u32.u64 %0, t; }"
        : "=r"(a) : "l"(p));
    return a;
}
#define CP_ASYNC16(dst, src) \
    asm volatile("cp.async.ca.shared.global [%0], [%1], 16;\n" \
                 :: "r"(dst), "l"(src) : "memory")
#define CP_COMMIT() asm volatile("cp.async.commit_group;\n" ::: "memory")
#define CP_WAIT0()  asm volatile("cp.async.wait_group 0;\n" ::: "memory")
#define CP_WAIT1()  asm volatile("cp.async.wait_group 1;\n" ::: "memory")

// --------------------------- pre-pass kernels ------------------------------
__global__ void split_kernel(const float* __restrict__ in,
                             __nv_bfloat16* __restrict__ oh,
                             __nv_bfloat16* __restrict__ ol, int n4) {
    int i = blockIdx.x * blockDim.x + threadIdx.x;
    if (i < n4) {
        float4 v = reinterpret_cast<const float4*>(in)[i];
        uint32_t h0, l0, h1, l1;
        split_pair(v.x, v.y, h0, l0);
        split_pair(v.z, v.w, h1, l1);
        reinterpret_cast<uint2*>(oh)[i] = make_uint2(h0, h1);
        reinterpret_cast<uint2*>(ol)[i] = make_uint2(l0, l1);
    }
}

__global__ void transpose_split_kernel(const float* __restrict__ in,
                                       __nv_bfloat16* __restrict__ oh,
                                       __nv_bfloat16* __restrict__ ol,
                                       int R, int Cdim,
                                       long inStrideZ, long outStrideZ) {
    __shared__ float t[32][33];
    in += (long)blockIdx.z * inStrideZ;
    const long ob = (long)blockIdx.z * outStrideZ;
    const int c0 = blockIdx.x * 32, r0 = blockIdx.y * 32;
#pragma unroll
    for (int i = threadIdx.y; i < 32; i += 8)
        t[i][threadIdx.x] = in[(long)(r0 + i) * Cdim + c0 + threadIdx.x];
    __syncthreads();
#pragma unroll
    for (int i = threadIdx.y; i < 32; i += 8) {
        float v = t[threadIdx.x][i];
        __nv_bfloat16 h = __float2bfloat16(v);
        __nv_bfloat16 l = __float2bfloat16(v - __bfloat162float(h));
        long idx = ob + (long)(c0 + i) * R + r0 + threadIdx.x;
        oh[idx] = h;
        ol[idx] = l;
    }
}

// V [bh][c][v] -> VT [bh][v][c] for hi and lo
__global__ void vtrans_kernel(const __nv_bfloat16* __restrict__ vh,
                              const __nv_bfloat16* __restrict__ vl,
                              __nv_bfloat16* __restrict__ oth,
                              __nv_bfloat16* __restrict__ otl) {
    const int bh = blockIdx.y;
    const int c0 = blockIdx.x * 64;
    const long ib = (long)bh * C_ * 64;
    const long ob = (long)bh * 64 * C_;
    __shared__ __nv_bfloat16 t[64][68];
    const int tid = threadIdx.x;

    for (int pass = 0; pass < 2; pass++) {
        const __nv_bfloat16* src = pass ? vl : vh;
        __nv_bfloat16* dst = pass ? otl : oth;
#pragma unroll
        for (int l = 0; l < 4; l++) {
            int e = tid + l * 256;
            int c = e >> 4, v4 = (e & 15) * 4;
            *reinterpret_cast<uint2*>(&t[c][v4]) =
                *reinterpret_cast<const uint2*>(&src[ib + (long)(c0 + c) * 64 + v4]);
        }
        __syncthreads();
#pragma unroll
        for (int l = 0; l < 4; l++) {
            int e = tid + l * 256;
            int v = e >> 4, c4 = (e & 15) * 4;
            __nv_bfloat16 tmp[4] = {t[c4][v], t[c4 + 1][v], t[c4 + 2][v], t[c4 + 3][v]};
            *reinterpret_cast<uint2*>(&dst[ob + (long)v * C_ + c0 + c4]) =
                *reinterpret_cast<const uint2*>(tmp);
        }
        __syncthreads();
    }
}

// ---------------------------------------------------------------------------
// bf16x3 GEMM, 128x128 tile, K-chunk 32, cp.async double-buffered.
// A hi/lo [rows][inner]; W hi/lo [n][inner]. 8 warps: wm=wid>>1 (4), wn=wid&1 (2).
// mode 0: fp32 out, idx = oOff + row*ldo + col
// mode 1: split bf16 out, idx = oOff + (col>>6)*headStride + row*64 + (col&63)
// ---------------------------------------------------------------------------
#define GS 40                       // smem row stride (bf16 elems), 80B
#define GARR (128 * GS * 2)         // 10240 bytes per array
#define GBUF (4 * GARR)             // 40960 per stage
#define GEMM_SMEM2 (2 * GBUF)       // 81920

__global__ void __launch_bounds__(256, 2)
gemm_bf16x3(const __nv_bfloat16* __restrict__ Ah, const __nv_bfloat16* __restrict__ Al,
            const __nv_bfloat16* __restrict__ Wh, const __nv_bfloat16* __restrict__ Wl,
            float* __restrict__ Ofp,
            __nv_bfloat16* __restrict__ Oh, __nv_bfloat16* __restrict__ Ol,
            int inner, int mode, int ldo, long headStride,
            long aOffZ, long wOffY, long oOffY, long oOffZ)
{
    const long aOff = (long)blockIdx.z * aOffZ;
    const long wOff = (long)blockIdx.y * wOffY;
    const long oOff = (long)blockIdx.z * oOffZ + (long)blockIdx.y * oOffY;
    const int row0 = blockIdx.x * 128;

    extern __shared__ char smem[];
    const uint32_t sb = smem_u32(smem);

    const int tid = threadIdx.x;
    const int wid = tid >> 5, lane = tid & 31;
    const int lq = lane >> 2, lr = lane & 3;
    const int wm = wid >> 1, wn = wid & 1;

    // per-thread cp.async geometry: e in {tid, tid+256}: r=e>>2 (0..127), q=e&3
    const int r_a = tid >> 2, q_a = tid & 3;
    const int r_b = (tid + 256) >> 2, q_b = (tid + 256) & 3;

    float acc[2][8][4];
#pragma unroll
    for (int a = 0; a < 2; a++)
#pragma unroll
        for (int b = 0; b < 8; b++)
#pragma unroll
            for (int c = 0; c < 4; c++) acc[a][b][c] = 0.0f;

    const int nch = inner >> 5;

    auto issue = [&](int ck, int s) {
        const int m0 = ck << 5;
        const uint32_t base = sb + s * GBUF;
        // A hi/lo
        {
            const __nv_bfloat16* s0 = Ah + aOff + (long)(row0 + r_a) * inner + m0 + q_a * 8;
            const __nv_bfloat16* s1 = Ah + aOff + (long)(row0 + r_b) * inner + m0 + q_b * 8;
            CP_ASYNC16(base + r_a * 80 + q_a * 16, s0);
            CP_ASYNC16(base + r_b * 80 + q_b * 16, s1);
            const __nv_bfloat16* s2 = Al + aOff + (long)(row0 + r_a) * inner + m0 + q_a * 8;
            const __nv_bfloat16* s3 = Al + aOff + (long)(row0 + r_b) * inner + m0 + q_b * 8;
            CP_ASYNC16(base + GARR + r_a * 80 + q_a * 16, s2);
            CP_ASYNC16(base + GARR + r_b * 80 + q_b * 16, s3);
        }
        // W hi/lo
        {
            const __nv_bfloat16* s0 = Wh + wOff + (long)r_a * inner + m0 + q_a * 8;
            const __nv_bfloat16* s1 = Wh + wOff + (long)r_b * inner + m0 + q_b * 8;
            CP_ASYNC16(base + 2 * GARR + r_a * 80 + q_a * 16, s0);
            CP_ASYNC16(base + 2 * GARR + r_b * 80 + q_b * 16, s1);
            const __nv_bfloat16* s2 = Wl + wOff + (long)r_a * inner + m0 + q_a * 8;
            const __nv_bfloat16* s3 = Wl + wOff + (long)r_b * inner + m0 + q_b * 8;
            CP_ASYNC16(base + 3 * GARR + r_a * 80 + q_a * 16, s2);
            CP_ASYNC16(base + 3 * GARR + r_b * 80 + q_b * 16, s3);
        }
    };

    issue(0, 0);
    CP_COMMIT();

    for (int it = 0; it < nch; it++) {
        if (it + 1 < nch) {
            issue(it + 1, (it + 1) & 1);
            CP_COMMIT();
            CP_WAIT1();
        } else {
            CP_WAIT0();
        }
        __syncthreads();

        const char* cb = smem + (it & 1) * GBUF;
        const __nv_bfloat16* sAh = (const __nv_bfloat16*)(cb);
        const __nv_bfloat16* sAl = (const __nv_bfloat16*)(cb + GARR);
        const __nv_bfloat16* sWh = (const __nv_bfloat16*)(cb + 2 * GARR);
        const __nv_bfloat16* sWl = (const __nv_bfloat16*)(cb + 3 * GARR);

#pragma unroll
        for (int ks = 0; ks < 2; ks++) {
            const int k0 = ks * 16 + lr * 2;
            uint32_t ah[2][4], al[2][4];
#pragma unroll
            for (int mt = 0; mt < 2; mt++) {
                const int r = wm * 32 + mt * 16 + lq;
                ah[mt][0] = *reinterpret_cast<const uint32_t*>(&sAh[r * GS + k0]);
                ah[mt][1] = *reinterpret_cast<const uint32_t*>(&sAh[(r + 8) * GS + k0]);
                ah[mt][2] = *reinterpret_cast<const uint32_t*>(&sAh[r * GS + k0 + 8]);
                ah[mt][3] = *reinterpret_cast<const uint32_t*>(&sAh[(r + 8) * GS + k0 + 8]);
                al[mt][0] = *reinterpret_cast<const uint32_t*>(&sAl[r * GS + k0]);
                al[mt][1] = *reinterpret_cast<const uint32_t*>(&sAl[(r + 8) * GS + k0]);
                al[mt][2] = *reinterpret_cast<const uint32_t*>(&sAl[r * GS + k0 + 8]);
                al[mt][3] = *reinterpret_cast<const uint32_t*>(&sAl[(r + 8) * GS + k0 + 8]);
            }
#pragma unroll
            for (int nt = 0; nt < 8; nt++) {
                const int n = wn * 64 + nt * 8 + lq;
                uint32_t bh[2], bl[2];
                bh[0] = *reinterpret_cast<const uint32_t*>(&sWh[n * GS + k0]);
                bh[1] = *reinterpret_cast<const uint32_t*>(&sWh[n * GS + k0 + 8]);
                bl[0] = *reinterpret_cast<const uint32_t*>(&sWl[n * GS + k0]);
                bl[1] = *reinterpret_cast<const uint32_t*>(&sWl[n * GS + k0 + 8]);
#pragma unroll
                for (int mt = 0; mt < 2; mt++) {
                    mma16816(acc[mt][nt], ah[mt], bh);
                    mma16816(acc[mt][nt], ah[mt], bl);
                    mma16816(acc[mt][nt], al[mt], bh);
                }
            }
        }
        __syncthreads();
    }

    // epilogue
#pragma unroll
    for (int mt = 0; mt < 2; mt++) {
        const int row_lo = row0 + wm * 32 + mt * 16 + lq;
        const int row_hi = row_lo + 8;
#pragma unroll
        for (int nt = 0; nt < 8; nt++) {
            const int col = wn * 64 + nt * 8 + lr * 2;
            const float* c = acc[mt][nt];
            if (mode == 0) {
                *reinterpret_cast<float2*>(&Ofp[oOff + (long)row_lo * ldo + col]) =
                    make_float2(c[0], c[1]);
                *reinterpret_cast<float2*>(&Ofp[oOff + (long)row_hi * ldo + col]) =
                    make_float2(c[2], c[3]);
            } else {
                const long hb = oOff + (long)(col >> 6) * headStride + (col & 63);
                const long i0 = hb + (long)row_lo * 64;
                const long i1 = hb + (long)row_hi * 64;
                uint32_t h0, l0, h1, l1;
                split_pair(c[0], c[1], h0, l0);
                split_pair(c[2], c[3], h1, l1);
                *reinterpret_cast<uint32_t*>(&Oh[i0]) = h0;
                *reinterpret_cast<uint32_t*>(&Ol[i0]) = l0;
                *reinterpret_cast<uint32_t*>(&Oh[i1]) = h1;
                *reinterpret_cast<uint32_t*>(&Ol[i1]) = l1;
            }
        }
    }
}

// ---------------------------------------------------------------------------
// Flash attention, bf16x3, cp.async double-buffered K/V, parallel softmax.
// 64 queries/block, 256 threads. V supplied pre-transposed [bh][v][c].
// ---------------------------------------------------------------------------
#define ATA  9216                   // one K/V array stage: 64*72*2B
#define AT_KH 0                     // 2 stages
#define AT_KL (2 * ATA)
#define AT_VH (4 * ATA)
#define AT_VL (6 * ATA)
#define AT_QH (8 * ATA)             // 73728
#define AT_QL (AT_QH + ATA)
#define AT_SS (AT_QH + 2 * ATA)     // 92160 : [64][66] fp32
#define AT_SM (AT_SS + 64 * 66 * 4) // 109056 : m,l,a
#define AT_TOTAL (AT_SM + 3 * 64 * 4)  // 109824

__global__ void __launch_bounds__(256, 2)
attn_kernel(const __nv_bfloat16* __restrict__ qh_g, const __nv_bfloat16* __restrict__ ql_g,
            const __nv_bfloat16* __restrict__ kh_g, const __nv_bfloat16* __restrict__ kl_g,
            const __nv_bfloat16* __restrict__ vth_g, const __nv_bfloat16* __restrict__ vtl_g,
            __nv_bfloat16* __restrict__ ph_g, __nv_bfloat16* __restrict__ pl_g)
{
    const int b = blockIdx.z, h = blockIdx.y, d0 = blockIdx.x * 64;
    const int bh = b * H_ + h;

    extern __shared__ char smem[];
    const uint32_t sb = smem_u32(smem);
    __nv_bfloat16* sQh = (__nv_bfloat16*)(smem + AT_QH);
    __nv_bfloat16* sQl = (__nv_bfloat16*)(smem + AT_QL);
    float* Ss   = (float*)(smem + AT_SS);
    float* sm_m = (float*)(smem + AT_SM);
    float* sm_l = sm_m + 64;
    float* sm_a = sm_m + 128;

    const int tid = threadIdx.x;
    const int wid = tid >> 5, lane = tid & 31;
    const int lq = lane >> 2, lr = lane & 3;
    const int dtile = (wid >> 1) * 16;
    const int half  = (wid & 1) * 32;
    const int r0 = dtile + lq;

    const __nv_bfloat16* Kh_g = kh_g + (long)bh * C_ * 64;
    const __nv_bfloat16* Kl_g = kl_g + (long)bh * C_ * 64;
    const __nv_bfloat16* Vh_g = vth_g + (long)bh * 64 * C_;
    const __nv_bfloat16* Vl_g = vtl_g + (long)bh * 64 * C_;

    // Q tile
#pragma unroll
    for (int l = 0; l < 2; l++) {
        int e = tid + l * 256;
        int r = e >> 3, q = (e & 7) * 8;
        long g = ((long)bh * C_ + d0 + r) * 64 + q;
        *reinterpret_cast<uint4*>(&sQh[r * 72 + q]) =
            *reinterpret_cast<const uint4*>(&qh_g[g]);
        *reinterpret_cast<uint4*>(&sQl[r * 72 + q]) =
            *reinterpret_cast<const uint4*>(&ql_g[g]);
    }
    if (tid < 64) { sm_m[tid] = -1e30f; sm_l[tid] = 0.0f; }

    // cp.async geometry: e in {tid, tid+256}: r = e>>3 (0..63), q = e&7
    const int r_a = tid >> 3, q_a = tid & 7;
    const int r_b = (tid + 256) >> 3, q_b = (tid + 256) & 7;

    auto issue = [&](int t, int s) {
        const int c0 = t * 64;
        const uint32_t kh_d = sb + AT_KH + s * ATA;
        const uint32_t kl_d = sb + AT_KL + s * ATA;
        const uint32_t vh_d = sb + AT_VH + s * ATA;
        const uint32_t vl_d = sb + AT_VL + s * ATA;
        CP_ASYNC16(kh_d + r_a * 144 + q_a * 16, Kh_g + (long)(c0 + r_a) * 64 + q_a * 8);
        CP_ASYNC16(kh_d + r_b * 144 + q_b * 16, Kh_g + (long)(c0 + r_b) * 64 + q_b * 8);
        CP_ASYNC16(kl_d + r_a * 144 + q_a * 16, Kl_g + (long)(c0 + r_a) * 64 + q_a * 8);
        CP_ASYNC16(kl_d + r_b * 144 + q_b * 16, Kl_g + (long)(c0 + r_b) * 64 + q_b * 8);
        CP_ASYNC16(vh_d + r_a * 144 + q_a * 16, Vh_g + (long)r_a * C_ + c0 + q_a * 8);
        CP_ASYNC16(vh_d + r_b * 144 + q_b * 16, Vh_g + (long)r_b * C_ + c0 + q_b * 8);
        CP_ASYNC16(vl_d + r_a * 144 + q_a * 16, Vl_g + (long)r_a * C_ + c0 + q_a * 8);
        CP_ASYNC16(vl_d + r_b * 144 + q_b * 16, Vl_g + (long)r_b * C_ + c0 + q_b * 8);
    };

    issue(0, 0);
    CP_COMMIT();
    __syncthreads();

    // persistent Q fragments
    uint32_t qh[4][4], ql[4][4];
#pragma unroll
    for (int ks = 0; ks < 4; ks++) {
        const int k0 = ks * 16 + lr * 2;
        qh[ks][0] = *reinterpret_cast<const uint32_t*>(&sQh[r0 * 72 + k0]);
        qh[ks][1] = *reinterpret_cast<const uint32_t*>(&sQh[(r0 + 8) * 72 + k0]);
        qh[ks][2] = *reinterpret_cast<const uint32_t*>(&sQh[r0 * 72 + k0 + 8]);
        qh[ks][3] = *reinterpret_cast<const uint32_t*>(&sQh[(r0 + 8) * 72 + k0 + 8]);
        ql[ks][0] = *reinterpret_cast<const uint32_t*>(&sQl[r0 * 72 + k0]);
        ql[ks][1] = *reinterpret_cast<const uint32_t*>(&sQl[(r0 + 8) * 72 + k0]);
        ql[ks][2] = *reinterpret_cast<const uint32_t*>(&sQl[r0 * 72 + k0 + 8]);
        ql[ks][3] = *reinterpret_cast<const uint32_t*>(&sQl[(r0 + 8) * 72 + k0 + 8]);
    }

    float oacc[4][4];
#pragma unroll
    for (int i = 0; i < 4; i++)
#pragma unroll
        for (int j = 0; j < 4; j++) oacc[i][j] = 0.0f;

    const int ntiles = C_ / 64;
    for (int t = 0; t < ntiles; t++) {
        if (t + 1 < ntiles) {
            issue(t + 1, (t + 1) & 1);
            CP_COMMIT();
            CP_WAIT1();
        } else {
            CP_WAIT0();
        }
        __syncthreads();

        const int s = t & 1;
        const int c0 = t * 64;
        const __nv_bfloat16* sKh = (const __nv_bfloat16*)(smem + AT_KH + s * ATA);
        const __nv_bfloat16* sKl = (const __nv_bfloat16*)(smem + AT_KL + s * ATA);
        const __nv_bfloat16* sVh = (const __nv_bfloat16*)(smem + AT_VH + s * ATA);
        const __nv_bfloat16* sVl = (const __nv_bfloat16*)(smem + AT_VL + s * ATA);

        // ---- S = Q @ K^T ----
        float sacc[4][4];
#pragma unroll
        for (int i = 0; i < 4; i++)
#pragma unroll
            for (int j = 0; j < 4; j++) sacc[i][j] = 0.0f;
#pragma unroll
        for (int ks = 0; ks < 4; ks++) {
            const int k0 = ks * 16 + lr * 2;
#pragma unroll
            for (int nt = 0; nt < 4; nt++) {
                const int n0 = half + nt * 8 + lq;
                uint32_t bh2[2], bl2[2];
                bh2[0] = *reinterpret_cast<const uint32_t*>(&sKh[n0 * 72 + k0]);
                bh2[1] = *reinterpret_cast<const uint32_t*>(&sKh[n0 * 72 + k0 + 8]);
                bl2[0] = *reinterpret_cast<const uint32_t*>(&sKl[n0 * 72 + k0]);
                bl2[1] = *reinterpret_cast<const uint32_t*>(&sKl[n0 * 72 + k0 + 8]);
                mma16816(sacc[nt], qh[ks], bh2);
                mma16816(sacc[nt], qh[ks], bl2);
                mma16816(sacc[nt], ql[ks], bh2);
            }
        }
        // mask + scale -> Ss
        {
            const int dg0 = d0 + r0, dg1 = d0 + r0 + 8;
#pragma unroll
            for (int nt = 0; nt < 4; nt++) {
                const int col = half + nt * 8 + lr * 2;
                const int cg = c0 + col;
                float v0 = sacc[nt][0]; if (cg     <= dg0) v0 -= 100.0f;
                float v1 = sacc[nt][1]; if (cg + 1 <= dg0) v1 -= 100.0f;
                float v2 = sacc[nt][2]; if (cg     <= dg1) v2 -= 100.0f;
                float v3 = sacc[nt][3]; if (cg + 1 <= dg1) v3 -= 100.0f;
                Ss[r0 * 66 + col]           = v0 * 0.125f;
                Ss[r0 * 66 + col + 1]       = v1 * 0.125f;
                Ss[(r0 + 8) * 66 + col]     = v2 * 0.125f;
                Ss[(r0 + 8) * 66 + col + 1] = v3 * 0.125f;
            }
        }
        __syncthreads();

        // ---- online softmax: 4 threads per row ----
        {
            const int row = tid >> 2, part = tid & 3;
            float* rp = &Ss[row * 66 + part * 16];
            float mt = rp[0];
#pragma unroll
            for (int j = 1; j < 16; j++) mt = fmaxf(mt, rp[j]);
            mt = fmaxf(mt, __shfl_xor_sync(0xffffffff, mt, 1));
            mt = fmaxf(mt, __shfl_xor_sync(0xffffffff, mt, 2));
            const float mold = sm_m[row];
            const float mnew = fmaxf(mold, mt);
            float sum = 0.0f;
#pragma unroll
            for (int j = 0; j < 16; j++) {
                float p = __expf(rp[j] - mnew);
                rp[j] = p;
                sum += p;
            }
            sum += __shfl_xor_sync(0xffffffff, sum, 1);
            sum += __shfl_xor_sync(0xffffffff, sum, 2);
            if (part == 0) {
                const float alpha = __expf(mold - mnew);
                sm_l[row] = sm_l[row] * alpha + sum;
                sm_m[row] = mnew;
                sm_a[row] = alpha;
            }
        }
        __syncthreads();

        // ---- O = O*alpha + P @ V ----
        {
            const float al0 = sm_a[r0], al1 = sm_a[r0 + 8];
#pragma unroll
            for (int nt = 0; nt < 4; nt++) {
                oacc[nt][0] *= al0; oacc[nt][1] *= al0;
                oacc[nt][2] *= al1; oacc[nt][3] *= al1;
            }
        }
#pragma unroll
        for (int ks = 0; ks < 4; ks++) {
            const int kc = ks * 16 + lr * 2;
            uint32_t ph[4], pl[4];
            float2 p0 = *reinterpret_cast<const float2*>(&Ss[r0 * 66 + kc]);
            float2 p1 = *reinterpret_cast<const float2*>(&Ss[(r0 + 8) * 66 + kc]);
            float2 p2 = *reinterpret_cast<const float2*>(&Ss[r0 * 66 + kc + 8]);
            float2 p3 = *reinterpret_cast<const float2*>(&Ss[(r0 + 8) * 66 + kc + 8]);
            split_pair(p0.x, p0.y, ph[0], pl[0]);
            split_pair(p1.x, p1.y, ph[1], pl[1]);
            split_pair(p2.x, p2.y, ph[2], pl[2]);
            split_pair(p3.x, p3.y, ph[3], pl[3]);
#pragma unroll
            for (int nt = 0; nt < 4; nt++) {
                const int n0 = half + nt * 8 + lq;
                uint32_t bh2[2], bl2[2];
                bh2[0] = *reinterpret_cast<const uint32_t*>(&sVh[n0 * 72 + kc]);
                bh2[1] = *reinterpret_cast<const uint32_t*>(&sVh[n0 * 72 + kc + 8]);
                bl2[0] = *reinterpret_cast<const uint32_t*>(&sVl[n0 * 72 + kc]);
                bl2[1] = *reinterpret_cast<const uint32_t*>(&sVl[n0 * 72 + kc + 8]);
                mma16816(oacc[nt], ph, bh2);
                mma16816(oacc[nt], ph, bl2);
                mma16816(oacc[nt], pl, bh2);
            }
        }
        __syncthreads();
    }

    // epilogue -> pre (hi/lo), layout [b*C + d][h*64 + v]
    {
        const float il0 = 1.0f / sm_l[r0];
        const float il1 = 1.0f / sm_l[r0 + 8];
#pragma unroll
        for (int nt = 0; nt < 4; nt++) {
            const int col = h * 64 + half + nt * 8 + lr * 2;
            const long i0 = ((long)(b * C_ + d0 + r0)) * (H_ * V_) + col;
            const long i1 = ((long)(b * C_ + d0 + r0 + 8)) * (H_ * V_) + col;
            uint32_t h0, l0, h1, l1;
            split_pair(oacc[nt][0] * il0, oacc[nt][1] * il0, h0, l0);
            split_pair(oacc[nt][2] * il1, oacc[nt][3] * il1, h1, l1);
            *reinterpret_cast<uint32_t*>(&ph_g[i0]) = h0;
            *reinterpret_cast<uint32_t*>(&pl_g[i0]) = l0;
            *reinterpret_cast<uint32_t*>(&ph_g[i1]) = h1;
            *reinterpret_cast<uint32_t*>(&pl_g[i1]) = l1;
        }
    }
}

// ---------------------------------------------------------------------------

extern "C" void kernel_launch(void* const* d_in, const int* in_sizes, int n_in,
                              void* d_out, int out_size)
{
    const float* kvinput = (const float*)d_in[0];
    const float* qinput  = (const float*)d_in[1];
    const float* wq      = (const float*)d_in[2];
    const float* wk      = (const float*)d_in[3];
    const float* wv      = (const float*)d_in[4];
    const float* wo      = (const float*)d_in[5];
    float* out = (float*)d_out;

    __nv_bfloat16 *xqh, *xql, *xkh, *xkl;
    __nv_bfloat16 *wqh, *wql, *wkh, *wkl, *wvh, *wvl, *woh, *wol;
    __nv_bfloat16 *qh, *ql, *kh, *kl, *vh, *vl, *vth, *vtl, *prh, *prl;
    cudaGetSymbolAddress((void**)&xqh, s_xq_hi);
    cudaGetSymbolAddress((void**)&xql, s_xq_lo);
    cudaGetSymbolAddress((void**)&xkh, s_xkv_hi);
    cudaGetSymbolAddress((void**)&xkl, s_xkv_lo);
    cudaGetSymbolAddress((void**)&wqh, s_wqT_hi);
    cudaGetSymbolAddress((void**)&wql, s_wqT_lo);
    cudaGetSymbolAddress((void**)&wkh, s_wkT_hi);
    cudaGetSymbolAddress((void**)&wkl, s_wkT_lo);
    cudaGetSymbolAddress((void**)&wvh, s_wvT_hi);
    cudaGetSymbolAddress((void**)&wvl, s_wvT_lo);
    cudaGetSymbolAddress((void**)&woh, s_woT_hi);
    cudaGetSymbolAddress((void**)&wol, s_woT_lo);
    cudaGetSymbolAddress((void**)&qh,  s_q_hi);
    cudaGetSymbolAddress((void**)&ql,  s_q_lo);
    cudaGetSymbolAddress((void**)&kh,  s_k_hi);
    cudaGetSymbolAddress((void**)&kl,  s_k_lo);
    cudaGetSymbolAddress((void**)&vh,  s_v_hi);
    cudaGetSymbolAddress((void**)&vl,  s_v_lo);
    cudaGetSymbolAddress((void**)&vth, s_vT_hi);
    cudaGetSymbolAddress((void**)&vtl, s_vT_lo);
    cudaGetSymbolAddress((void**)&prh, s_pre_hi);
    cudaGetSymbolAddress((void**)&prl, s_pre_lo);

    cudaFuncSetAttribute(gemm_bf16x3,
                         cudaFuncAttributeMaxDynamicSharedMemorySize, GEMM_SMEM2);
    cudaFuncSetAttribute(attn_kernel,
                         cudaFuncAttributeMaxDynamicSharedMemorySize, AT_TOTAL);

    // ---- pre-pass ----
    {
        int n4 = B_ * C_ * M_ / 4;
        split_kernel<<<(n4 + 255) / 256, 256>>>(qinput,  xqh, xql, n4);
        split_kernel<<<(n4 + 255) / 256, 256>>>(kvinput, xkh, xkl, n4);
    }
    {
        dim3 tb(32, 8);
        dim3 gw(K_ / 32, M_ / 32, H_);
        transpose_split_kernel<<<gw, tb>>>(wq, wqh, wql, M_, K_,
                                           (long)M_ * K_, (long)K_ * M_);
        transpose_split_kernel<<<gw, tb>>>(wk, wkh, wkl, M_, K_,
                                           (long)M_ * K_, (long)K_ * M_);
        transpose_split_kernel<<<gw, tb>>>(wv, wvh, wvl, M_, V_,
                                           (long)M_ * V_, (long)V_ * M_);
        dim3 go(M_ / 32, (H_ * V_) / 32, 1);
        transpose_split_kernel<<<go, tb>>>(wo, woh, wol, H_ * V_, M_, 0L, 0L);
    }

    dim3 blk(256);

    // ---- projections: 128x128 tiles, 2 heads per y-block ----
    dim3 pgrid(C_ / 128, H_ / 2, B_);
    const long hs = (long)C_ * 64;     // headStride
    gemm_bf16x3<<<pgrid, blk, GEMM_SMEM2>>>(xqh, xql, wqh, wql,
        nullptr, qh, ql, M_, 1, 0, hs,
        (long)C_ * M_, (long)128 * M_, 2 * hs, (long)H_ * C_ * 64);
    gemm_bf16x3<<<pgrid, blk, GEMM_SMEM2>>>(xkh, xkl, wkh, wkl,
        nullptr, kh, kl, M_, 1, 0, hs,
        (long)C_ * M_, (long)128 * M_, 2 * hs, (long)H_ * C_ * 64);
    gemm_bf16x3<<<pgrid, blk, GEMM_SMEM2>>>(xkh, xkl, wvh, wvl,
        nullptr, vh, vl, M_, 1, 0, hs,
        (long)C_ * M_, (long)128 * M_, 2 * hs, (long)H_ * C_ * 64);

    // ---- V transpose: [bh][c][v] -> [bh][v][c] ----
    {
        dim3 vg(C_ / 64, B_ * H_);
        vtrans_kernel<<<vg, 256>>>(vh, vl, vth, vtl);
    }

    // ---- attention ----
    dim3 agrid(C_ / 64, H_, B_);
    attn_kernel<<<agrid, blk, AT_TOTAL>>>(qh, ql, kh, kl, vth, vtl, prh, prl);

    // ---- output projection: out[4096][1024] = pre @ woT ----
    dim3 ogrid((B_ * C_) / 128, M_ / 128, 1);
    gemm_bf16x3<<<ogrid, blk, GEMM_SMEM2>>>(prh, prl, woh, wol,
        out, nullptr, nullptr, M_, 0, M_, 0L,
        0L, (long)128 * M_, 128L, 0L);
}

// round 5
// speedup vs baseline: 2.7533x; 1.2300x over previous
#include <cuda_runtime.h>
#include <cuda_bf16.h>
#include <cstdint>
#include <math.h>

#define B_ 2
#define C_ 2048
#define M_ 1024
#define H_ 16
#define K_ 64
#define V_ 64

// ------------------------- scratch (no cudaMalloc) -------------------------
__device__ __nv_bfloat16 s_xq_hi [(size_t)B_ * C_ * M_];
__device__ __nv_bfloat16 s_xq_lo [(size_t)B_ * C_ * M_];
__device__ __nv_bfloat16 s_xkv_hi[(size_t)B_ * C_ * M_];
__device__ __nv_bfloat16 s_xkv_lo[(size_t)B_ * C_ * M_];

__device__ __nv_bfloat16 s_wqT_hi [(size_t)H_ * K_ * M_];
__device__ __nv_bfloat16 s_wqT_lo [(size_t)H_ * K_ * M_];
__device__ __nv_bfloat16 s_wkvT_hi[(size_t)H_ * 128 * M_];   // rows 0-63 K, 64-127 V
__device__ __nv_bfloat16 s_wkvT_lo[(size_t)H_ * 128 * M_];
__device__ __nv_bfloat16 s_woT_hi [(size_t)M_ * (H_ * V_)];
__device__ __nv_bfloat16 s_woT_lo [(size_t)M_ * (H_ * V_)];

__device__ __nv_bfloat16 s_q_hi [(size_t)B_ * H_ * C_ * K_];
__device__ __nv_bfloat16 s_q_lo [(size_t)B_ * H_ * C_ * K_];
__device__ __nv_bfloat16 s_kv_hi[(size_t)B_ * H_ * 2 * C_ * 64];  // [bh][0]=K,[bh][1]=V
__device__ __nv_bfloat16 s_kv_lo[(size_t)B_ * H_ * 2 * C_ * 64];
__device__ __nv_bfloat16 s_vT_hi[(size_t)B_ * H_ * V_ * C_];
__device__ __nv_bfloat16 s_vT_lo[(size_t)B_ * H_ * V_ * C_];

__device__ __nv_bfloat16 s_pre_hi[(size_t)B_ * C_ * (H_ * V_)];
__device__ __nv_bfloat16 s_pre_lo[(size_t)B_ * C_ * (H_ * V_)];

// ------------------------------ helpers ------------------------------------
__device__ __forceinline__ void split_pair(float x, float y,
                                           uint32_t& hi, uint32_t& lo) {
    __nv_bfloat162 h = __floats2bfloat162_rn(x, y);
    float hx = __bfloat162float(h.x);
    float hy = __bfloat162float(h.y);
    __nv_bfloat162 l = __floats2bfloat162_rn(x - hx, y - hy);
    hi = *reinterpret_cast<uint32_t*>(&h);
    lo = *reinterpret_cast<uint32_t*>(&l);
}

__device__ __forceinline__ void mma16816(float* c, const uint32_t* a,
                                         const uint32_t* b) {
    asm volatile(
        "mma.sync.aligned.m16n8k16.row.col.f32.bf16.bf16.f32 "
        "{%0,%1,%2,%3}, {%4,%5,%6,%7}, {%8,%9}, {%0,%1,%2,%3};\n"
        : "+f"(c[0]), "+f"(c[1]), "+f"(c[2]), "+f"(c[3])
        : "r"(a[0]), "r"(a[1]), "r"(a[2]), "r"(a[3]), "r"(b[0]), "r"(b[1]));
}

__device__ __forceinline__ uint32_t smem_u32(const void* p) {
    uint32_t a;
    asm("{ .reg .u64 t; cvta.to.shared.u64 t, %1; cvt.u32.u64 %0, t; }"
        : "=r"(a) : "l"(p));
    return a;
}
#define CP_ASYNC16(dst, src) \
    asm volatile("cp.async.ca.shared.global [%0], [%1], 16;\n" \
                 :: "r"(dst), "l"(src) : "memory")
#define CP_COMMIT() asm volatile("cp.async.commit_group;\n" ::: "memory")
#define CP_WAIT0()  asm volatile("cp.async.wait_group 0;\n" ::: "memory")
#define CP_WAIT1()  asm volatile("cp.async.wait_group 1;\n" ::: "memory")

// --------------------------- pre-pass kernels ------------------------------
__global__ void split_kernel(const float* __restrict__ in,
                             __nv_bfloat16* __restrict__ oh,
                             __nv_bfloat16* __restrict__ ol, int n4) {
    int i = blockIdx.x * blockDim.x + threadIdx.x;
    if (i < n4) {
        float4 v = reinterpret_cast<const float4*>(in)[i];
        uint32_t h0, l0, h1, l1;
        split_pair(v.x, v.y, h0, l0);
        split_pair(v.z, v.w, h1, l1);
        reinterpret_cast<uint2*>(oh)[i] = make_uint2(h0, h1);
        reinterpret_cast<uint2*>(ol)[i] = make_uint2(l0, l1);
    }
}

__global__ void transpose_split_kernel(const float* __restrict__ in,
                                       __nv_bfloat16* __restrict__ oh,
                                       __nv_bfloat16* __restrict__ ol,
                                       int R, int Cdim,
                                       long inStrideZ, long outStrideZ) {
    __shared__ float t[32][33];
    in += (long)blockIdx.z * inStrideZ;
    const long ob = (long)blockIdx.z * outStrideZ;
    const int c0 = blockIdx.x * 32, r0 = blockIdx.y * 32;
#pragma unroll
    for (int i = threadIdx.y; i < 32; i += 8)
        t[i][threadIdx.x] = in[(long)(r0 + i) * Cdim + c0 + threadIdx.x];
    __syncthreads();
#pragma unroll
    for (int i = threadIdx.y; i < 32; i += 8) {
        float v = t[threadIdx.x][i];
        __nv_bfloat16 h = __float2bfloat16(v);
        __nv_bfloat16 l = __float2bfloat16(v - __bfloat162float(h));
        long idx = ob + (long)(c0 + i) * R + r0 + threadIdx.x;
        oh[idx] = h;
        ol[idx] = l;
    }
}

// V (in combined KV) [bh][1][c][v] -> VT [bh][v][c] for hi and lo
__global__ void vtrans_kernel(const __nv_bfloat16* __restrict__ kvh,
                              const __nv_bfloat16* __restrict__ kvl,
                              __nv_bfloat16* __restrict__ oth,
                              __nv_bfloat16* __restrict__ otl) {
    const int bh = blockIdx.y;
    const int c0 = blockIdx.x * 64;
    const long ib = ((long)bh * 2 + 1) * C_ * 64;
    const long ob = (long)bh * 64 * C_;
    __shared__ __nv_bfloat16 t[64][68];
    const int tid = threadIdx.x;

    for (int pass = 0; pass < 2; pass++) {
        const __nv_bfloat16* src = pass ? kvl : kvh;
        __nv_bfloat16* dst = pass ? otl : oth;
#pragma unroll
        for (int l = 0; l < 4; l++) {
            int e = tid + l * 256;
            int c = e >> 4, v4 = (e & 15) * 4;
            *reinterpret_cast<uint2*>(&t[c][v4]) =
                *reinterpret_cast<const uint2*>(&src[ib + (long)(c0 + c) * 64 + v4]);
        }
        __syncthreads();
#pragma unroll
        for (int l = 0; l < 4; l++) {
            int e = tid + l * 256;
            int v = e >> 4, c4 = (e & 15) * 4;
            __nv_bfloat16 tmp[4] = {t[c4][v], t[c4 + 1][v], t[c4 + 2][v], t[c4 + 3][v]};
            *reinterpret_cast<uint2*>(&dst[ob + (long)v * C_ + c0 + c4]) =
                *reinterpret_cast<const uint2*>(tmp);
        }
        __syncthreads();
    }
}

// ---------------------------------------------------------------------------
// bf16x3 GEMM, 128x128 tile, K-chunk 32, cp.async double-buffered.
// mode 0: fp32 out, idx = oOff + row*ldo + col
// mode 1: split bf16 out, idx = oOff + (col>>6)*headStride + row*64 + (col&63)
// ---------------------------------------------------------------------------
#define GS 40
#define GARR (128 * GS * 2)
#define GBUF (4 * GARR)
#define GEMM_SMEM2 (2 * GBUF)

__global__ void __launch_bounds__(256, 2)
gemm_bf16x3(const __nv_bfloat16* __restrict__ Ah, const __nv_bfloat16* __restrict__ Al,
            const __nv_bfloat16* __restrict__ Wh, const __nv_bfloat16* __restrict__ Wl,
            float* __restrict__ Ofp,
            __nv_bfloat16* __restrict__ Oh, __nv_bfloat16* __restrict__ Ol,
            int inner, int mode, int ldo, long headStride,
            long aOffZ, long wOffY, long oOffY, long oOffZ)
{
    const long aOff = (long)blockIdx.z * aOffZ;
    const long wOff = (long)blockIdx.y * wOffY;
    const long oOff = (long)blockIdx.z * oOffZ + (long)blockIdx.y * oOffY;
    const int row0 = blockIdx.x * 128;

    extern __shared__ char smem[];
    const uint32_t sb = smem_u32(smem);

    const int tid = threadIdx.x;
    const int wid = tid >> 5, lane = tid & 31;
    const int lq = lane >> 2, lr = lane & 3;
    const int wm = wid >> 1, wn = wid & 1;

    const int r_a = tid >> 2, q_a = tid & 3;
    const int r_b = (tid + 256) >> 2, q_b = (tid + 256) & 3;

    float acc[2][8][4];
#pragma unroll
    for (int a = 0; a < 2; a++)
#pragma unroll
        for (int b = 0; b < 8; b++)
#pragma unroll
            for (int c = 0; c < 4; c++) acc[a][b][c] = 0.0f;

    const int nch = inner >> 5;

    auto issue = [&](int ck, int s) {
        const int m0 = ck << 5;
        const uint32_t base = sb + s * GBUF;
        {
            const __nv_bfloat16* s0 = Ah + aOff + (long)(row0 + r_a) * inner + m0 + q_a * 8;
            const __nv_bfloat16* s1 = Ah + aOff + (long)(row0 + r_b) * inner + m0 + q_b * 8;
            CP_ASYNC16(base + r_a * 80 + q_a * 16, s0);
            CP_ASYNC16(base + r_b * 80 + q_b * 16, s1);
            const __nv_bfloat16* s2 = Al + aOff + (long)(row0 + r_a) * inner + m0 + q_a * 8;
            const __nv_bfloat16* s3 = Al + aOff + (long)(row0 + r_b) * inner + m0 + q_b * 8;
            CP_ASYNC16(base + GARR + r_a * 80 + q_a * 16, s2);
            CP_ASYNC16(base + GARR + r_b * 80 + q_b * 16, s3);
        }
        {
            const __nv_bfloat16* s0 = Wh + wOff + (long)r_a * inner + m0 + q_a * 8;
            const __nv_bfloat16* s1 = Wh + wOff + (long)r_b * inner + m0 + q_b * 8;
            CP_ASYNC16(base + 2 * GARR + r_a * 80 + q_a * 16, s0);
            CP_ASYNC16(base + 2 * GARR + r_b * 80 + q_b * 16, s1);
            const __nv_bfloat16* s2 = Wl + wOff + (long)r_a * inner + m0 + q_a * 8;
            const __nv_bfloat16* s3 = Wl + wOff + (long)r_b * inner + m0 + q_b * 8;
            CP_ASYNC16(base + 3 * GARR + r_a * 80 + q_a * 16, s2);
            CP_ASYNC16(base + 3 * GARR + r_b * 80 + q_b * 16, s3);
        }
    };

    issue(0, 0);
    CP_COMMIT();

    for (int it = 0; it < nch; it++) {
        if (it + 1 < nch) {
            issue(it + 1, (it + 1) & 1);
            CP_COMMIT();
            CP_WAIT1();
        } else {
            CP_WAIT0();
        }
        __syncthreads();

        const char* cb = smem + (it & 1) * GBUF;
        const __nv_bfloat16* sAh = (const __nv_bfloat16*)(cb);
        const __nv_bfloat16* sAl = (const __nv_bfloat16*)(cb + GARR);
        const __nv_bfloat16* sWh = (const __nv_bfloat16*)(cb + 2 * GARR);
        const __nv_bfloat16* sWl = (const __nv_bfloat16*)(cb + 3 * GARR);

#pragma unroll
        for (int ks = 0; ks < 2; ks++) {
            const int k0 = ks * 16 + lr * 2;
            uint32_t ah[2][4], al[2][4];
#pragma unroll
            for (int mt = 0; mt < 2; mt++) {
                const int r = wm * 32 + mt * 16 + lq;
                ah[mt][0] = *reinterpret_cast<const uint32_t*>(&sAh[r * GS + k0]);
                ah[mt][1] = *reinterpret_cast<const uint32_t*>(&sAh[(r + 8) * GS + k0]);
                ah[mt][2] = *reinterpret_cast<const uint32_t*>(&sAh[r * GS + k0 + 8]);
                ah[mt][3] = *reinterpret_cast<const uint32_t*>(&sAh[(r + 8) * GS + k0 + 8]);
                al[mt][0] = *reinterpret_cast<const uint32_t*>(&sAl[r * GS + k0]);
                al[mt][1] = *reinterpret_cast<const uint32_t*>(&sAl[(r + 8) * GS + k0]);
                al[mt][2] = *reinterpret_cast<const uint32_t*>(&sAl[r * GS + k0 + 8]);
                al[mt][3] = *reinterpret_cast<const uint32_t*>(&sAl[(r + 8) * GS + k0 + 8]);
            }
#pragma unroll
            for (int nt = 0; nt < 8; nt++) {
                const int n = wn * 64 + nt * 8 + lq;
                uint32_t bh[2], bl[2];
                bh[0] = *reinterpret_cast<const uint32_t*>(&sWh[n * GS + k0]);
                bh[1] = *reinterpret_cast<const uint32_t*>(&sWh[n * GS + k0 + 8]);
                bl[0] = *reinterpret_cast<const uint32_t*>(&sWl[n * GS + k0]);
                bl[1] = *reinterpret_cast<const uint32_t*>(&sWl[n * GS + k0 + 8]);
#pragma unroll
                for (int mt = 0; mt < 2; mt++) {
                    mma16816(acc[mt][nt], ah[mt], bh);
                    mma16816(acc[mt][nt], ah[mt], bl);
                    mma16816(acc[mt][nt], al[mt], bh);
                }
            }
        }
        __syncthreads();
    }

#pragma unroll
    for (int mt = 0; mt < 2; mt++) {
        const int row_lo = row0 + wm * 32 + mt * 16 + lq;
        const int row_hi = row_lo + 8;
#pragma unroll
        for (int nt = 0; nt < 8; nt++) {
            const int col = wn * 64 + nt * 8 + lr * 2;
            const float* c = acc[mt][nt];
            if (mode == 0) {
                *reinterpret_cast<float2*>(&Ofp[oOff + (long)row_lo * ldo + col]) =
                    make_float2(c[0], c[1]);
                *reinterpret_cast<float2*>(&Ofp[oOff + (long)row_hi * ldo + col]) =
                    make_float2(c[2], c[3]);
            } else {
                const long hb = oOff + (long)(col >> 6) * headStride + (col & 63);
                const long i0 = hb + (long)row_lo * 64;
                const long i1 = hb + (long)row_hi * 64;
                uint32_t h0, l0, h1, l1;
                split_pair(c[0], c[1], h0, l0);
                split_pair(c[2], c[3], h1, l1);
                *reinterpret_cast<uint32_t*>(&Oh[i0]) = h0;
                *reinterpret_cast<uint32_t*>(&Ol[i0]) = l0;
                *reinterpret_cast<uint32_t*>(&Oh[i1]) = h1;
                *reinterpret_cast<uint32_t*>(&Ol[i1]) = l1;
            }
        }
    }
}

// ---------------------------------------------------------------------------
// Flash attention, bf16x3, cp.async double-buffered K/V, parallel softmax,
// and MASK-AWARE TILE SKIPPING: key tiles cb < qb are fully masked (weight
// e^-12.5) and skipped, except for the last query block (row 2047 has no
// unmasked keys — its softmax mass is entirely masked entries).
// ---------------------------------------------------------------------------
#define ATA  9216
#define AT_KH 0
#define AT_KL (2 * ATA)
#define AT_VH (4 * ATA)
#define AT_VL (6 * ATA)
#define AT_QH (8 * ATA)
#define AT_QL (AT_QH + ATA)
#define AT_SS (AT_QH + 2 * ATA)
#define AT_SM (AT_SS + 64 * 66 * 4)
#define AT_TOTAL (AT_SM + 3 * 64 * 4)

__global__ void __launch_bounds__(256, 2)
attn_kernel(const __nv_bfloat16* __restrict__ qh_g, const __nv_bfloat16* __restrict__ ql_g,
            const __nv_bfloat16* __restrict__ kvh_g, const __nv_bfloat16* __restrict__ kvl_g,
            const __nv_bfloat16* __restrict__ vth_g, const __nv_bfloat16* __restrict__ vtl_g,
            __nv_bfloat16* __restrict__ ph_g, __nv_bfloat16* __restrict__ pl_g)
{
    const int b = blockIdx.z, h = blockIdx.y;
    const int qb = blockIdx.x;
    const int d0 = qb * 64;
    const int bh = b * H_ + h;
    const int ntiles = C_ / 64;
    const int tstart = (qb == ntiles - 1) ? 0 : qb;

    extern __shared__ char smem[];
    const uint32_t sb = smem_u32(smem);
    __nv_bfloat16* sQh = (__nv_bfloat16*)(smem + AT_QH);
    __nv_bfloat16* sQl = (__nv_bfloat16*)(smem + AT_QL);
    float* Ss   = (float*)(smem + AT_SS);
    float* sm_m = (float*)(smem + AT_SM);
    float* sm_l = sm_m + 64;
    float* sm_a = sm_m + 128;

    const int tid = threadIdx.x;
    const int wid = tid >> 5, lane = tid & 31;
    const int lq = lane >> 2, lr = lane & 3;
    const int dtile = (wid >> 1) * 16;
    const int half  = (wid & 1) * 32;
    const int r0 = dtile + lq;

    const __nv_bfloat16* Kh_g = kvh_g + ((long)bh * 2) * C_ * 64;
    const __nv_bfloat16* Kl_g = kvl_g + ((long)bh * 2) * C_ * 64;
    const __nv_bfloat16* Vh_g = vth_g + (long)bh * 64 * C_;
    const __nv_bfloat16* Vl_g = vtl_g + (long)bh * 64 * C_;

#pragma unroll
    for (int l = 0; l < 2; l++) {
        int e = tid + l * 256;
        int r = e >> 3, q = (e & 7) * 8;
        long g = ((long)bh * C_ + d0 + r) * 64 + q;
        *reinterpret_cast<uint4*>(&sQh[r * 72 + q]) =
            *reinterpret_cast<const uint4*>(&qh_g[g]);
        *reinterpret_cast<uint4*>(&sQl[r * 72 + q]) =
            *reinterpret_cast<const uint4*>(&ql_g[g]);
    }
    if (tid < 64) { sm_m[tid] = -1e30f; sm_l[tid] = 0.0f; }

    const int r_a = tid >> 3, q_a = tid & 7;
    const int r_b = (tid + 256) >> 3, q_b = (tid + 256) & 7;

    auto issue = [&](int t, int s) {
        const int c0 = t * 64;
        const uint32_t kh_d = sb + AT_KH + s * ATA;
        const uint32_t kl_d = sb + AT_KL + s * ATA;
        const uint32_t vh_d = sb + AT_VH + s * ATA;
        const uint32_t vl_d = sb + AT_VL + s * ATA;
        CP_ASYNC16(kh_d + r_a * 144 + q_a * 16, Kh_g + (long)(c0 + r_a) * 64 + q_a * 8);
        CP_ASYNC16(kh_d + r_b * 144 + q_b * 16, Kh_g + (long)(c0 + r_b) * 64 + q_b * 8);
        CP_ASYNC16(kl_d + r_a * 144 + q_a * 16, Kl_g + (long)(c0 + r_a) * 64 + q_a * 8);
        CP_ASYNC16(kl_d + r_b * 144 + q_b * 16, Kl_g + (long)(c0 + r_b) * 64 + q_b * 8);
        CP_ASYNC16(vh_d + r_a * 144 + q_a * 16, Vh_g + (long)r_a * C_ + c0 + q_a * 8);
        CP_ASYNC16(vh_d + r_b * 144 + q_b * 16, Vh_g + (long)r_b * C_ + c0 + q_b * 8);
        CP_ASYNC16(vl_d + r_a * 144 + q_a * 16, Vl_g + (long)r_a * C_ + c0 + q_a * 8);
        CP_ASYNC16(vl_d + r_b * 144 + q_b * 16, Vl_g + (long)r_b * C_ + c0 + q_b * 8);
    };

    issue(tstart, tstart & 1);
    CP_COMMIT();
    __syncthreads();

    uint32_t qh[4][4], ql[4][4];
#pragma unroll
    for (int ks = 0; ks < 4; ks++) {
        const int k0 = ks * 16 + lr * 2;
        qh[ks][0] = *reinterpret_cast<const uint32_t*>(&sQh[r0 * 72 + k0]);
        qh[ks][1] = *reinterpret_cast<const uint32_t*>(&sQh[(r0 + 8) * 72 + k0]);
        qh[ks][2] = *reinterpret_cast<const uint32_t*>(&sQh[r0 * 72 + k0 + 8]);
        qh[ks][3] = *reinterpret_cast<const uint32_t*>(&sQh[(r0 + 8) * 72 + k0 + 8]);
        ql[ks][0] = *reinterpret_cast<const uint32_t*>(&sQl[r0 * 72 + k0]);
        ql[ks][1] = *reinterpret_cast<const uint32_t*>(&sQl[(r0 + 8) * 72 + k0]);
        ql[ks][2] = *reinterpret_cast<const uint32_t*>(&sQl[r0 * 72 + k0 + 8]);
        ql[ks][3] = *reinterpret_cast<const uint32_t*>(&sQl[(r0 + 8) * 72 + k0 + 8]);
    }

    float oacc[4][4];
#pragma unroll
    for (int i = 0; i < 4; i++)
#pragma unroll
        for (int j = 0; j < 4; j++) oacc[i][j] = 0.0f;

    for (int t = tstart; t < ntiles; t++) {
        if (t + 1 < ntiles) {
            issue(t + 1, (t + 1) & 1);
            CP_COMMIT();
            CP_WAIT1();
        } else {
            CP_WAIT0();
        }
        __syncthreads();

        const int s = t & 1;
        const int c0 = t * 64;
        const __nv_bfloat16* sKh = (const __nv_bfloat16*)(smem + AT_KH + s * ATA);
        const __nv_bfloat16* sKl = (const __nv_bfloat16*)(smem + AT_KL + s * ATA);
        const __nv_bfloat16* sVh = (const __nv_bfloat16*)(smem + AT_VH + s * ATA);
        const __nv_bfloat16* sVl = (const __nv_bfloat16*)(smem + AT_VL + s * ATA);

        float sacc[4][4];
#pragma unroll
        for (int i = 0; i < 4; i++)
#pragma unroll
            for (int j = 0; j < 4; j++) sacc[i][j] = 0.0f;
#pragma unroll
        for (int ks = 0; ks < 4; ks++) {
            const int k0 = ks * 16 + lr * 2;
#pragma unroll
            for (int nt = 0; nt < 4; nt++) {
                const int n0 = half + nt * 8 + lq;
                uint32_t bh2[2], bl2[2];
                bh2[0] = *reinterpret_cast<const uint32_t*>(&sKh[n0 * 72 + k0]);
                bh2[1] = *reinterpret_cast<const uint32_t*>(&sKh[n0 * 72 + k0 + 8]);
                bl2[0] = *reinterpret_cast<const uint32_t*>(&sKl[n0 * 72 + k0]);
                bl2[1] = *reinterpret_cast<const uint32_t*>(&sKl[n0 * 72 + k0 + 8]);
                mma16816(sacc[nt], qh[ks], bh2);
                mma16816(sacc[nt], qh[ks], bl2);
                mma16816(sacc[nt], ql[ks], bh2);
            }
        }
        {
            const int dg0 = d0 + r0, dg1 = d0 + r0 + 8;
#pragma unroll
            for (int nt = 0; nt < 4; nt++) {
                const int col = half + nt * 8 + lr * 2;
                const int cg = c0 + col;
                float v0 = sacc[nt][0]; if (cg     <= dg0) v0 -= 100.0f;
                float v1 = sacc[nt][1]; if (cg + 1 <= dg0) v1 -= 100.0f;
                float v2 = sacc[nt][2]; if (cg     <= dg1) v2 -= 100.0f;
                float v3 = sacc[nt][3]; if (cg + 1 <= dg1) v3 -= 100.0f;
                Ss[r0 * 66 + col]           = v0 * 0.125f;
                Ss[r0 * 66 + col + 1]       = v1 * 0.125f;
                Ss[(r0 + 8) * 66 + col]     = v2 * 0.125f;
                Ss[(r0 + 8) * 66 + col + 1] = v3 * 0.125f;
            }
        }
        __syncthreads();

        {
            const int row = tid >> 2, part = tid & 3;
            float* rp = &Ss[row * 66 + part * 16];
            float mt = rp[0];
#pragma unroll
            for (int j = 1; j < 16; j++) mt = fmaxf(mt, rp[j]);
            mt = fmaxf(mt, __shfl_xor_sync(0xffffffff, mt, 1));
            mt = fmaxf(mt, __shfl_xor_sync(0xffffffff, mt, 2));
            const float mold = sm_m[row];
            const float mnew = fmaxf(mold, mt);
            float sum = 0.0f;
#pragma unroll
            for (int j = 0; j < 16; j++) {
                float p = __expf(rp[j] - mnew);
                rp[j] = p;
                sum += p;
            }
            sum += __shfl_xor_sync(0xffffffff, sum, 1);
            sum += __shfl_xor_sync(0xffffffff, sum, 2);
            if (part == 0) {
                const float alpha = __expf(mold - mnew);
                sm_l[row] = sm_l[row] * alpha + sum;
                sm_m[row] = mnew;
                sm_a[row] = alpha;
            }
        }
        __syncthreads();

        {
            const float al0 = sm_a[r0], al1 = sm_a[r0 + 8];
#pragma unroll
            for (int nt = 0; nt < 4; nt++) {
                oacc[nt][0] *= al0; oacc[nt][1] *= al0;
                oacc[nt][2] *= al1; oacc[nt][3] *= al1;
            }
        }
#pragma unroll
        for (int ks = 0; ks < 4; ks++) {
            const int kc = ks * 16 + lr * 2;
            uint32_t ph[4], pl[4];
            float2 p0 = *reinterpret_cast<const float2*>(&Ss[r0 * 66 + kc]);
            float2 p1 = *reinterpret_cast<const float2*>(&Ss[(r0 + 8) * 66 + kc]);
            float2 p2 = *reinterpret_cast<const float2*>(&Ss[r0 * 66 + kc + 8]);
            float2 p3 = *reinterpret_cast<const float2*>(&Ss[(r0 + 8) * 66 + kc + 8]);
            split_pair(p0.x, p0.y, ph[0], pl[0]);
            split_pair(p1.x, p1.y, ph[1], pl[1]);
            split_pair(p2.x, p2.y, ph[2], pl[2]);
            split_pair(p3.x, p3.y, ph[3], pl[3]);
#pragma unroll
            for (int nt = 0; nt < 4; nt++) {
                const int n0 = half + nt * 8 + lq;
                uint32_t bh2[2], bl2[2];
                bh2[0] = *reinterpret_cast<const uint32_t*>(&sVh[n0 * 72 + kc]);
                bh2[1] = *reinterpret_cast<const uint32_t*>(&sVh[n0 * 72 + kc + 8]);
                bl2[0] = *reinterpret_cast<const uint32_t*>(&sVl[n0 * 72 + kc]);
                bl2[1] = *reinterpret_cast<const uint32_t*>(&sVl[n0 * 72 + kc + 8]);
                mma16816(oacc[nt], ph, bh2);
                mma16816(oacc[nt], ph, bl2);
                mma16816(oacc[nt], pl, bh2);
            }
        }
        __syncthreads();
    }

    {
        const float il0 = 1.0f / sm_l[r0];
        const float il1 = 1.0f / sm_l[r0 + 8];
#pragma unroll
        for (int nt = 0; nt < 4; nt++) {
            const int col = h * 64 + half + nt * 8 + lr * 2;
            const long i0 = ((long)(b * C_ + d0 + r0)) * (H_ * V_) + col;
            const long i1 = ((long)(b * C_ + d0 + r0 + 8)) * (H_ * V_) + col;
            uint32_t h0, l0, h1, l1;
            split_pair(oacc[nt][0] * il0, oacc[nt][1] * il0, h0, l0);
            split_pair(oacc[nt][2] * il1, oacc[nt][3] * il1, h1, l1);
            *reinterpret_cast<uint32_t*>(&ph_g[i0]) = h0;
            *reinterpret_cast<uint32_t*>(&pl_g[i0]) = l0;
            *reinterpret_cast<uint32_t*>(&ph_g[i1]) = h1;
            *reinterpret_cast<uint32_t*>(&pl_g[i1]) = l1;
        }
    }
}

// ---------------------------------------------------------------------------

extern "C" void kernel_launch(void* const* d_in, const int* in_sizes, int n_in,
                              void* d_out, int out_size)
{
    const float* kvinput = (const float*)d_in[0];
    const float* qinput  = (const float*)d_in[1];
    const float* wq      = (const float*)d_in[2];
    const float* wk      = (const float*)d_in[3];
    const float* wv      = (const float*)d_in[4];
    const float* wo      = (const float*)d_in[5];
    float* out = (float*)d_out;

    __nv_bfloat16 *xqh, *xql, *xkh, *xkl;
    __nv_bfloat16 *wqh, *wql, *wkvh, *wkvl, *woh, *wol;
    __nv_bfloat16 *qh, *ql, *kvh, *kvl, *vth, *vtl, *prh, *prl;
    cudaGetSymbolAddress((void**)&xqh, s_xq_hi);
    cudaGetSymbolAddress((void**)&xql, s_xq_lo);
    cudaGetSymbolAddress((void**)&xkh, s_xkv_hi);
    cudaGetSymbolAddress((void**)&xkl, s_xkv_lo);
    cudaGetSymbolAddress((void**)&wqh, s_wqT_hi);
    cudaGetSymbolAddress((void**)&wql, s_wqT_lo);
    cudaGetSymbolAddress((void**)&wkvh, s_wkvT_hi);
    cudaGetSymbolAddress((void**)&wkvl, s_wkvT_lo);
    cudaGetSymbolAddress((void**)&woh, s_woT_hi);
    cudaGetSymbolAddress((void**)&wol, s_woT_lo);
    cudaGetSymbolAddress((void**)&qh,  s_q_hi);
    cudaGetSymbolAddress((void**)&ql,  s_q_lo);
    cudaGetSymbolAddress((void**)&kvh, s_kv_hi);
    cudaGetSymbolAddress((void**)&kvl, s_kv_lo);
    cudaGetSymbolAddress((void**)&vth, s_vT_hi);
    cudaGetSymbolAddress((void**)&vtl, s_vT_lo);
    cudaGetSymbolAddress((void**)&prh, s_pre_hi);
    cudaGetSymbolAddress((void**)&prl, s_pre_lo);

    cudaFuncSetAttribute(gemm_bf16x3,
                         cudaFuncAttributeMaxDynamicSharedMemorySize, GEMM_SMEM2);
    cudaFuncSetAttribute(attn_kernel,
                         cudaFuncAttributeMaxDynamicSharedMemorySize, AT_TOTAL);

    // ---- pre-pass ----
    {
        int n4 = B_ * C_ * M_ / 4;
        split_kernel<<<(n4 + 255) / 256, 256>>>(qinput,  xqh, xql, n4);
        split_kernel<<<(n4 + 255) / 256, 256>>>(kvinput, xkh, xkl, n4);
    }
    {
        dim3 tb(32, 8);
        dim3 gw(K_ / 32, M_ / 32, H_);
        transpose_split_kernel<<<gw, tb>>>(wq, wqh, wql, M_, K_,
                                           (long)M_ * K_, (long)K_ * M_);
        // K weights -> rows 0-63 of combined, V weights -> rows 64-127
        transpose_split_kernel<<<gw, tb>>>(wk, wkvh, wkvl, M_, K_,
                                           (long)M_ * K_, (long)128 * M_);
        transpose_split_kernel<<<gw, tb>>>(wv, wkvh + (size_t)64 * M_,
                                           wkvl + (size_t)64 * M_, M_, V_,
                                           (long)M_ * V_, (long)128 * M_);
        dim3 go(M_ / 32, (H_ * V_) / 32, 1);
        transpose_split_kernel<<<go, tb>>>(wo, woh, wol, H_ * V_, M_, 0L, 0L);
    }

    dim3 blk(256);
    const long hs = (long)C_ * 64;

    // ---- Q projection: 2 heads per y-block ----
    dim3 pgrid(C_ / 128, H_ / 2, B_);
    gemm_bf16x3<<<pgrid, blk, GEMM_SMEM2>>>(xqh, xql, wqh, wql,
        nullptr, qh, ql, M_, 1, 0, hs,
        (long)C_ * M_, (long)128 * M_, 2 * hs, (long)H_ * C_ * 64);

    // ---- K+V projection: one head per y-block (cols 0-63 K, 64-127 V) ----
    dim3 kvgrid(C_ / 128, H_, B_);
    gemm_bf16x3<<<kvgrid, blk, GEMM_SMEM2>>>(xkh, xkl, wkvh, wkvl,
        nullptr, kvh, kvl, M_, 1, 0, hs,
        (long)C_ * M_, (long)128 * M_, 2 * hs, (long)H_ * 2 * C_ * 64);

    // ---- V transpose ----
    {
        dim3 vg(C_ / 64, B_ * H_);
        vtrans_kernel<<<vg, 256>>>(kvh, kvl, vth, vtl);
    }

    // ---- attention (mask-aware tile skipping) ----
    dim3 agrid(C_ / 64, H_, B_);
    attn_kernel<<<agrid, blk, AT_TOTAL>>>(qh, ql, kvh, kvl, vth, vtl, prh, prl);

    // ---- output projection ----
    dim3 ogrid((B_ * C_) / 128, M_ / 128, 1);
    gemm_bf16x3<<<ogrid, blk, GEMM_SMEM2>>>(prh, prl, woh, wol,
        out, nullptr, nullptr, M_, 0, M_, 0L,
        0L, (long)128 * M_, 128L, 0L);
}

// round 6
// speedup vs baseline: 2.8344x; 1.0295x over previous
#include <cuda_runtime.h>
#include <cuda_bf16.h>
#include <cstdint>
#include <math.h>

#define B_ 2
#define C_ 2048
#define M_ 1024
#define H_ 16
#define K_ 64
#define V_ 64

// ------------------------- scratch (no cudaMalloc) -------------------------
__device__ __nv_bfloat16 s_xq_hi [(size_t)B_ * C_ * M_];
__device__ __nv_bfloat16 s_xq_lo [(size_t)B_ * C_ * M_];
__device__ __nv_bfloat16 s_xkv_hi[(size_t)B_ * C_ * M_];
__device__ __nv_bfloat16 s_xkv_lo[(size_t)B_ * C_ * M_];

__device__ __nv_bfloat16 s_wqT_hi [(size_t)H_ * K_ * M_];
__device__ __nv_bfloat16 s_wqT_lo [(size_t)H_ * K_ * M_];
__device__ __nv_bfloat16 s_wkvT_hi[(size_t)H_ * 128 * M_];   // rows 0-63 K, 64-127 V
__device__ __nv_bfloat16 s_wkvT_lo[(size_t)H_ * 128 * M_];
__device__ __nv_bfloat16 s_woT_hi [(size_t)M_ * (H_ * V_)];
__device__ __nv_bfloat16 s_woT_lo [(size_t)M_ * (H_ * V_)];

__device__ __nv_bfloat16 s_q_hi [(size_t)B_ * H_ * C_ * K_];
__device__ __nv_bfloat16 s_q_lo [(size_t)B_ * H_ * C_ * K_];
__device__ __nv_bfloat16 s_kv_hi[(size_t)B_ * H_ * 2 * C_ * 64];  // [bh][0]=K,[bh][1]=V
__device__ __nv_bfloat16 s_kv_lo[(size_t)B_ * H_ * 2 * C_ * 64];
__device__ __nv_bfloat16 s_vT_hi[(size_t)B_ * H_ * V_ * C_];
__device__ __nv_bfloat16 s_vT_lo[(size_t)B_ * H_ * V_ * C_];

__device__ __nv_bfloat16 s_pre_hi[(size_t)B_ * C_ * (H_ * V_)];
__device__ __nv_bfloat16 s_pre_lo[(size_t)B_ * C_ * (H_ * V_)];

// ------------------------------ helpers ------------------------------------
__device__ __forceinline__ void split_pair(float x, float y,
                                           uint32_t& hi, uint32_t& lo) {
    __nv_bfloat162 h = __floats2bfloat162_rn(x, y);
    float hx = __bfloat162float(h.x);
    float hy = __bfloat162float(h.y);
    __nv_bfloat162 l = __floats2bfloat162_rn(x - hx, y - hy);
    hi = *reinterpret_cast<uint32_t*>(&h);
    lo = *reinterpret_cast<uint32_t*>(&l);
}

__device__ __forceinline__ void mma16816(float* c, const uint32_t* a,
                                         const uint32_t* b) {
    asm volatile(
        "mma.sync.aligned.m16n8k16.row.col.f32.bf16.bf16.f32 "
        "{%0,%1,%2,%3}, {%4,%5,%6,%7}, {%8,%9}, {%0,%1,%2,%3};\n"
        : "+f"(c[0]), "+f"(c[1]), "+f"(c[2]), "+f"(c[3])
        : "r"(a[0]), "r"(a[1]), "r"(a[2]), "r"(a[3]), "r"(b[0]), "r"(b[1]));
}

__device__ __forceinline__ void ldsm_x4(uint32_t* r, uint32_t addr) {
    asm volatile(
        "ldmatrix.sync.aligned.m8n8.x4.shared.b16 {%0,%1,%2,%3}, [%4];\n"
        : "=r"(r[0]), "=r"(r[1]), "=r"(r[2]), "=r"(r[3]) : "r"(addr));
}

__device__ __forceinline__ uint32_t smem_u32(const void* p) {
    uint32_t a;
    asm("{ .reg .u64 t; cvta.to.shared.u64 t, %1; cvt.u32.u64 %0, t; }"
        : "=r"(a) : "l"(p));
    return a;
}
#define CP_ASYNC16(dst, src) \
    asm volatile("cp.async.ca.shared.global [%0], [%1], 16;\n" \
                 :: "r"(dst), "l"(src) : "memory")
#define CP_COMMIT() asm volatile("cp.async.commit_group;\n" ::: "memory")
#define CP_WAIT0()  asm volatile("cp.async.wait_group 0;\n" ::: "memory")
#define CP_WAIT1()  asm volatile("cp.async.wait_group 1;\n" ::: "memory")

// --------------------------- pre-pass kernels ------------------------------
__global__ void split_kernel(const float* __restrict__ in,
                             __nv_bfloat16* __restrict__ oh,
                             __nv_bfloat16* __restrict__ ol, int n4) {
    int i = blockIdx.x * blockDim.x + threadIdx.x;
    if (i < n4) {
        float4 v = reinterpret_cast<const float4*>(in)[i];
        uint32_t h0, l0, h1, l1;
        split_pair(v.x, v.y, h0, l0);
        split_pair(v.z, v.w, h1, l1);
        reinterpret_cast<uint2*>(oh)[i] = make_uint2(h0, h1);
        reinterpret_cast<uint2*>(ol)[i] = make_uint2(l0, l1);
    }
}

__global__ void transpose_split_kernel(const float* __restrict__ in,
                                       __nv_bfloat16* __restrict__ oh,
                                       __nv_bfloat16* __restrict__ ol,
                                       int R, int Cdim,
                                       long inStrideZ, long outStrideZ) {
    __shared__ float t[32][33];
    in += (long)blockIdx.z * inStrideZ;
    const long ob = (long)blockIdx.z * outStrideZ;
    const int c0 = blockIdx.x * 32, r0 = blockIdx.y * 32;
#pragma unroll
    for (int i = threadIdx.y; i < 32; i += 8)
        t[i][threadIdx.x] = in[(long)(r0 + i) * Cdim + c0 + threadIdx.x];
    __syncthreads();
#pragma unroll
    for (int i = threadIdx.y; i < 32; i += 8) {
        float v = t[threadIdx.x][i];
        __nv_bfloat16 h = __float2bfloat16(v);
        __nv_bfloat16 l = __float2bfloat16(v - __bfloat162float(h));
        long idx = ob + (long)(c0 + i) * R + r0 + threadIdx.x;
        oh[idx] = h;
        ol[idx] = l;
    }
}

// V (in combined KV) [bh][1][c][v] -> VT [bh][v][c] for hi and lo
__global__ void vtrans_kernel(const __nv_bfloat16* __restrict__ kvh,
                              const __nv_bfloat16* __restrict__ kvl,
                              __nv_bfloat16* __restrict__ oth,
                              __nv_bfloat16* __restrict__ otl) {
    const int bh = blockIdx.y;
    const int c0 = blockIdx.x * 64;
    const long ib = ((long)bh * 2 + 1) * C_ * 64;
    const long ob = (long)bh * 64 * C_;
    __shared__ __nv_bfloat16 t[64][68];
    const int tid = threadIdx.x;

    for (int pass = 0; pass < 2; pass++) {
        const __nv_bfloat16* src = pass ? kvl : kvh;
        __nv_bfloat16* dst = pass ? otl : oth;
#pragma unroll
        for (int l = 0; l < 4; l++) {
            int e = tid + l * 256;
            int c = e >> 4, v4 = (e & 15) * 4;
            *reinterpret_cast<uint2*>(&t[c][v4]) =
                *reinterpret_cast<const uint2*>(&src[ib + (long)(c0 + c) * 64 + v4]);
        }
        __syncthreads();
#pragma unroll
        for (int l = 0; l < 4; l++) {
            int e = tid + l * 256;
            int v = e >> 4, c4 = (e & 15) * 4;
            __nv_bfloat16 tmp[4] = {t[c4][v], t[c4 + 1][v], t[c4 + 2][v], t[c4 + 3][v]};
            *reinterpret_cast<uint2*>(&dst[ob + (long)v * C_ + c0 + c4]) =
                *reinterpret_cast<const uint2*>(tmp);
        }
        __syncthreads();
    }
}

// ---------------------------------------------------------------------------
// bf16x3 GEMM, 128x128 tile, K-chunk 32, cp.async double-buffered, ldmatrix.
// ---------------------------------------------------------------------------
#define GS 40
#define GARR (128 * GS * 2)
#define GBUF (4 * GARR)
#define GEMM_SMEM2 (2 * GBUF)

__global__ void __launch_bounds__(256, 2)
gemm_bf16x3(const __nv_bfloat16* __restrict__ Ah, const __nv_bfloat16* __restrict__ Al,
            const __nv_bfloat16* __restrict__ Wh, const __nv_bfloat16* __restrict__ Wl,
            float* __restrict__ Ofp,
            __nv_bfloat16* __restrict__ Oh, __nv_bfloat16* __restrict__ Ol,
            int inner, int mode, int ldo, long headStride,
            long aOffZ, long wOffY, long oOffY, long oOffZ)
{
    const long aOff = (long)blockIdx.z * aOffZ;
    const long wOff = (long)blockIdx.y * wOffY;
    const long oOff = (long)blockIdx.z * oOffZ + (long)blockIdx.y * oOffY;
    const int row0 = blockIdx.x * 128;

    extern __shared__ char smem[];
    const uint32_t sb = smem_u32(smem);

    const int tid = threadIdx.x;
    const int wid = tid >> 5, lane = tid & 31;
    const int lq = lane >> 2, lr = lane & 3;
    const int wm = wid >> 1, wn = wid & 1;

    // ldmatrix lane geometry
    const int lane15 = lane & 15;
    const int aK = (lane >> 4) << 3;                    // A: k offset 0/8
    const int bN = ((lane >> 4) << 3) + (lane & 7);     // B: n offset within pair
    const int bK = ((lane >> 3) & 1) << 3;              // B: k offset 0/8

    const int r_a = tid >> 2, q_a = tid & 3;
    const int r_b = (tid + 256) >> 2, q_b = (tid + 256) & 3;

    float acc[2][8][4];
#pragma unroll
    for (int a = 0; a < 2; a++)
#pragma unroll
        for (int b = 0; b < 8; b++)
#pragma unroll
            for (int c = 0; c < 4; c++) acc[a][b][c] = 0.0f;

    const int nch = inner >> 5;

    auto issue = [&](int ck, int s) {
        const int m0 = ck << 5;
        const uint32_t base = sb + s * GBUF;
        {
            const __nv_bfloat16* s0 = Ah + aOff + (long)(row0 + r_a) * inner + m0 + q_a * 8;
            const __nv_bfloat16* s1 = Ah + aOff + (long)(row0 + r_b) * inner + m0 + q_b * 8;
            CP_ASYNC16(base + r_a * 80 + q_a * 16, s0);
            CP_ASYNC16(base + r_b * 80 + q_b * 16, s1);
            const __nv_bfloat16* s2 = Al + aOff + (long)(row0 + r_a) * inner + m0 + q_a * 8;
            const __nv_bfloat16* s3 = Al + aOff + (long)(row0 + r_b) * inner + m0 + q_b * 8;
            CP_ASYNC16(base + GARR + r_a * 80 + q_a * 16, s2);
            CP_ASYNC16(base + GARR + r_b * 80 + q_b * 16, s3);
        }
        {
            const __nv_bfloat16* s0 = Wh + wOff + (long)r_a * inner + m0 + q_a * 8;
            const __nv_bfloat16* s1 = Wh + wOff + (long)r_b * inner + m0 + q_b * 8;
            CP_ASYNC16(base + 2 * GARR + r_a * 80 + q_a * 16, s0);
            CP_ASYNC16(base + 2 * GARR + r_b * 80 + q_b * 16, s1);
            const __nv_bfloat16* s2 = Wl + wOff + (long)r_a * inner + m0 + q_a * 8;
            const __nv_bfloat16* s3 = Wl + wOff + (long)r_b * inner + m0 + q_b * 8;
            CP_ASYNC16(base + 3 * GARR + r_a * 80 + q_a * 16, s2);
            CP_ASYNC16(base + 3 * GARR + r_b * 80 + q_b * 16, s3);
        }
    };

    issue(0, 0);
    CP_COMMIT();

    for (int it = 0; it < nch; it++) {
        if (it + 1 < nch) {
            issue(it + 1, (it + 1) & 1);
            CP_COMMIT();
            CP_WAIT1();
        } else {
            CP_WAIT0();
        }
        __syncthreads();

        const uint32_t cbase = sb + (it & 1) * GBUF;
        const uint32_t sAh_b = cbase;
        const uint32_t sAl_b = cbase + GARR;
        const uint32_t sWh_b = cbase + 2 * GARR;
        const uint32_t sWl_b = cbase + 3 * GARR;

#pragma unroll
        for (int ks = 0; ks < 2; ks++) {
            const int kA = ks * 16 + aK;
            const int kB = ks * 16 + bK;
            uint32_t ah[2][4], al[2][4];
#pragma unroll
            for (int mt = 0; mt < 2; mt++) {
                const uint32_t off = (uint32_t)((wm * 32 + mt * 16 + lane15) * GS + kA) * 2;
                ldsm_x4(ah[mt], sAh_b + off);
                ldsm_x4(al[mt], sAl_b + off);
            }
#pragma unroll
            for (int ntp = 0; ntp < 4; ntp++) {
                const uint32_t off = (uint32_t)((wn * 64 + ntp * 16 + bN) * GS + kB) * 2;
                uint32_t bhf[4], blf[4];
                ldsm_x4(bhf, sWh_b + off);
                ldsm_x4(blf, sWl_b + off);
#pragma unroll
                for (int h2 = 0; h2 < 2; h2++) {
                    const int nt = ntp * 2 + h2;
#pragma unroll
                    for (int mt = 0; mt < 2; mt++) {
                        mma16816(acc[mt][nt], ah[mt], bhf + h2 * 2);
                        mma16816(acc[mt][nt], ah[mt], blf + h2 * 2);
                        mma16816(acc[mt][nt], al[mt], bhf + h2 * 2);
                    }
                }
            }
        }
        __syncthreads();
    }

#pragma unroll
    for (int mt = 0; mt < 2; mt++) {
        const int row_lo = row0 + wm * 32 + mt * 16 + lq;
        const int row_hi = row_lo + 8;
#pragma unroll
        for (int nt = 0; nt < 8; nt++) {
            const int col = wn * 64 + nt * 8 + lr * 2;
            const float* c = acc[mt][nt];
            if (mode == 0) {
                *reinterpret_cast<float2*>(&Ofp[oOff + (long)row_lo * ldo + col]) =
                    make_float2(c[0], c[1]);
                *reinterpret_cast<float2*>(&Ofp[oOff + (long)row_hi * ldo + col]) =
                    make_float2(c[2], c[3]);
            } else {
                const long hb = oOff + (long)(col >> 6) * headStride + (col & 63);
                const long i0 = hb + (long)row_lo * 64;
                const long i1 = hb + (long)row_hi * 64;
                uint32_t h0, l0, h1, l1;
                split_pair(c[0], c[1], h0, l0);
                split_pair(c[2], c[3], h1, l1);
                *reinterpret_cast<uint32_t*>(&Oh[i0]) = h0;
                *reinterpret_cast<uint32_t*>(&Ol[i0]) = l0;
                *reinterpret_cast<uint32_t*>(&Oh[i1]) = h1;
                *reinterpret_cast<uint32_t*>(&Ol[i1]) = l1;
            }
        }
    }
}

// ---------------------------------------------------------------------------
// Flash attention, bf16x3, cp.async double-buffered K/V, parallel softmax,
// mask-aware tile skipping, ldmatrix fragment loads.
// ---------------------------------------------------------------------------
#define ATA  9216
#define AT_KH 0
#define AT_KL (2 * ATA)
#define AT_VH (4 * ATA)
#define AT_VL (6 * ATA)
#define AT_QH (8 * ATA)
#define AT_QL (AT_QH + ATA)
#define AT_SS (AT_QH + 2 * ATA)
#define AT_SM (AT_SS + 64 * 66 * 4)
#define AT_TOTAL (AT_SM + 3 * 64 * 4)

__global__ void __launch_bounds__(256, 2)
attn_kernel(const __nv_bfloat16* __restrict__ qh_g, const __nv_bfloat16* __restrict__ ql_g,
            const __nv_bfloat16* __restrict__ kvh_g, const __nv_bfloat16* __restrict__ kvl_g,
            const __nv_bfloat16* __restrict__ vth_g, const __nv_bfloat16* __restrict__ vtl_g,
            __nv_bfloat16* __restrict__ ph_g, __nv_bfloat16* __restrict__ pl_g)
{
    const int b = blockIdx.z, h = blockIdx.y;
    const int qb = blockIdx.x;
    const int d0 = qb * 64;
    const int bh = b * H_ + h;
    const int ntiles = C_ / 64;
    const int tstart = (qb == ntiles - 1) ? 0 : qb;

    extern __shared__ char smem[];
    const uint32_t sb = smem_u32(smem);
    __nv_bfloat16* sQh = (__nv_bfloat16*)(smem + AT_QH);
    __nv_bfloat16* sQl = (__nv_bfloat16*)(smem + AT_QL);
    float* Ss   = (float*)(smem + AT_SS);
    float* sm_m = (float*)(smem + AT_SM);
    float* sm_l = sm_m + 64;
    float* sm_a = sm_m + 128;

    const int tid = threadIdx.x;
    const int wid = tid >> 5, lane = tid & 31;
    const int lq = lane >> 2, lr = lane & 3;
    const int dtile = (wid >> 1) * 16;
    const int half  = (wid & 1) * 32;
    const int r0 = dtile + lq;

    // ldmatrix lane geometry
    const int lane15 = lane & 15;
    const int aK = (lane >> 4) << 3;
    const int bN = ((lane >> 4) << 3) + (lane & 7);
    const int bK = ((lane >> 3) & 1) << 3;

    const __nv_bfloat16* Kh_g = kvh_g + ((long)bh * 2) * C_ * 64;
    const __nv_bfloat16* Kl_g = kvl_g + ((long)bh * 2) * C_ * 64;
    const __nv_bfloat16* Vh_g = vth_g + (long)bh * 64 * C_;
    const __nv_bfloat16* Vl_g = vtl_g + (long)bh * 64 * C_;

#pragma unroll
    for (int l = 0; l < 2; l++) {
        int e = tid + l * 256;
        int r = e >> 3, q = (e & 7) * 8;
        long g = ((long)bh * C_ + d0 + r) * 64 + q;
        *reinterpret_cast<uint4*>(&sQh[r * 72 + q]) =
            *reinterpret_cast<const uint4*>(&qh_g[g]);
        *reinterpret_cast<uint4*>(&sQl[r * 72 + q]) =
            *reinterpret_cast<const uint4*>(&ql_g[g]);
    }
    if (tid < 64) { sm_m[tid] = -1e30f; sm_l[tid] = 0.0f; }

    const int r_a = tid >> 3, q_a = tid & 7;
    const int r_b = (tid + 256) >> 3, q_b = (tid + 256) & 7;

    auto issue = [&](int t, int s) {
        const int c0 = t * 64;
        const uint32_t kh_d = sb + AT_KH + s * ATA;
        const uint32_t kl_d = sb + AT_KL + s * ATA;
        const uint32_t vh_d = sb + AT_VH + s * ATA;
        const uint32_t vl_d = sb + AT_VL + s * ATA;
        CP_ASYNC16(kh_d + r_a * 144 + q_a * 16, Kh_g + (long)(c0 + r_a) * 64 + q_a * 8);
        CP_ASYNC16(kh_d + r_b * 144 + q_b * 16, Kh_g + (long)(c0 + r_b) * 64 + q_b * 8);
        CP_ASYNC16(kl_d + r_a * 144 + q_a * 16, Kl_g + (long)(c0 + r_a) * 64 + q_a * 8);
        CP_ASYNC16(kl_d + r_b * 144 + q_b * 16, Kl_g + (long)(c0 + r_b) * 64 + q_b * 8);
        CP_ASYNC16(vh_d + r_a * 144 + q_a * 16, Vh_g + (long)r_a * C_ + c0 + q_a * 8);
        CP_ASYNC16(vh_d + r_b * 144 + q_b * 16, Vh_g + (long)r_b * C_ + c0 + q_b * 8);
        CP_ASYNC16(vl_d + r_a * 144 + q_a * 16, Vl_g + (long)r_a * C_ + c0 + q_a * 8);
        CP_ASYNC16(vl_d + r_b * 144 + q_b * 16, Vl_g + (long)r_b * C_ + c0 + q_b * 8);
    };

    issue(tstart, tstart & 1);
    CP_COMMIT();
    __syncthreads();

    // persistent Q fragments via ldmatrix
    uint32_t qh[4][4], ql[4][4];
#pragma unroll
    for (int ks = 0; ks < 4; ks++) {
        const uint32_t off = (uint32_t)((dtile + lane15) * 72 + ks * 16 + aK) * 2;
        ldsm_x4(qh[ks], sb + AT_QH + off);
        ldsm_x4(ql[ks], sb + AT_QL + off);
    }

    float oacc[4][4];
#pragma unroll
    for (int i = 0; i < 4; i++)
#pragma unroll
        for (int j = 0; j < 4; j++) oacc[i][j] = 0.0f;

    for (int t = tstart; t < ntiles; t++) {
        if (t + 1 < ntiles) {
            issue(t + 1, (t + 1) & 1);
            CP_COMMIT();
            CP_WAIT1();
        } else {
            CP_WAIT0();
        }
        __syncthreads();

        const int s = t & 1;
        const int c0 = t * 64;
        const uint32_t sKh_b = sb + AT_KH + s * ATA;
        const uint32_t sKl_b = sb + AT_KL + s * ATA;
        const uint32_t sVh_b = sb + AT_VH + s * ATA;
        const uint32_t sVl_b = sb + AT_VL + s * ATA;

        // ---- S = Q @ K^T ----
        float sacc[4][4];
#pragma unroll
        for (int i = 0; i < 4; i++)
#pragma unroll
            for (int j = 0; j < 4; j++) sacc[i][j] = 0.0f;
#pragma unroll
        for (int ks = 0; ks < 4; ks++) {
            const int kB = ks * 16 + bK;
#pragma unroll
            for (int ntp = 0; ntp < 2; ntp++) {
                const uint32_t off = (uint32_t)((half + ntp * 16 + bN) * 72 + kB) * 2;
                uint32_t bhf[4], blf[4];
                ldsm_x4(bhf, sKh_b + off);
                ldsm_x4(blf, sKl_b + off);
#pragma unroll
                for (int h2 = 0; h2 < 2; h2++) {
                    const int nt = ntp * 2 + h2;
                    mma16816(sacc[nt], qh[ks], bhf + h2 * 2);
                    mma16816(sacc[nt], qh[ks], blf + h2 * 2);
                    mma16816(sacc[nt], ql[ks], bhf + h2 * 2);
                }
            }
        }
        {
            const int dg0 = d0 + r0, dg1 = d0 + r0 + 8;
#pragma unroll
            for (int nt = 0; nt < 4; nt++) {
                const int col = half + nt * 8 + lr * 2;
                const int cg = c0 + col;
                float v0 = sacc[nt][0]; if (cg     <= dg0) v0 -= 100.0f;
                float v1 = sacc[nt][1]; if (cg + 1 <= dg0) v1 -= 100.0f;
                float v2 = sacc[nt][2]; if (cg     <= dg1) v2 -= 100.0f;
                float v3 = sacc[nt][3]; if (cg + 1 <= dg1) v3 -= 100.0f;
                Ss[r0 * 66 + col]           = v0 * 0.125f;
                Ss[r0 * 66 + col + 1]       = v1 * 0.125f;
                Ss[(r0 + 8) * 66 + col]     = v2 * 0.125f;
                Ss[(r0 + 8) * 66 + col + 1] = v3 * 0.125f;
            }
        }
        __syncthreads();

        // ---- online softmax: 4 threads per row ----
        {
            const int row = tid >> 2, part = tid & 3;
            float* rp = &Ss[row * 66 + part * 16];
            float mt = rp[0];
#pragma unroll
            for (int j = 1; j < 16; j++) mt = fmaxf(mt, rp[j]);
            mt = fmaxf(mt, __shfl_xor_sync(0xffffffff, mt, 1));
            mt = fmaxf(mt, __shfl_xor_sync(0xffffffff, mt, 2));
            const float mold = sm_m[row];
            const float mnew = fmaxf(mold, mt);
            float sum = 0.0f;
#pragma unroll
            for (int j = 0; j < 16; j++) {
                float p = __expf(rp[j] - mnew);
                rp[j] = p;
                sum += p;
            }
            sum += __shfl_xor_sync(0xffffffff, sum, 1);
            sum += __shfl_xor_sync(0xffffffff, sum, 2);
            if (part == 0) {
                const float alpha = __expf(mold - mnew);
                sm_l[row] = sm_l[row] * alpha + sum;
                sm_m[row] = mnew;
                sm_a[row] = alpha;
            }
        }
        __syncthreads();

        // ---- O = O*alpha + P @ V ----
        {
            const float al0 = sm_a[r0], al1 = sm_a[r0 + 8];
#pragma unroll
            for (int nt = 0; nt < 4; nt++) {
                oacc[nt][0] *= al0; oacc[nt][1] *= al0;
                oacc[nt][2] *= al1; oacc[nt][3] *= al1;
            }
        }
#pragma unroll
        for (int ks = 0; ks < 4; ks++) {
            const int kc = ks * 16 + lr * 2;
            const int kB = ks * 16 + bK;
            uint32_t ph[4], pl[4];
            float2 p0 = *reinterpret_cast<const float2*>(&Ss[r0 * 66 + kc]);
            float2 p1 = *reinterpret_cast<const float2*>(&Ss[(r0 + 8) * 66 + kc]);
            float2 p2 = *reinterpret_cast<const float2*>(&Ss[r0 * 66 + kc + 8]);
            float2 p3 = *reinterpret_cast<const float2*>(&Ss[(r0 + 8) * 66 + kc + 8]);
            split_pair(p0.x, p0.y, ph[0], pl[0]);
            split_pair(p1.x, p1.y, ph[1], pl[1]);
            split_pair(p2.x, p2.y, ph[2], pl[2]);
            split_pair(p3.x, p3.y, ph[3], pl[3]);
#pragma unroll
            for (int ntp = 0; ntp < 2; ntp++) {
                const uint32_t off = (uint32_t)((half + ntp * 16 + bN) * 72 + kB) * 2;
                uint32_t bhf[4], blf[4];
                ldsm_x4(bhf, sVh_b + off);
                ldsm_x4(blf, sVl_b + off);
#pragma unroll
                for (int h2 = 0; h2 < 2; h2++) {
                    const int nt = ntp * 2 + h2;
                    mma16816(oacc[nt], ph, bhf + h2 * 2);
                    mma16816(oacc[nt], ph, blf + h2 * 2);
                    mma16816(oacc[nt], pl, bhf + h2 * 2);
                }
            }
        }
        __syncthreads();
    }

    {
        const float il0 = 1.0f / sm_l[r0];
        const float il1 = 1.0f / sm_l[r0 + 8];
#pragma unroll
        for (int nt = 0; nt < 4; nt++) {
            const int col = h * 64 + half + nt * 8 + lr * 2;
            const long i0 = ((long)(b * C_ + d0 + r0)) * (H_ * V_) + col;
            const long i1 = ((long)(b * C_ + d0 + r0 + 8)) * (H_ * V_) + col;
            uint32_t h0, l0, h1, l1;
            split_pair(oacc[nt][0] * il0, oacc[nt][1] * il0, h0, l0);
            split_pair(oacc[nt][2] * il1, oacc[nt][3] * il1, h1, l1);
            *reinterpret_cast<uint32_t*>(&ph_g[i0]) = h0;
            *reinterpret_cast<uint32_t*>(&pl_g[i0]) = l0;
            *reinterpret_cast<uint32_t*>(&ph_g[i1]) = h1;
            *reinterpret_cast<uint32_t*>(&pl_g[i1]) = l1;
        }
    }
}

// ---------------------------------------------------------------------------

extern "C" void kernel_launch(void* const* d_in, const int* in_sizes, int n_in,
                              void* d_out, int out_size)
{
    const float* kvinput = (const float*)d_in[0];
    const float* qinput  = (const float*)d_in[1];
    const float* wq      = (const float*)d_in[2];
    const float* wk      = (const float*)d_in[3];
    const float* wv      = (const float*)d_in[4];
    const float* wo      = (const float*)d_in[5];
    float* out = (float*)d_out;

    __nv_bfloat16 *xqh, *xql, *xkh, *xkl;
    __nv_bfloat16 *wqh, *wql, *wkvh, *wkvl, *woh, *wol;
    __nv_bfloat16 *qh, *ql, *kvh, *kvl, *vth, *vtl, *prh, *prl;
    cudaGetSymbolAddress((void**)&xqh, s_xq_hi);
    cudaGetSymbolAddress((void**)&xql, s_xq_lo);
    cudaGetSymbolAddress((void**)&xkh, s_xkv_hi);
    cudaGetSymbolAddress((void**)&xkl, s_xkv_lo);
    cudaGetSymbolAddress((void**)&wqh, s_wqT_hi);
    cudaGetSymbolAddress((void**)&wql, s_wqT_lo);
    cudaGetSymbolAddress((void**)&wkvh, s_wkvT_hi);
    cudaGetSymbolAddress((void**)&wkvl, s_wkvT_lo);
    cudaGetSymbolAddress((void**)&woh, s_woT_hi);
    cudaGetSymbolAddress((void**)&wol, s_woT_lo);
    cudaGetSymbolAddress((void**)&qh,  s_q_hi);
    cudaGetSymbolAddress((void**)&ql,  s_q_lo);
    cudaGetSymbolAddress((void**)&kvh, s_kv_hi);
    cudaGetSymbolAddress((void**)&kvl, s_kv_lo);
    cudaGetSymbolAddress((void**)&vth, s_vT_hi);
    cudaGetSymbolAddress((void**)&vtl, s_vT_lo);
    cudaGetSymbolAddress((void**)&prh, s_pre_hi);
    cudaGetSymbolAddress((void**)&prl, s_pre_lo);

    cudaFuncSetAttribute(gemm_bf16x3,
                         cudaFuncAttributeMaxDynamicSharedMemorySize, GEMM_SMEM2);
    cudaFuncSetAttribute(attn_kernel,
                         cudaFuncAttributeMaxDynamicSharedMemorySize, AT_TOTAL);

    // ---- pre-pass ----
    {
        int n4 = B_ * C_ * M_ / 4;
        split_kernel<<<(n4 + 255) / 256, 256>>>(qinput,  xqh, xql, n4);
        split_kernel<<<(n4 + 255) / 256, 256>>>(kvinput, xkh, xkl, n4);
    }
    {
        dim3 tb(32, 8);
        dim3 gw(K_ / 32, M_ / 32, H_);
        transpose_split_kernel<<<gw, tb>>>(wq, wqh, wql, M_, K_,
                                           (long)M_ * K_, (long)K_ * M_);
        transpose_split_kernel<<<gw, tb>>>(wk, wkvh, wkvl, M_, K_,
                                           (long)M_ * K_, (long)128 * M_);
        transpose_split_kernel<<<gw, tb>>>(wv, wkvh + (size_t)64 * M_,
                                           wkvl + (size_t)64 * M_, M_, V_,
                                           (long)M_ * V_, (long)128 * M_);
        dim3 go(M_ / 32, (H_ * V_) / 32, 1);
        transpose_split_kernel<<<go, tb>>>(wo, woh, wol, H_ * V_, M_, 0L, 0L);
    }

    dim3 blk(256);
    const long hs = (long)C_ * 64;

    // ---- Q projection: 2 heads per y-block ----
    dim3 pgrid(C_ / 128, H_ / 2, B_);
    gemm_bf16x3<<<pgrid, blk, GEMM_SMEM2>>>(xqh, xql, wqh, wql,
        nullptr, qh, ql, M_, 1, 0, hs,
        (long)C_ * M_, (long)128 * M_, 2 * hs, (long)H_ * C_ * 64);

    // ---- K+V projection ----
    dim3 kvgrid(C_ / 128, H_, B_);
    gemm_bf16x3<<<kvgrid, blk, GEMM_SMEM2>>>(xkh, xkl, wkvh, wkvl,
        nullptr, kvh, kvl, M_, 1, 0, hs,
        (long)C_ * M_, (long)128 * M_, 2 * hs, (long)H_ * 2 * C_ * 64);

    // ---- V transpose ----
    {
        dim3 vg(C_ / 64, B_ * H_);
        vtrans_kernel<<<vg, 256>>>(kvh, kvl, vth, vtl);
    }

    // ---- attention (mask-aware tile skipping) ----
    dim3 agrid(C_ / 64, H_, B_);
    attn_kernel<<<agrid, blk, AT_TOTAL>>>(qh, ql, kvh, kvl, vth, vtl, prh, prl);

    // ---- output projection ----
    dim3 ogrid((B_ * C_) / 128, M_ / 128, 1);
    gemm_bf16x3<<<ogrid, blk, GEMM_SMEM2>>>(prh, prl, woh, wol,
        out, nullptr, nullptr, M_, 0, M_, 0L,
        0L, (long)128 * M_, 128L, 0L);
}

// round 7
// speedup vs baseline: 3.5205x; 1.2420x over previous
#include <cuda_runtime.h>
#include <cuda_bf16.h>
#include <cstdint>
#include <math.h>

#define B_ 2
#define C_ 2048
#define M_ 1024
#define H_ 16
#define K_ 64
#define V_ 64

// ------------------------- scratch (no cudaMalloc) -------------------------
__device__ __nv_bfloat16 s_xq_hi [(size_t)B_ * C_ * M_];
__device__ __nv_bfloat16 s_xq_lo [(size_t)B_ * C_ * M_];
__device__ __nv_bfloat16 s_xkv_hi[(size_t)B_ * C_ * M_];
__device__ __nv_bfloat16 s_xkv_lo[(size_t)B_ * C_ * M_];

__device__ __nv_bfloat16 s_wqT_hi [(size_t)H_ * K_ * M_];
__device__ __nv_bfloat16 s_wqT_lo [(size_t)H_ * K_ * M_];
__device__ __nv_bfloat16 s_wkvT_hi[(size_t)H_ * 128 * M_];   // rows 0-63 K, 64-127 V
__device__ __nv_bfloat16 s_wkvT_lo[(size_t)H_ * 128 * M_];
__device__ __nv_bfloat16 s_woT_hi [(size_t)M_ * (H_ * V_)];
__device__ __nv_bfloat16 s_woT_lo [(size_t)M_ * (H_ * V_)];

__device__ __nv_bfloat16 s_q_hi [(size_t)B_ * H_ * C_ * K_];
__device__ __nv_bfloat16 s_q_lo [(size_t)B_ * H_ * C_ * K_];
__device__ __nv_bfloat16 s_kv_hi[(size_t)B_ * H_ * 2 * C_ * 64];  // [bh][0]=K,[bh][1]=V
__device__ __nv_bfloat16 s_kv_lo[(size_t)B_ * H_ * 2 * C_ * 64];
__device__ __nv_bfloat16 s_vT_hi[(size_t)B_ * H_ * V_ * C_];
__device__ __nv_bfloat16 s_vT_lo[(size_t)B_ * H_ * V_ * C_];

__device__ __nv_bfloat16 s_pre_hi[(size_t)B_ * C_ * (H_ * V_)];
__device__ __nv_bfloat16 s_pre_lo[(size_t)B_ * C_ * (H_ * V_)];

// ------------------------------ helpers ------------------------------------
__device__ __forceinline__ void split_pair(float x, float y,
                                           uint32_t& hi, uint32_t& lo) {
    __nv_bfloat162 h = __floats2bfloat162_rn(x, y);
    float hx = __bfloat162float(h.x);
    float hy = __bfloat162float(h.y);
    __nv_bfloat162 l = __floats2bfloat162_rn(x - hx, y - hy);
    hi = *reinterpret_cast<uint32_t*>(&h);
    lo = *reinterpret_cast<uint32_t*>(&l);
}

__device__ __forceinline__ void mma16816(float* c, const uint32_t* a,
                                         const uint32_t* b) {
    asm volatile(
        "mma.sync.aligned.m16n8k16.row.col.f32.bf16.bf16.f32 "
        "{%0,%1,%2,%3}, {%4,%5,%6,%7}, {%8,%9}, {%0,%1,%2,%3};\n"
        : "+f"(c[0]), "+f"(c[1]), "+f"(c[2]), "+f"(c[3])
        : "r"(a[0]), "r"(a[1]), "r"(a[2]), "r"(a[3]), "r"(b[0]), "r"(b[1]));
}

__device__ __forceinline__ void ldsm_x4(uint32_t* r, uint32_t addr) {
    asm volatile(
        "ldmatrix.sync.aligned.m8n8.x4.shared.b16 {%0,%1,%2,%3}, [%4];\n"
        : "=r"(r[0]), "=r"(r[1]), "=r"(r[2]), "=r"(r[3]) : "r"(addr));
}

__device__ __forceinline__ uint32_t smem_u32(const void* p) {
    uint32_t a;
    asm("{ .reg .u64 t; cvta.to.shared.u64 t, %1; cvt.u32.u64 %0, t; }"
        : "=r"(a) : "l"(p));
    return a;
}
#define CP_ASYNC16(dst, src) \
    asm volatile("cp.async.ca.shared.global [%0], [%1], 16;\n" \
                 :: "r"(dst), "l"(src) : "memory")
#define CP_COMMIT() asm volatile("cp.async.commit_group;\n" ::: "memory")
#define CP_WAIT0()  asm volatile("cp.async.wait_group 0;\n" ::: "memory")
#define CP_WAIT1()  asm volatile("cp.async.wait_group 1;\n" ::: "memory")

// --------------------------- pre-pass kernels ------------------------------
// split both inputs in ONE launch (keeps launch idx of attn at 5 for ncu)
__global__ void split2_kernel(const float* __restrict__ inq,
                              const float* __restrict__ inkv,
                              __nv_bfloat16* __restrict__ qoh, __nv_bfloat16* __restrict__ qol,
                              __nv_bfloat16* __restrict__ koh, __nv_bfloat16* __restrict__ kol,
                              int n4each) {
    int i = blockIdx.x * blockDim.x + threadIdx.x;
    const float* in;
    __nv_bfloat16 *oh, *ol;
    int idx;
    if (i < n4each) { in = inq; oh = qoh; ol = qol; idx = i; }
    else if (i < 2 * n4each) { in = inkv; oh = koh; ol = kol; idx = i - n4each; }
    else return;
    float4 v = reinterpret_cast<const float4*>(in)[idx];
    uint32_t h0, l0, h1, l1;
    split_pair(v.x, v.y, h0, l0);
    split_pair(v.z, v.w, h1, l1);
    reinterpret_cast<uint2*>(oh)[idx] = make_uint2(h0, h1);
    reinterpret_cast<uint2*>(ol)[idx] = make_uint2(l0, l1);
}

// all 4 weight transposes in ONE launch. 4096 blocks:
//  [0,1024)  wq   : grid (x=2,y=32,h=16), R=M, Cdim=K
//  [1024,2048) wk  -> wkv rows 0-63
//  [2048,3072) wv  -> wkv rows 64-127
//  [3072,4096) wo  : grid (x=32,y=32), R=H*V, Cdim=M
__global__ void trans_all_kernel(const float* __restrict__ wq,
                                 const float* __restrict__ wk,
                                 const float* __restrict__ wv,
                                 const float* __restrict__ wo,
                                 __nv_bfloat16* __restrict__ wqh, __nv_bfloat16* __restrict__ wql,
                                 __nv_bfloat16* __restrict__ wkvh, __nv_bfloat16* __restrict__ wkvl,
                                 __nv_bfloat16* __restrict__ woh, __nv_bfloat16* __restrict__ wol) {
    __shared__ float t[32][33];
    const int bid = blockIdx.x;
    const float* in;
    __nv_bfloat16 *oh, *ol;
    int R, Cdim, c0, r0;
    long ib, ob;
    if (bid < 3072) {
        const int m = bid >> 10;           // 0=wq 1=wk 2=wv
        const int r = bid & 1023;
        const int hh = r >> 6;
        const int rem = r & 63;
        const int gy = rem >> 1, gx = rem & 1;
        R = M_; Cdim = K_;
        c0 = gx * 32; r0 = gy * 32;
        if (m == 0) {
            in = wq;  oh = wqh;  ol = wql;
            ib = (long)hh * M_ * K_; ob = (long)hh * K_ * M_;
        } else if (m == 1) {
            in = wk;  oh = wkvh; ol = wkvl;
            ib = (long)hh * M_ * K_; ob = (long)hh * 128 * M_;
        } else {
            in = wv;  oh = wkvh + (size_t)64 * M_; ol = wkvl + (size_t)64 * M_;
            ib = (long)hh * M_ * V_; ob = (long)hh * 128 * M_;
        }
    } else {
        const int r = bid - 3072;
        R = H_ * V_; Cdim = M_;
        c0 = (r & 31) * 32; r0 = (r >> 5) * 32;
        in = wo; oh = woh; ol = wol; ib = 0; ob = 0;
    }
    in += ib;
#pragma unroll
    for (int i = threadIdx.y; i < 32; i += 8)
        t[i][threadIdx.x] = in[(long)(r0 + i) * Cdim + c0 + threadIdx.x];
    __syncthreads();
#pragma unroll
    for (int i = threadIdx.y; i < 32; i += 8) {
        float v = t[threadIdx.x][i];
        __nv_bfloat16 h = __float2bfloat16(v);
        __nv_bfloat16 l = __float2bfloat16(v - __bfloat162float(h));
        long idx = ob + (long)(c0 + i) * R + r0 + threadIdx.x;
        oh[idx] = h;
        ol[idx] = l;
    }
}

// V (in combined KV) [bh][1][c][v] -> VT [bh][v][c]
__global__ void vtrans_kernel(const __nv_bfloat16* __restrict__ kvh,
                              const __nv_bfloat16* __restrict__ kvl,
                              __nv_bfloat16* __restrict__ oth,
                              __nv_bfloat16* __restrict__ otl) {
    const int bh = blockIdx.y;
    const int c0 = blockIdx.x * 64;
    const long ib = ((long)bh * 2 + 1) * C_ * 64;
    const long ob = (long)bh * 64 * C_;
    __shared__ __nv_bfloat16 t[64][68];
    const int tid = threadIdx.x;

    for (int pass = 0; pass < 2; pass++) {
        const __nv_bfloat16* src = pass ? kvl : kvh;
        __nv_bfloat16* dst = pass ? otl : oth;
#pragma unroll
        for (int l = 0; l < 4; l++) {
            int e = tid + l * 256;
            int c = e >> 4, v4 = (e & 15) * 4;
            *reinterpret_cast<uint2*>(&t[c][v4]) =
                *reinterpret_cast<const uint2*>(&src[ib + (long)(c0 + c) * 64 + v4]);
        }
        __syncthreads();
#pragma unroll
        for (int l = 0; l < 4; l++) {
            int e = tid + l * 256;
            int v = e >> 4, c4 = (e & 15) * 4;
            __nv_bfloat16 tmp[4] = {t[c4][v], t[c4 + 1][v], t[c4 + 2][v], t[c4 + 3][v]};
            *reinterpret_cast<uint2*>(&dst[ob + (long)v * C_ + c0 + c4]) =
                *reinterpret_cast<const uint2*>(tmp);
        }
        __syncthreads();
    }
}

// ---------------------------------------------------------------------------
// bf16x3 GEMM, 128x128 tile, K-chunk 32, cp.async double-buffered, ldmatrix.
// ---------------------------------------------------------------------------
#define GS 40
#define GARR (128 * GS * 2)
#define GBUF (4 * GARR)
#define GEMM_SMEM2 (2 * GBUF)

__global__ void __launch_bounds__(256, 2)
gemm_bf16x3(const __nv_bfloat16* __restrict__ Ah, const __nv_bfloat16* __restrict__ Al,
            const __nv_bfloat16* __restrict__ Wh, const __nv_bfloat16* __restrict__ Wl,
            float* __restrict__ Ofp,
            __nv_bfloat16* __restrict__ Oh, __nv_bfloat16* __restrict__ Ol,
            int inner, int mode, int ldo, long headStride,
            long aOffZ, long wOffY, long oOffY, long oOffZ)
{
    const long aOff = (long)blockIdx.z * aOffZ;
    const long wOff = (long)blockIdx.y * wOffY;
    const long oOff = (long)blockIdx.z * oOffZ + (long)blockIdx.y * oOffY;
    const int row0 = blockIdx.x * 128;

    extern __shared__ char smem[];
    const uint32_t sb = smem_u32(smem);

    const int tid = threadIdx.x;
    const int wid = tid >> 5, lane = tid & 31;
    const int lq = lane >> 2, lr = lane & 3;
    const int wm = wid >> 1, wn = wid & 1;

    const int lane15 = lane & 15;
    const int aK = (lane >> 4) << 3;
    const int bN = ((lane >> 4) << 3) + (lane & 7);
    const int bK = ((lane >> 3) & 1) << 3;

    const int r_a = tid >> 2, q_a = tid & 3;
    const int r_b = (tid + 256) >> 2, q_b = (tid + 256) & 3;

    float acc[2][8][4];
#pragma unroll
    for (int a = 0; a < 2; a++)
#pragma unroll
        for (int b = 0; b < 8; b++)
#pragma unroll
            for (int c = 0; c < 4; c++) acc[a][b][c] = 0.0f;

    const int nch = inner >> 5;

    auto issue = [&](int ck, int s) {
        const int m0 = ck << 5;
        const uint32_t base = sb + s * GBUF;
        {
            const __nv_bfloat16* s0 = Ah + aOff + (long)(row0 + r_a) * inner + m0 + q_a * 8;
            const __nv_bfloat16* s1 = Ah + aOff + (long)(row0 + r_b) * inner + m0 + q_b * 8;
            CP_ASYNC16(base + r_a * 80 + q_a * 16, s0);
            CP_ASYNC16(base + r_b * 80 + q_b * 16, s1);
            const __nv_bfloat16* s2 = Al + aOff + (long)(row0 + r_a) * inner + m0 + q_a * 8;
            const __nv_bfloat16* s3 = Al + aOff + (long)(row0 + r_b) * inner + m0 + q_b * 8;
            CP_ASYNC16(base + GARR + r_a * 80 + q_a * 16, s2);
            CP_ASYNC16(base + GARR + r_b * 80 + q_b * 16, s3);
        }
        {
            const __nv_bfloat16* s0 = Wh + wOff + (long)r_a * inner + m0 + q_a * 8;
            const __nv_bfloat16* s1 = Wh + wOff + (long)r_b * inner + m0 + q_b * 8;
            CP_ASYNC16(base + 2 * GARR + r_a * 80 + q_a * 16, s0);
            CP_ASYNC16(base + 2 * GARR + r_b * 80 + q_b * 16, s1);
            const __nv_bfloat16* s2 = Wl + wOff + (long)r_a * inner + m0 + q_a * 8;
            const __nv_bfloat16* s3 = Wl + wOff + (long)r_b * inner + m0 + q_b * 8;
            CP_ASYNC16(base + 3 * GARR + r_a * 80 + q_a * 16, s2);
            CP_ASYNC16(base + 3 * GARR + r_b * 80 + q_b * 16, s3);
        }
    };

    issue(0, 0);
    CP_COMMIT();

    for (int it = 0; it < nch; it++) {
        if (it + 1 < nch) {
            issue(it + 1, (it + 1) & 1);
            CP_COMMIT();
            CP_WAIT1();
        } else {
            CP_WAIT0();
        }
        __syncthreads();

        const uint32_t cbase = sb + (it & 1) * GBUF;
        const uint32_t sAh_b = cbase;
        const uint32_t sAl_b = cbase + GARR;
        const uint32_t sWh_b = cbase + 2 * GARR;
        const uint32_t sWl_b = cbase + 3 * GARR;

#pragma unroll
        for (int ks = 0; ks < 2; ks++) {
            const int kA = ks * 16 + aK;
            const int kB = ks * 16 + bK;
            uint32_t ah[2][4], al[2][4];
#pragma unroll
            for (int mt = 0; mt < 2; mt++) {
                const uint32_t off = (uint32_t)((wm * 32 + mt * 16 + lane15) * GS + kA) * 2;
                ldsm_x4(ah[mt], sAh_b + off);
                ldsm_x4(al[mt], sAl_b + off);
            }
#pragma unroll
            for (int ntp = 0; ntp < 4; ntp++) {
                const uint32_t off = (uint32_t)((wn * 64 + ntp * 16 + bN) * GS + kB) * 2;
                uint32_t bhf[4], blf[4];
                ldsm_x4(bhf, sWh_b + off);
                ldsm_x4(blf, sWl_b + off);
#pragma unroll
                for (int h2 = 0; h2 < 2; h2++) {
                    const int nt = ntp * 2 + h2;
#pragma unroll
                    for (int mt = 0; mt < 2; mt++) {
                        mma16816(acc[mt][nt], ah[mt], bhf + h2 * 2);
                        mma16816(acc[mt][nt], ah[mt], blf + h2 * 2);
                        mma16816(acc[mt][nt], al[mt], bhf + h2 * 2);
                    }
                }
            }
        }
        __syncthreads();
    }

#pragma unroll
    for (int mt = 0; mt < 2; mt++) {
        const int row_lo = row0 + wm * 32 + mt * 16 + lq;
        const int row_hi = row_lo + 8;
#pragma unroll
        for (int nt = 0; nt < 8; nt++) {
            const int col = wn * 64 + nt * 8 + lr * 2;
            const float* c = acc[mt][nt];
            if (mode == 0) {
                *reinterpret_cast<float2*>(&Ofp[oOff + (long)row_lo * ldo + col]) =
                    make_float2(c[0], c[1]);
                *reinterpret_cast<float2*>(&Ofp[oOff + (long)row_hi * ldo + col]) =
                    make_float2(c[2], c[3]);
            } else {
                const long hb = oOff + (long)(col >> 6) * headStride + (col & 63);
                const long i0 = hb + (long)row_lo * 64;
                const long i1 = hb + (long)row_hi * 64;
                uint32_t h0, l0, h1, l1;
                split_pair(c[0], c[1], h0, l0);
                split_pair(c[2], c[3], h1, l1);
                *reinterpret_cast<uint32_t*>(&Oh[i0]) = h0;
                *reinterpret_cast<uint32_t*>(&Ol[i0]) = l0;
                *reinterpret_cast<uint32_t*>(&Oh[i1]) = h1;
                *reinterpret_cast<uint32_t*>(&Ol[i1]) = l1;
            }
        }
    }
}

// ---------------------------------------------------------------------------
// Flash attention, bf16x3, REGISTER-RESIDENT softmax (FA2-style).
// 128 threads / 4 warps; each warp owns 16 query rows x full 64-key width.
// Row stats (m,l) and P stay in registers; no S smem buffer at all.
// ---------------------------------------------------------------------------
#define ATA  9216                   // one 64x72 bf16 array
#define AT_KH 0                     // 2 stages each
#define AT_KL (2 * ATA)
#define AT_VH (4 * ATA)
#define AT_VL (6 * ATA)
#define AT_QH (8 * ATA)             // 73728
#define AT_QL (AT_QH + ATA)
#define AT_TOTAL (AT_QH + 2 * ATA)  // 92160

__global__ void __launch_bounds__(128, 2)
attn_kernel(const __nv_bfloat16* __restrict__ qh_g, const __nv_bfloat16* __restrict__ ql_g,
            const __nv_bfloat16* __restrict__ kvh_g, const __nv_bfloat16* __restrict__ kvl_g,
            const __nv_bfloat16* __restrict__ vth_g, const __nv_bfloat16* __restrict__ vtl_g,
            __nv_bfloat16* __restrict__ ph_g, __nv_bfloat16* __restrict__ pl_g)
{
    const int b = blockIdx.z, h = blockIdx.y;
    const int qb = blockIdx.x;
    const int d0 = qb * 64;
    const int bh = b * H_ + h;
    const int ntiles = C_ / 64;
    const int tstart = (qb == ntiles - 1) ? 0 : qb;

    extern __shared__ char smem[];
    const uint32_t sb = smem_u32(smem);
    __nv_bfloat16* sQh = (__nv_bfloat16*)(smem + AT_QH);
    __nv_bfloat16* sQl = (__nv_bfloat16*)(smem + AT_QL);

    const int tid = threadIdx.x;
    const int wid = tid >> 5, lane = tid & 31;
    const int lq = lane >> 2, lr = lane & 3;
    const int dtile = wid * 16;
    const int r0 = dtile + lq;

    const int lane15 = lane & 15;
    const int aK = (lane >> 4) << 3;
    const int bN = ((lane >> 4) << 3) + (lane & 7);
    const int bK = ((lane >> 3) & 1) << 3;

    const __nv_bfloat16* Kh_g = kvh_g + ((long)bh * 2) * C_ * 64;
    const __nv_bfloat16* Kl_g = kvl_g + ((long)bh * 2) * C_ * 64;
    const __nv_bfloat16* Vh_g = vth_g + (long)bh * 64 * C_;
    const __nv_bfloat16* Vl_g = vtl_g + (long)bh * 64 * C_;

    // Q tile: 64 rows x 64 cols hi+lo = 1024 x 16B, 8 per thread
#pragma unroll
    for (int l = 0; l < 4; l++) {
        int e = tid + l * 128;      // 0..511
        int r = e >> 3, q = (e & 7) * 8;
        long g = ((long)bh * C_ + d0 + r) * 64 + q;
        *reinterpret_cast<uint4*>(&sQh[r * 72 + q]) =
            *reinterpret_cast<const uint4*>(&qh_g[g]);
        *reinterpret_cast<uint4*>(&sQl[r * 72 + q]) =
            *reinterpret_cast<const uint4*>(&ql_g[g]);
    }

    // cp.async geometry: per array 512 vec4 / 128 threads = 4 each
    auto issue = [&](int t, int s) {
        const int c0 = t * 64;
        const uint32_t kh_d = sb + AT_KH + s * ATA;
        const uint32_t kl_d = sb + AT_KL + s * ATA;
        const uint32_t vh_d = sb + AT_VH + s * ATA;
        const uint32_t vl_d = sb + AT_VL + s * ATA;
#pragma unroll
        for (int j = 0; j < 4; j++) {
            const int e = tid + j * 128;
            const int r = e >> 3, q = e & 7;
            CP_ASYNC16(kh_d + r * 144 + q * 16, Kh_g + (long)(c0 + r) * 64 + q * 8);
            CP_ASYNC16(kl_d + r * 144 + q * 16, Kl_g + (long)(c0 + r) * 64 + q * 8);
            CP_ASYNC16(vh_d + r * 144 + q * 16, Vh_g + (long)r * C_ + c0 + q * 8);
            CP_ASYNC16(vl_d + r * 144 + q * 16, Vl_g + (long)r * C_ + c0 + q * 8);
        }
    };

    issue(tstart, tstart & 1);
    CP_COMMIT();
    __syncthreads();

    // persistent Q fragments
    uint32_t qh[4][4], ql[4][4];
#pragma unroll
    for (int ks = 0; ks < 4; ks++) {
        const uint32_t off = (uint32_t)((dtile + lane15) * 72 + ks * 16 + aK) * 2;
        ldsm_x4(qh[ks], sb + AT_QH + off);
        ldsm_x4(ql[ks], sb + AT_QL + off);
    }

    float oacc[8][4];
#pragma unroll
    for (int i = 0; i < 8; i++)
#pragma unroll
        for (int j = 0; j < 4; j++) oacc[i][j] = 0.0f;
    float m0 = -1e30f, m1 = -1e30f, l0 = 0.0f, l1 = 0.0f;

    for (int t = tstart; t < ntiles; t++) {
        if (t + 1 < ntiles) {
            issue(t + 1, (t + 1) & 1);
            CP_COMMIT();
            CP_WAIT1();
        } else {
            CP_WAIT0();
        }
        __syncthreads();

        const int s = t & 1;
        const int c0 = t * 64;
        const uint32_t sKh_b = sb + AT_KH + s * ATA;
        const uint32_t sKl_b = sb + AT_KL + s * ATA;
        const uint32_t sVh_b = sb + AT_VH + s * ATA;
        const uint32_t sVl_b = sb + AT_VL + s * ATA;

        // ---- S = Q @ K^T (full 64-col width per warp) ----
        float sacc[8][4];
#pragma unroll
        for (int i = 0; i < 8; i++)
#pragma unroll
            for (int j = 0; j < 4; j++) sacc[i][j] = 0.0f;
#pragma unroll
        for (int ks = 0; ks < 4; ks++) {
            const int kB = ks * 16 + bK;
#pragma unroll
            for (int ntp = 0; ntp < 4; ntp++) {
                const uint32_t off = (uint32_t)((ntp * 16 + bN) * 72 + kB) * 2;
                uint32_t bhf[4], blf[4];
                ldsm_x4(bhf, sKh_b + off);
                ldsm_x4(blf, sKl_b + off);
#pragma unroll
                for (int h2 = 0; h2 < 2; h2++) {
                    const int nt = ntp * 2 + h2;
                    mma16816(sacc[nt], qh[ks], bhf + h2 * 2);
                    mma16816(sacc[nt], qh[ks], blf + h2 * 2);
                    mma16816(sacc[nt], ql[ks], bhf + h2 * 2);
                }
            }
        }

        // ---- mask + scale in registers ----
        {
            const int dg0 = d0 + r0, dg1 = d0 + r0 + 8;
#pragma unroll
            for (int nt = 0; nt < 8; nt++) {
                const int cg = c0 + nt * 8 + lr * 2;
                if (cg     <= dg0) sacc[nt][0] -= 100.0f;
                if (cg + 1 <= dg0) sacc[nt][1] -= 100.0f;
                if (cg     <= dg1) sacc[nt][2] -= 100.0f;
                if (cg + 1 <= dg1) sacc[nt][3] -= 100.0f;
#pragma unroll
                for (int j = 0; j < 4; j++) sacc[nt][j] *= 0.125f;
            }
        }

        // ---- register softmax (quad shuffles; rows r0 and r0+8) ----
        {
            float mt0 = sacc[0][0], mt1 = sacc[0][2];
#pragma unroll
            for (int nt = 0; nt < 8; nt++) {
                mt0 = fmaxf(mt0, fmaxf(sacc[nt][0], sacc[nt][1]));
                mt1 = fmaxf(mt1, fmaxf(sacc[nt][2], sacc[nt][3]));
            }
            mt0 = fmaxf(mt0, __shfl_xor_sync(0xffffffff, mt0, 1));
            mt0 = fmaxf(mt0, __shfl_xor_sync(0xffffffff, mt0, 2));
            mt1 = fmaxf(mt1, __shfl_xor_sync(0xffffffff, mt1, 1));
            mt1 = fmaxf(mt1, __shfl_xor_sync(0xffffffff, mt1, 2));
            const float mn0 = fmaxf(m0, mt0);
            const float mn1 = fmaxf(m1, mt1);
            const float a0 = __expf(m0 - mn0);
            const float a1 = __expf(m1 - mn1);
            float s0 = 0.0f, s1 = 0.0f;
#pragma unroll
            for (int nt = 0; nt < 8; nt++) {
                sacc[nt][0] = __expf(sacc[nt][0] - mn0); s0 += sacc[nt][0];
                sacc[nt][1] = __expf(sacc[nt][1] - mn0); s0 += sacc[nt][1];
                sacc[nt][2] = __expf(sacc[nt][2] - mn1); s1 += sacc[nt][2];
                sacc[nt][3] = __expf(sacc[nt][3] - mn1); s1 += sacc[nt][3];
            }
            s0 += __shfl_xor_sync(0xffffffff, s0, 1);
            s0 += __shfl_xor_sync(0xffffffff, s0, 2);
            s1 += __shfl_xor_sync(0xffffffff, s1, 1);
            s1 += __shfl_xor_sync(0xffffffff, s1, 2);
            l0 = l0 * a0 + s0;
            l1 = l1 * a1 + s1;
            m0 = mn0; m1 = mn1;
#pragma unroll
            for (int nt = 0; nt < 8; nt++) {
                oacc[nt][0] *= a0; oacc[nt][1] *= a0;
                oacc[nt][2] *= a1; oacc[nt][3] *= a1;
            }
        }

        // ---- O += P @ V ; P fragments straight from sacc registers ----
#pragma unroll
        for (int ks = 0; ks < 4; ks++) {
            uint32_t pah[4], pal[4];
            split_pair(sacc[2 * ks][0],     sacc[2 * ks][1],     pah[0], pal[0]);
            split_pair(sacc[2 * ks][2],     sacc[2 * ks][3],     pah[1], pal[1]);
            split_pair(sacc[2 * ks + 1][0], sacc[2 * ks + 1][1], pah[2], pal[2]);
            split_pair(sacc[2 * ks + 1][2], sacc[2 * ks + 1][3], pah[3], pal[3]);
            const int kB = ks * 16 + bK;
#pragma unroll
            for (int ntp = 0; ntp < 4; ntp++) {
                const uint32_t off = (uint32_t)((ntp * 16 + bN) * 72 + kB) * 2;
                uint32_t bhf[4], blf[4];
                ldsm_x4(bhf, sVh_b + off);
                ldsm_x4(blf, sVl_b + off);
#pragma unroll
                for (int h2 = 0; h2 < 2; h2++) {
                    const int nt = ntp * 2 + h2;
                    mma16816(oacc[nt], pah, bhf + h2 * 2);
                    mma16816(oacc[nt], pah, blf + h2 * 2);
                    mma16816(oacc[nt], pal, bhf + h2 * 2);
                }
            }
        }
        __syncthreads();   // all warps done with stage s before it is refilled
    }

    // ---- epilogue -> pre (hi/lo), layout [b*C + d][h*64 + v] ----
    {
        const float il0 = 1.0f / l0;
        const float il1 = 1.0f / l1;
#pragma unroll
        for (int nt = 0; nt < 8; nt++) {
            const int col = h * 64 + nt * 8 + lr * 2;
            const long i0 = ((long)(b * C_ + d0 + r0)) * (H_ * V_) + col;
            const long i1 = ((long)(b * C_ + d0 + r0 + 8)) * (H_ * V_) + col;
            uint32_t h0, lo0, h1, lo1;
            split_pair(oacc[nt][0] * il0, oacc[nt][1] * il0, h0, lo0);
            split_pair(oacc[nt][2] * il1, oacc[nt][3] * il1, h1, lo1);
            *reinterpret_cast<uint32_t*>(&ph_g[i0]) = h0;
            *reinterpret_cast<uint32_t*>(&pl_g[i0]) = lo0;
            *reinterpret_cast<uint32_t*>(&ph_g[i1]) = h1;
            *reinterpret_cast<uint32_t*>(&pl_g[i1]) = lo1;
        }
    }
}

// ---------------------------------------------------------------------------

extern "C" void kernel_launch(void* const* d_in, const int* in_sizes, int n_in,
                              void* d_out, int out_size)
{
    const float* kvinput = (const float*)d_in[0];
    const float* qinput  = (const float*)d_in[1];
    const float* wq      = (const float*)d_in[2];
    const float* wk      = (const float*)d_in[3];
    const float* wv      = (const float*)d_in[4];
    const float* wo      = (const float*)d_in[5];
    float* out = (float*)d_out;

    __nv_bfloat16 *xqh, *xql, *xkh, *xkl;
    __nv_bfloat16 *wqh, *wql, *wkvh, *wkvl, *woh, *wol;
    __nv_bfloat16 *qh, *ql, *kvh, *kvl, *vth, *vtl, *prh, *prl;
    cudaGetSymbolAddress((void**)&xqh, s_xq_hi);
    cudaGetSymbolAddress((void**)&xql, s_xq_lo);
    cudaGetSymbolAddress((void**)&xkh, s_xkv_hi);
    cudaGetSymbolAddress((void**)&xkl, s_xkv_lo);
    cudaGetSymbolAddress((void**)&wqh, s_wqT_hi);
    cudaGetSymbolAddress((void**)&wql, s_wqT_lo);
    cudaGetSymbolAddress((void**)&wkvh, s_wkvT_hi);
    cudaGetSymbolAddress((void**)&wkvl, s_wkvT_lo);
    cudaGetSymbolAddress((void**)&woh, s_woT_hi);
    cudaGetSymbolAddress((void**)&wol, s_woT_lo);
    cudaGetSymbolAddress((void**)&qh,  s_q_hi);
    cudaGetSymbolAddress((void**)&ql,  s_q_lo);
    cudaGetSymbolAddress((void**)&kvh, s_kv_hi);
    cudaGetSymbolAddress((void**)&kvl, s_kv_lo);
    cudaGetSymbolAddress((void**)&vth, s_vT_hi);
    cudaGetSymbolAddress((void**)&vtl, s_vT_lo);
    cudaGetSymbolAddress((void**)&prh, s_pre_hi);
    cudaGetSymbolAddress((void**)&prl, s_pre_lo);

    cudaFuncSetAttribute(gemm_bf16x3,
                         cudaFuncAttributeMaxDynamicSharedMemorySize, GEMM_SMEM2);
    cudaFuncSetAttribute(attn_kernel,
                         cudaFuncAttributeMaxDynamicSharedMemorySize, AT_TOTAL);

    // launch 0: split both inputs
    {
        int n4 = B_ * C_ * M_ / 4;
        split2_kernel<<<(2 * n4 + 255) / 256, 256>>>(qinput, kvinput,
                                                     xqh, xql, xkh, xkl, n4);
    }
    // launch 1: all weight transposes
    {
        dim3 tb(32, 8);
        trans_all_kernel<<<4096, tb>>>(wq, wk, wv, wo,
                                       wqh, wql, wkvh, wkvl, woh, wol);
    }

    dim3 blk(256);
    const long hs = (long)C_ * 64;

    // launch 2: Q projection (2 heads per y-block)
    dim3 pgrid(C_ / 128, H_ / 2, B_);
    gemm_bf16x3<<<pgrid, blk, GEMM_SMEM2>>>(xqh, xql, wqh, wql,
        nullptr, qh, ql, M_, 1, 0, hs,
        (long)C_ * M_, (long)128 * M_, 2 * hs, (long)H_ * C_ * 64);

    // launch 3: K+V projection
    dim3 kvgrid(C_ / 128, H_, B_);
    gemm_bf16x3<<<kvgrid, blk, GEMM_SMEM2>>>(xkh, xkl, wkvh, wkvl,
        nullptr, kvh, kvl, M_, 1, 0, hs,
        (long)C_ * M_, (long)128 * M_, 2 * hs, (long)H_ * 2 * C_ * 64);

    // launch 4: V transpose
    {
        dim3 vg(C_ / 64, B_ * H_);
        vtrans_kernel<<<vg, 256>>>(kvh, kvl, vth, vtl);
    }

    // launch 5: attention (register softmax, mask-aware tile skipping)
    dim3 agrid(C_ / 64, H_, B_);
    attn_kernel<<<agrid, 128, AT_TOTAL>>>(qh, ql, kvh, kvl, vth, vtl, prh, prl);

    // launch 6: output projection
    dim3 ogrid((B_ * C_) / 128, M_ / 128, 1);
    gemm_bf16x3<<<ogrid, blk, GEMM_SMEM2>>>(prh, prl, woh, wol,
        out, nullptr, nullptr, M_, 0, M_, 0L,
        0L, (long)128 * M_, 128L, 0L);
}

// round 8
// speedup vs baseline: 4.7988x; 1.3631x over previous
#include <cuda_runtime.h>
#include <cuda_fp16.h>
#include <cstdint>
#include <math.h>

#define B_ 2
#define C_ 2048
#define M_ 1024
#define H_ 16
#define K_ 64
#define V_ 64

// ------------------------- scratch (no cudaMalloc) -------------------------
__device__ __half s_xq_h [(size_t)B_ * C_ * M_];        // A-side: hi only
__device__ __half s_xkv_h[(size_t)B_ * C_ * M_];

__device__ __half s_wqT_h [(size_t)H_ * K_ * M_];       // B-side: hi + lo
__device__ __half s_wqT_l [(size_t)H_ * K_ * M_];
__device__ __half s_wkvT_h[(size_t)H_ * 128 * M_];      // rows 0-63 K, 64-127 V
__device__ __half s_wkvT_l[(size_t)H_ * 128 * M_];
__device__ __half s_woT_h [(size_t)M_ * (H_ * V_)];
__device__ __half s_woT_l [(size_t)M_ * (H_ * V_)];

__device__ __half s_q_h [(size_t)B_ * H_ * C_ * K_];    // A operand: hi only
__device__ __half s_kv_h[(size_t)B_ * H_ * 2 * C_ * 64];// B operand: hi+lo
__device__ __half s_kv_l[(size_t)B_ * H_ * 2 * C_ * 64];
__device__ __half s_vT_h[(size_t)B_ * H_ * V_ * C_];
__device__ __half s_vT_l[(size_t)B_ * H_ * V_ * C_];

__device__ __half s_pre_h[(size_t)B_ * C_ * (H_ * V_)]; // A operand: hi only

// ------------------------------ helpers ------------------------------------
__device__ __forceinline__ uint32_t packh2(float x, float y) {
    __half2 h = __floats2half2_rn(x, y);
    return *reinterpret_cast<uint32_t*>(&h);
}
__device__ __forceinline__ void split_h(float x, float y,
                                        uint32_t& hi, uint32_t& lo) {
    __half2 h = __floats2half2_rn(x, y);
    float hx = __half2float(h.x);
    float hy = __half2float(h.y);
    __half2 l = __floats2half2_rn(x - hx, y - hy);
    hi = *reinterpret_cast<uint32_t*>(&h);
    lo = *reinterpret_cast<uint32_t*>(&l);
}

__device__ __forceinline__ void mma16816(float* c, const uint32_t* a,
                                         const uint32_t* b) {
    asm volatile(
        "mma.sync.aligned.m16n8k16.row.col.f32.f16.f16.f32 "
        "{%0,%1,%2,%3}, {%4,%5,%6,%7}, {%8,%9}, {%0,%1,%2,%3};\n"
        : "+f"(c[0]), "+f"(c[1]), "+f"(c[2]), "+f"(c[3])
        : "r"(a[0]), "r"(a[1]), "r"(a[2]), "r"(a[3]), "r"(b[0]), "r"(b[1]));
}

__device__ __forceinline__ void ldsm_x4(uint32_t* r, uint32_t addr) {
    asm volatile(
        "ldmatrix.sync.aligned.m8n8.x4.shared.b16 {%0,%1,%2,%3}, [%4];\n"
        : "=r"(r[0]), "=r"(r[1]), "=r"(r[2]), "=r"(r[3]) : "r"(addr));
}

__device__ __forceinline__ uint32_t smem_u32(const void* p) {
    uint32_t a;
    asm("{ .reg .u64 t; cvta.to.shared.u64 t, %1; cvt.u32.u64 %0, t; }"
        : "=r"(a) : "l"(p));
    return a;
}
#define CP_ASYNC16(dst, src) \
    asm volatile("cp.async.ca.shared.global [%0], [%1], 16;\n" \
                 :: "r"(dst), "l"(src) : "memory")
#define CP_COMMIT() asm volatile("cp.async.commit_group;\n" ::: "memory")
#define CP_WAIT0()  asm volatile("cp.async.wait_group 0;\n" ::: "memory")
#define CP_WAIT1()  asm volatile("cp.async.wait_group 1;\n" ::: "memory")

// --------------------------- pre-pass kernels ------------------------------
// convert both inputs to fp16 hi-only in one launch
__global__ void cvt2_kernel(const float* __restrict__ inq,
                            const float* __restrict__ inkv,
                            __half* __restrict__ oq, __half* __restrict__ okv,
                            int n4each) {
    int i = blockIdx.x * blockDim.x + threadIdx.x;
    const float* in;
    __half* o;
    int idx;
    if (i < n4each) { in = inq; o = oq; idx = i; }
    else if (i < 2 * n4each) { in = inkv; o = okv; idx = i - n4each; }
    else return;
    float4 v = reinterpret_cast<const float4*>(in)[idx];
    reinterpret_cast<uint2*>(o)[idx] =
        make_uint2(packh2(v.x, v.y), packh2(v.z, v.w));
}

// all 4 weight transposes (fp16 hi/lo split) in one launch; 4096 blocks
__global__ void trans_all_kernel(const float* __restrict__ wq,
                                 const float* __restrict__ wk,
                                 const float* __restrict__ wv,
                                 const float* __restrict__ wo,
                                 __half* __restrict__ wqh, __half* __restrict__ wql,
                                 __half* __restrict__ wkvh, __half* __restrict__ wkvl,
                                 __half* __restrict__ woh, __half* __restrict__ wol) {
    __shared__ float t[32][33];
    const int bid = blockIdx.x;
    const float* in;
    __half *oh, *ol;
    int R, Cdim, c0, r0;
    long ib, ob;
    if (bid < 3072) {
        const int m = bid >> 10;
        const int r = bid & 1023;
        const int hh = r >> 6;
        const int rem = r & 63;
        const int gy = rem >> 1, gx = rem & 1;
        R = M_; Cdim = K_;
        c0 = gx * 32; r0 = gy * 32;
        if (m == 0) {
            in = wq;  oh = wqh;  ol = wql;
            ib = (long)hh * M_ * K_; ob = (long)hh * K_ * M_;
        } else if (m == 1) {
            in = wk;  oh = wkvh; ol = wkvl;
            ib = (long)hh * M_ * K_; ob = (long)hh * 128 * M_;
        } else {
            in = wv;  oh = wkvh + (size_t)64 * M_; ol = wkvl + (size_t)64 * M_;
            ib = (long)hh * M_ * V_; ob = (long)hh * 128 * M_;
        }
    } else {
        const int r = bid - 3072;
        R = H_ * V_; Cdim = M_;
        c0 = (r & 31) * 32; r0 = (r >> 5) * 32;
        in = wo; oh = woh; ol = wol; ib = 0; ob = 0;
    }
    in += ib;
#pragma unroll
    for (int i = threadIdx.y; i < 32; i += 8)
        t[i][threadIdx.x] = in[(long)(r0 + i) * Cdim + c0 + threadIdx.x];
    __syncthreads();
#pragma unroll
    for (int i = threadIdx.y; i < 32; i += 8) {
        float v = t[threadIdx.x][i];
        __half h = __float2half_rn(v);
        __half l = __float2half_rn(v - __half2float(h));
        long idx = ob + (long)(c0 + i) * R + r0 + threadIdx.x;
        oh[idx] = h;
        ol[idx] = l;
    }
}

// V (in combined KV) [bh][1][c][v] -> VT [bh][v][c] for hi and lo
__global__ void vtrans_kernel(const __half* __restrict__ kvh,
                              const __half* __restrict__ kvl,
                              __half* __restrict__ oth,
                              __half* __restrict__ otl) {
    const int bh = blockIdx.y;
    const int c0 = blockIdx.x * 64;
    const long ib = ((long)bh * 2 + 1) * C_ * 64;
    const long ob = (long)bh * 64 * C_;
    __shared__ __half t[64][68];
    const int tid = threadIdx.x;

    for (int pass = 0; pass < 2; pass++) {
        const __half* src = pass ? kvl : kvh;
        __half* dst = pass ? otl : oth;
#pragma unroll
        for (int l = 0; l < 4; l++) {
            int e = tid + l * 256;
            int c = e >> 4, v4 = (e & 15) * 4;
            *reinterpret_cast<uint2*>(&t[c][v4]) =
                *reinterpret_cast<const uint2*>(&src[ib + (long)(c0 + c) * 64 + v4]);
        }
        __syncthreads();
#pragma unroll
        for (int l = 0; l < 4; l++) {
            int e = tid + l * 256;
            int v = e >> 4, c4 = (e & 15) * 4;
            __half tmp[4] = {t[c4][v], t[c4 + 1][v], t[c4 + 2][v], t[c4 + 3][v]};
            *reinterpret_cast<uint2*>(&dst[ob + (long)v * C_ + c0 + c4]) =
                *reinterpret_cast<const uint2*>(tmp);
        }
        __syncthreads();
    }
}

// ---------------------------------------------------------------------------
// fp16x2 GEMM core: O = A_hi * (W_hi + W_lo), 128x128 tile, inner = 1024,
// K-chunk 32, 3-stage cp.async pipeline, one syncthreads per chunk, ldmatrix.
// ---------------------------------------------------------------------------
#define GS 40
#define PARR 10240                   // 128 * GS * 2B
#define PSTG (3 * PARR)              // A + Wh + Wl per stage = 30720
#define GEMM_SMEM3 (3 * PSTG)        // 92160

#define GEMM_CORE(A_, Wh_, Wl_)                                              \
    const int tid = threadIdx.x;                                             \
    const int wid = tid >> 5, lane = tid & 31;                               \
    const int lq = lane >> 2, lr = lane & 3;                                 \
    const int wm = wid >> 1, wn = wid & 1;                                   \
    const int lane15 = lane & 15;                                            \
    const int aK = (lane >> 4) << 3;                                         \
    const int bN = ((lane >> 4) << 3) + (lane & 7);                          \
    const int bK = ((lane >> 3) & 1) << 3;                                   \
    const int r_a = tid >> 2, q_a = tid & 3;                                 \
    const int r_b = (tid + 256) >> 2, q_b = (tid + 256) & 3;                 \
    float acc[2][8][4];                                                      \
    _Pragma("unroll") for (int a = 0; a < 2; a++)                            \
    _Pragma("unroll") for (int b = 0; b < 8; b++)                            \
    _Pragma("unroll") for (int c = 0; c < 4; c++) acc[a][b][c] = 0.0f;       \
    auto issue = [&](int ck, int s) {                                        \
        const int m0 = ck << 5;                                              \
        const uint32_t base = sb + s * PSTG;                                 \
        CP_ASYNC16(base + r_a * 80 + q_a * 16,                               \
                   A_ + (long)(row0 + r_a) * 1024 + m0 + q_a * 8);           \
        CP_ASYNC16(base + r_b * 80 + q_b * 16,                               \
                   A_ + (long)(row0 + r_b) * 1024 + m0 + q_b * 8);           \
        CP_ASYNC16(base + PARR + r_a * 80 + q_a * 16,                        \
                   Wh_ + (long)r_a * 1024 + m0 + q_a * 8);                   \
        CP_ASYNC16(base + PARR + r_b * 80 + q_b * 16,                        \
                   Wh_ + (long)r_b * 1024 + m0 + q_b * 8);                   \
        CP_ASYNC16(base + 2 * PARR + r_a * 80 + q_a * 16,                    \
                   Wl_ + (long)r_a * 1024 + m0 + q_a * 8);                   \
        CP_ASYNC16(base + 2 * PARR + r_b * 80 + q_b * 16,                    \
                   Wl_ + (long)r_b * 1024 + m0 + q_b * 8);                   \
    };                                                                       \
    issue(0, 0); CP_COMMIT();                                                \
    issue(1, 1); CP_COMMIT();                                                \
    for (int it = 0; it < 32; it++) {                                        \
        if (it < 31) { CP_WAIT1(); } else { CP_WAIT0(); }                    \
        __syncthreads();                                                     \
        if (it + 2 < 32) { issue(it + 2, (it + 2) % 3); CP_COMMIT(); }       \
        const uint32_t cbase = sb + (it % 3) * PSTG;                         \
        _Pragma("unroll")                                                    \
        for (int ks = 0; ks < 2; ks++) {                                     \
            const int kA = ks * 16 + aK;                                     \
            const int kB = ks * 16 + bK;                                     \
            uint32_t ah[2][4];                                               \
            _Pragma("unroll")                                                \
            for (int mt = 0; mt < 2; mt++) {                                 \
                const uint32_t off =                                         \
                    (uint32_t)((wm * 32 + mt * 16 + lane15) * GS + kA) * 2;  \
                ldsm_x4(ah[mt], cbase + off);                                \
            }                                                                \
            _Pragma("unroll")                                                \
            for (int ntp = 0; ntp < 4; ntp++) {                              \
                const uint32_t off =                                         \
                    (uint32_t)((wn * 64 + ntp * 16 + bN) * GS + kB) * 2;     \
                uint32_t bhf[4], blf[4];                                     \
                ldsm_x4(bhf, cbase + PARR + off);                            \
                ldsm_x4(blf, cbase + 2 * PARR + off);                        \
                _Pragma("unroll")                                            \
                for (int h2 = 0; h2 < 2; h2++) {                             \
                    const int nt = ntp * 2 + h2;                             \
                    _Pragma("unroll")                                        \
                    for (int mt = 0; mt < 2; mt++) {                         \
                        mma16816(acc[mt][nt], ah[mt], bhf + h2 * 2);         \
                        mma16816(acc[mt][nt], ah[mt], blf + h2 * 2);         \
                    }                                                        \
                }                                                            \
            }                                                                \
        }                                                                    \
    }

// Merged Q + KV projections: grid (16, 24, 2). y<8: Q (2 heads/tile, hi-only
// out); y>=8: KV head y-8 (hi+lo out, K cols 0-63, V cols 64-127).
__global__ void __launch_bounds__(256, 2)
proj_kernel(const __half* __restrict__ xq, const __half* __restrict__ xkv,
            const __half* __restrict__ wqh, const __half* __restrict__ wql,
            const __half* __restrict__ wkvh, const __half* __restrict__ wkvl,
            __half* __restrict__ q_out,
            __half* __restrict__ kv_h, __half* __restrict__ kv_l)
{
    const int z = blockIdx.z, y = blockIdx.y;
    const int row0 = blockIdx.x * 128;
    const long hs = (long)C_ * 64;
    const bool isQ = (y < 8);
    const __half *A, *Wh, *Wl;
    long oOff;
    if (isQ) {
        A  = xq + (long)z * C_ * M_;
        Wh = wqh + (long)y * 128 * M_;
        Wl = wql + (long)y * 128 * M_;
        oOff = (long)z * H_ * hs + (long)y * 2 * hs;
    } else {
        const int yk = y - 8;
        A  = xkv + (long)z * C_ * M_;
        Wh = wkvh + (long)yk * 128 * M_;
        Wl = wkvl + (long)yk * 128 * M_;
        oOff = (long)z * H_ * 2 * hs + (long)yk * 2 * hs;
    }

    extern __shared__ char smem[];
    const uint32_t sb = smem_u32(smem);
    GEMM_CORE(A, Wh, Wl)

#pragma unroll
    for (int mt = 0; mt < 2; mt++) {
        const int row_lo = row0 + wm * 32 + mt * 16 + lq;
        const int row_hi = row_lo + 8;
#pragma unroll
        for (int nt = 0; nt < 8; nt++) {
            const int col = wn * 64 + nt * 8 + lr * 2;
            const float* c = acc[mt][nt];
            const long hb = oOff + (long)(col >> 6) * hs + (col & 63);
            const long i0 = hb + (long)row_lo * 64;
            const long i1 = hb + (long)row_hi * 64;
            if (isQ) {
                *reinterpret_cast<uint32_t*>(&q_out[i0]) = packh2(c[0], c[1]);
                *reinterpret_cast<uint32_t*>(&q_out[i1]) = packh2(c[2], c[3]);
            } else {
                uint32_t h0, l0, h1, l1;
                split_h(c[0], c[1], h0, l0);
                split_h(c[2], c[3], h1, l1);
                *reinterpret_cast<uint32_t*>(&kv_h[i0]) = h0;
                *reinterpret_cast<uint32_t*>(&kv_l[i0]) = l0;
                *reinterpret_cast<uint32_t*>(&kv_h[i1]) = h1;
                *reinterpret_cast<uint32_t*>(&kv_l[i1]) = l1;
            }
        }
    }
}

// Output projection: out[4096][1024] = pre_hi @ (woT hi+lo). grid (32, 8).
__global__ void __launch_bounds__(256, 2)
outproj_kernel(const __half* __restrict__ pre,
               const __half* __restrict__ woh, const __half* __restrict__ wol,
               float* __restrict__ out)
{
    const int row0 = blockIdx.x * 128;
    const int col0 = blockIdx.y * 128;
    const __half* A  = pre;
    const __half* Wh = woh + (long)col0 * M_;
    const __half* Wl = wol + (long)col0 * M_;

    extern __shared__ char smem[];
    const uint32_t sb = smem_u32(smem);
    GEMM_CORE(A, Wh, Wl)

#pragma unroll
    for (int mt = 0; mt < 2; mt++) {
        const int row_lo = row0 + wm * 32 + mt * 16 + lq;
        const int row_hi = row_lo + 8;
#pragma unroll
        for (int nt = 0; nt < 8; nt++) {
            const int col = col0 + wn * 64 + nt * 8 + lr * 2;
            const float* c = acc[mt][nt];
            *reinterpret_cast<float2*>(&out[(long)row_lo * M_ + col]) =
                make_float2(c[0], c[1]);
            *reinterpret_cast<float2*>(&out[(long)row_hi * M_ + col]) =
                make_float2(c[2], c[3]);
        }
    }
}

// ---------------------------------------------------------------------------
// Flash attention, fp16x2 (Q/P hi-only; K/V hi+lo), register softmax,
// mask-aware tile skipping, cp.async double-buffered, ldmatrix.
// ---------------------------------------------------------------------------
#define ATA  9216                    // one 64x72 fp16 array
#define AT_KH 0                      // 2 stages each
#define AT_KL (2 * ATA)
#define AT_VH (4 * ATA)
#define AT_VL (6 * ATA)
#define AT_QH (8 * ATA)              // 73728
#define AT_TOTAL (AT_QH + ATA)       // 82944

__global__ void __launch_bounds__(128, 2)
attn_kernel(const __half* __restrict__ qh_g,
            const __half* __restrict__ kvh_g, const __half* __restrict__ kvl_g,
            const __half* __restrict__ vth_g, const __half* __restrict__ vtl_g,
            __half* __restrict__ pre_g)
{
    const int b = blockIdx.z, h = blockIdx.y;
    const int qb = blockIdx.x;
    const int d0 = qb * 64;
    const int bh = b * H_ + h;
    const int ntiles = C_ / 64;
    const int tstart = (qb == ntiles - 1) ? 0 : qb;

    extern __shared__ char smem[];
    const uint32_t sb = smem_u32(smem);
    __half* sQh = (__half*)(smem + AT_QH);

    const int tid = threadIdx.x;
    const int wid = tid >> 5, lane = tid & 31;
    const int lq = lane >> 2, lr = lane & 3;
    const int dtile = wid * 16;
    const int r0 = dtile + lq;

    const int lane15 = lane & 15;
    const int aK = (lane >> 4) << 3;
    const int bN = ((lane >> 4) << 3) + (lane & 7);
    const int bK = ((lane >> 3) & 1) << 3;

    const __half* Kh_g = kvh_g + ((long)bh * 2) * C_ * 64;
    const __half* Kl_g = kvl_g + ((long)bh * 2) * C_ * 64;
    const __half* Vh_g = vth_g + (long)bh * 64 * C_;
    const __half* Vl_g = vtl_g + (long)bh * 64 * C_;

    // Q tile: 64 rows x 64 cols hi = 512 x 16B, 4 per thread
#pragma unroll
    for (int l = 0; l < 4; l++) {
        int e = tid + l * 128;
        int r = e >> 3, q = (e & 7) * 8;
        long g = ((long)bh * C_ + d0 + r) * 64 + q;
        *reinterpret_cast<uint4*>(&sQh[r * 72 + q]) =
            *reinterpret_cast<const uint4*>(&qh_g[g]);
    }

    auto issue = [&](int t, int s) {
        const int c0 = t * 64;
        const uint32_t kh_d = sb + AT_KH + s * ATA;
        const uint32_t kl_d = sb + AT_KL + s * ATA;
        const uint32_t vh_d = sb + AT_VH + s * ATA;
        const uint32_t vl_d = sb + AT_VL + s * ATA;
#pragma unroll
        for (int j = 0; j < 4; j++) {
            const int e = tid + j * 128;
            const int r = e >> 3, q = e & 7;
            CP_ASYNC16(kh_d + r * 144 + q * 16, Kh_g + (long)(c0 + r) * 64 + q * 8);
            CP_ASYNC16(kl_d + r * 144 + q * 16, Kl_g + (long)(c0 + r) * 64 + q * 8);
            CP_ASYNC16(vh_d + r * 144 + q * 16, Vh_g + (long)r * C_ + c0 + q * 8);
            CP_ASYNC16(vl_d + r * 144 + q * 16, Vl_g + (long)r * C_ + c0 + q * 8);
        }
    };

    issue(tstart, tstart & 1);
    CP_COMMIT();
    __syncthreads();

    // persistent Q fragments (hi only)
    uint32_t qh[4][4];
#pragma unroll
    for (int ks = 0; ks < 4; ks++) {
        const uint32_t off = (uint32_t)((dtile + lane15) * 72 + ks * 16 + aK) * 2;
        ldsm_x4(qh[ks], sb + AT_QH + off);
    }

    float oacc[8][4];
#pragma unroll
    for (int i = 0; i < 8; i++)
#pragma unroll
        for (int j = 0; j < 4; j++) oacc[i][j] = 0.0f;
    float m0 = -1e30f, m1 = -1e30f, l0 = 0.0f, l1 = 0.0f;

    for (int t = tstart; t < ntiles; t++) {
        if (t + 1 < ntiles) {
            issue(t + 1, (t + 1) & 1);
            CP_COMMIT();
            CP_WAIT1();
        } else {
            CP_WAIT0();
        }
        __syncthreads();

        const int s = t & 1;
        const int c0 = t * 64;
        const uint32_t sKh_b = sb + AT_KH + s * ATA;
        const uint32_t sKl_b = sb + AT_KL + s * ATA;
        const uint32_t sVh_b = sb + AT_VH + s * ATA;
        const uint32_t sVl_b = sb + AT_VL + s * ATA;

        // ---- S = Q @ K^T ----
        float sacc[8][4];
#pragma unroll
        for (int i = 0; i < 8; i++)
#pragma unroll
            for (int j = 0; j < 4; j++) sacc[i][j] = 0.0f;
#pragma unroll
        for (int ks = 0; ks < 4; ks++) {
            const int kB = ks * 16 + bK;
#pragma unroll
            for (int ntp = 0; ntp < 4; ntp++) {
                const uint32_t off = (uint32_t)((ntp * 16 + bN) * 72 + kB) * 2;
                uint32_t bhf[4], blf[4];
                ldsm_x4(bhf, sKh_b + off);
                ldsm_x4(blf, sKl_b + off);
#pragma unroll
                for (int h2 = 0; h2 < 2; h2++) {
                    const int nt = ntp * 2 + h2;
                    mma16816(sacc[nt], qh[ks], bhf + h2 * 2);
                    mma16816(sacc[nt], qh[ks], blf + h2 * 2);
                }
            }
        }

        // ---- mask + scale in registers ----
        {
            const int dg0 = d0 + r0, dg1 = d0 + r0 + 8;
#pragma unroll
            for (int nt = 0; nt < 8; nt++) {
                const int cg = c0 + nt * 8 + lr * 2;
                if (cg     <= dg0) sacc[nt][0] -= 100.0f;
                if (cg + 1 <= dg0) sacc[nt][1] -= 100.0f;
                if (cg     <= dg1) sacc[nt][2] -= 100.0f;
                if (cg + 1 <= dg1) sacc[nt][3] -= 100.0f;
#pragma unroll
                for (int j = 0; j < 4; j++) sacc[nt][j] *= 0.125f;
            }
        }

        // ---- register softmax (quad shuffles) ----
        {
            float mt0 = sacc[0][0], mt1 = sacc[0][2];
#pragma unroll
            for (int nt = 0; nt < 8; nt++) {
                mt0 = fmaxf(mt0, fmaxf(sacc[nt][0], sacc[nt][1]));
                mt1 = fmaxf(mt1, fmaxf(sacc[nt][2], sacc[nt][3]));
            }
            mt0 = fmaxf(mt0, __shfl_xor_sync(0xffffffff, mt0, 1));
            mt0 = fmaxf(mt0, __shfl_xor_sync(0xffffffff, mt0, 2));
            mt1 = fmaxf(mt1, __shfl_xor_sync(0xffffffff, mt1, 1));
            mt1 = fmaxf(mt1, __shfl_xor_sync(0xffffffff, mt1, 2));
            const float mn0 = fmaxf(m0, mt0);
            const float mn1 = fmaxf(m1, mt1);
            const float a0 = __expf(m0 - mn0);
            const float a1 = __expf(m1 - mn1);
            float s0 = 0.0f, s1 = 0.0f;
#pragma unroll
            for (int nt = 0; nt < 8; nt++) {
                sacc[nt][0] = __expf(sacc[nt][0] - mn0); s0 += sacc[nt][0];
                sacc[nt][1] = __expf(sacc[nt][1] - mn0); s0 += sacc[nt][1];
                sacc[nt][2] = __expf(sacc[nt][2] - mn1); s1 += sacc[nt][2];
                sacc[nt][3] = __expf(sacc[nt][3] - mn1); s1 += sacc[nt][3];
            }
            s0 += __shfl_xor_sync(0xffffffff, s0, 1);
            s0 += __shfl_xor_sync(0xffffffff, s0, 2);
            s1 += __shfl_xor_sync(0xffffffff, s1, 1);
            s1 += __shfl_xor_sync(0xffffffff, s1, 2);
            l0 = l0 * a0 + s0;
            l1 = l1 * a1 + s1;
            m0 = mn0; m1 = mn1;
#pragma unroll
            for (int nt = 0; nt < 8; nt++) {
                oacc[nt][0] *= a0; oacc[nt][1] *= a0;
                oacc[nt][2] *= a1; oacc[nt][3] *= a1;
            }
        }

        // ---- O += P @ V ; P hi-only fragments straight from sacc ----
#pragma unroll
        for (int ks = 0; ks < 4; ks++) {
            uint32_t ph[4];
            ph[0] = packh2(sacc[2 * ks][0],     sacc[2 * ks][1]);
            ph[1] = packh2(sacc[2 * ks][2],     sacc[2 * ks][3]);
            ph[2] = packh2(sacc[2 * ks + 1][0], sacc[2 * ks + 1][1]);
            ph[3] = packh2(sacc[2 * ks + 1][2], sacc[2 * ks + 1][3]);
            const int kB = ks * 16 + bK;
#pragma unroll
            for (int ntp = 0; ntp < 4; ntp++) {
                const uint32_t off = (uint32_t)((ntp * 16 + bN) * 72 + kB) * 2;
                uint32_t bhf[4], blf[4];
                ldsm_x4(bhf, sVh_b + off);
                ldsm_x4(blf, sVl_b + off);
#pragma unroll
                for (int h2 = 0; h2 < 2; h2++) {
                    const int nt = ntp * 2 + h2;
                    mma16816(oacc[nt], ph, bhf + h2 * 2);
                    mma16816(oacc[nt], ph, blf + h2 * 2);
                }
            }
        }
        __syncthreads();
    }

    // ---- epilogue -> pre hi-only, layout [b*C + d][h*64 + v] ----
    {
        const float il0 = 1.0f / l0;
        const float il1 = 1.0f / l1;
#pragma unroll
        for (int nt = 0; nt < 8; nt++) {
            const int col = h * 64 + nt * 8 + lr * 2;
            const long i0 = ((long)(b * C_ + d0 + r0)) * (H_ * V_) + col;
            const long i1 = ((long)(b * C_ + d0 + r0 + 8)) * (H_ * V_) + col;
            *reinterpret_cast<uint32_t*>(&pre_g[i0]) =
                packh2(oacc[nt][0] * il0, oacc[nt][1] * il0);
            *reinterpret_cast<uint32_t*>(&pre_g[i1]) =
                packh2(oacc[nt][2] * il1, oacc[nt][3] * il1);
        }
    }
}

// ---------------------------------------------------------------------------

extern "C" void kernel_launch(void* const* d_in, const int* in_sizes, int n_in,
                              void* d_out, int out_size)
{
    const float* kvinput = (const float*)d_in[0];
    const float* qinput  = (const float*)d_in[1];
    const float* wq      = (const float*)d_in[2];
    const float* wk      = (const float*)d_in[3];
    const float* wv      = (const float*)d_in[4];
    const float* wo      = (const float*)d_in[5];
    float* out = (float*)d_out;

    __half *xqh, *xkh;
    __half *wqh, *wql, *wkvh, *wkvl, *woh, *wol;
    __half *qh, *kvh, *kvl, *vth, *vtl, *prh;
    cudaGetSymbolAddress((void**)&xqh, s_xq_h);
    cudaGetSymbolAddress((void**)&xkh, s_xkv_h);
    cudaGetSymbolAddress((void**)&wqh, s_wqT_h);
    cudaGetSymbolAddress((void**)&wql, s_wqT_l);
    cudaGetSymbolAddress((void**)&wkvh, s_wkvT_h);
    cudaGetSymbolAddress((void**)&wkvl, s_wkvT_l);
    cudaGetSymbolAddress((void**)&woh, s_woT_h);
    cudaGetSymbolAddress((void**)&wol, s_woT_l);
    cudaGetSymbolAddress((void**)&qh,  s_q_h);
    cudaGetSymbolAddress((void**)&kvh, s_kv_h);
    cudaGetSymbolAddress((void**)&kvl, s_kv_l);
    cudaGetSymbolAddress((void**)&vth, s_vT_h);
    cudaGetSymbolAddress((void**)&vtl, s_vT_l);
    cudaGetSymbolAddress((void**)&prh, s_pre_h);

    cudaFuncSetAttribute(proj_kernel,
                         cudaFuncAttributeMaxDynamicSharedMemorySize, GEMM_SMEM3);
    cudaFuncSetAttribute(outproj_kernel,
                         cudaFuncAttributeMaxDynamicSharedMemorySize, GEMM_SMEM3);
    cudaFuncSetAttribute(attn_kernel,
                         cudaFuncAttributeMaxDynamicSharedMemorySize, AT_TOTAL);

    // launch 0: convert inputs to fp16 hi
    {
        int n4 = B_ * C_ * M_ / 4;
        cvt2_kernel<<<(2 * n4 + 255) / 256, 256>>>(qinput, kvinput, xqh, xkh, n4);
    }
    // launch 1: all weight transposes (fp16 hi/lo)
    {
        dim3 tb(32, 8);
        trans_all_kernel<<<4096, tb>>>(wq, wk, wv, wo,
                                       wqh, wql, wkvh, wkvl, woh, wol);
    }
    // launch 2: merged Q + KV projections (768 blocks)
    {
        dim3 pg(C_ / 128, 24, B_);
        proj_kernel<<<pg, 256, GEMM_SMEM3>>>(xqh, xkh, wqh, wql, wkvh, wkvl,
                                             qh, kvh, kvl);
    }
    // launch 3: V transpose
    {
        dim3 vg(C_ / 64, B_ * H_);
        vtrans_kernel<<<vg, 256>>>(kvh, kvl, vth, vtl);
    }
    // launch 4: attention
    {
        dim3 ag(C_ / 64, H_, B_);
        attn_kernel<<<ag, 128, AT_TOTAL>>>(qh, kvh, kvl, vth, vtl, prh);
    }
    // launch 5: output projection
    {
        dim3 og((B_ * C_) / 128, M_ / 128, 1);
        outproj_kernel<<<og, 256, GEMM_SMEM3>>>(prh, woh, wol, out);
    }
}

// round 9
// speedup vs baseline: 7.9068x; 1.6477x over previous
#include <cuda_runtime.h>
#include <cuda_fp16.h>
#include <cstdint>
#include <math.h>

#define B_ 2
#define C_ 2048
#define M_ 1024
#define H_ 16
#define K_ 64
#define V_ 64

// ------------------------- scratch (no cudaMalloc) -------------------------
__device__ __half s_xq_h [(size_t)B_ * C_ * M_];
__device__ __half s_xkv_h[(size_t)B_ * C_ * M_];

__device__ __half s_wqT_h [(size_t)H_ * K_ * M_];
__device__ __half s_wkvT_h[(size_t)H_ * 128 * M_];      // rows 0-63 K, 64-127 V
__device__ __half s_woT_h [(size_t)M_ * (H_ * V_)];

__device__ __half s_q_h [(size_t)B_ * H_ * C_ * K_];
__device__ __half s_kv_h[(size_t)B_ * H_ * 2 * C_ * 64];// [bh][0]=K,[bh][1]=V
__device__ __half s_vT_h[(size_t)B_ * H_ * V_ * C_];

__device__ __half s_pre_h[(size_t)B_ * C_ * (H_ * V_)];

// ------------------------------ helpers ------------------------------------
__device__ __forceinline__ uint32_t packh2(float x, float y) {
    __half2 h = __floats2half2_rn(x, y);
    return *reinterpret_cast<uint32_t*>(&h);
}

__device__ __forceinline__ void mma16816(float* c, const uint32_t* a,
                                         const uint32_t* b) {
    asm volatile(
        "mma.sync.aligned.m16n8k16.row.col.f32.f16.f16.f32 "
        "{%0,%1,%2,%3}, {%4,%5,%6,%7}, {%8,%9}, {%0,%1,%2,%3};\n"
        : "+f"(c[0]), "+f"(c[1]), "+f"(c[2]), "+f"(c[3])
        : "r"(a[0]), "r"(a[1]), "r"(a[2]), "r"(a[3]), "r"(b[0]), "r"(b[1]));
}

__device__ __forceinline__ void ldsm_x4(uint32_t* r, uint32_t addr) {
    asm volatile(
        "ldmatrix.sync.aligned.m8n8.x4.shared.b16 {%0,%1,%2,%3}, [%4];\n"
        : "=r"(r[0]), "=r"(r[1]), "=r"(r[2]), "=r"(r[3]) : "r"(addr));
}

__device__ __forceinline__ uint32_t smem_u32(const void* p) {
    uint32_t a;
    asm("{ .reg .u64 t; cvta.to.shared.u64 t, %1; cvt.u32.u64 %0, t; }"
        : "=r"(a) : "l"(p));
    return a;
}
#define CP_ASYNC16(dst, src) \
    asm volatile("cp.async.ca.shared.global [%0], [%1], 16;\n" \
                 :: "r"(dst), "l"(src) : "memory")
#define CP_COMMIT() asm volatile("cp.async.commit_group;\n" ::: "memory")
#define CP_WAIT0()  asm volatile("cp.async.wait_group 0;\n" ::: "memory")
#define CP_WAIT1()  asm volatile("cp.async.wait_group 1;\n" ::: "memory")

// --------------------------- pre-pass kernels ------------------------------
__global__ void cvt2_kernel(const float* __restrict__ inq,
                            const float* __restrict__ inkv,
                            __half* __restrict__ oq, __half* __restrict__ okv,
                            int n4each) {
    int i = blockIdx.x * blockDim.x + threadIdx.x;
    const float* in;
    __half* o;
    int idx;
    if (i < n4each) { in = inq; o = oq; idx = i; }
    else if (i < 2 * n4each) { in = inkv; o = okv; idx = i - n4each; }
    else return;
    float4 v = reinterpret_cast<const float4*>(in)[idx];
    reinterpret_cast<uint2*>(o)[idx] =
        make_uint2(packh2(v.x, v.y), packh2(v.z, v.w));
}

// all 4 weight transposes (fp16) in one launch; 4096 blocks
__global__ void trans_all_kernel(const float* __restrict__ wq,
                                 const float* __restrict__ wk,
                                 const float* __restrict__ wv,
                                 const float* __restrict__ wo,
                                 __half* __restrict__ wqh,
                                 __half* __restrict__ wkvh,
                                 __half* __restrict__ woh) {
    __shared__ float t[32][33];
    const int bid = blockIdx.x;
    const float* in;
    __half* oh;
    int R, Cdim, c0, r0;
    long ib, ob;
    if (bid < 3072) {
        const int m = bid >> 10;
        const int r = bid & 1023;
        const int hh = r >> 6;
        const int rem = r & 63;
        const int gy = rem >> 1, gx = rem & 1;
        R = M_; Cdim = K_;
        c0 = gx * 32; r0 = gy * 32;
        if (m == 0) {
            in = wq;  oh = wqh;
            ib = (long)hh * M_ * K_; ob = (long)hh * K_ * M_;
        } else if (m == 1) {
            in = wk;  oh = wkvh;
            ib = (long)hh * M_ * K_; ob = (long)hh * 128 * M_;
        } else {
            in = wv;  oh = wkvh + (size_t)64 * M_;
            ib = (long)hh * M_ * V_; ob = (long)hh * 128 * M_;
        }
    } else {
        const int r = bid - 3072;
        R = H_ * V_; Cdim = M_;
        c0 = (r & 31) * 32; r0 = (r >> 5) * 32;
        in = wo; oh = woh; ib = 0; ob = 0;
    }
    in += ib;
#pragma unroll
    for (int i = threadIdx.y; i < 32; i += 8)
        t[i][threadIdx.x] = in[(long)(r0 + i) * Cdim + c0 + threadIdx.x];
    __syncthreads();
#pragma unroll
    for (int i = threadIdx.y; i < 32; i += 8) {
        long idx = ob + (long)(c0 + i) * R + r0 + threadIdx.x;
        oh[idx] = __float2half_rn(t[threadIdx.x][i]);
    }
}

// V (in combined KV) [bh][1][c][v] -> VT [bh][v][c]
__global__ void vtrans_kernel(const __half* __restrict__ kvh,
                              __half* __restrict__ oth) {
    const int bh = blockIdx.y;
    const int c0 = blockIdx.x * 64;
    const long ib = ((long)bh * 2 + 1) * C_ * 64;
    const long ob = (long)bh * 64 * C_;
    __shared__ __half t[64][68];
    const int tid = threadIdx.x;
#pragma unroll
    for (int l = 0; l < 4; l++) {
        int e = tid + l * 256;
        int c = e >> 4, v4 = (e & 15) * 4;
        *reinterpret_cast<uint2*>(&t[c][v4]) =
            *reinterpret_cast<const uint2*>(&kvh[ib + (long)(c0 + c) * 64 + v4]);
    }
    __syncthreads();
#pragma unroll
    for (int l = 0; l < 4; l++) {
        int e = tid + l * 256;
        int v = e >> 4, c4 = (e & 15) * 4;
        __half tmp[4] = {t[c4][v], t[c4 + 1][v], t[c4 + 2][v], t[c4 + 3][v]};
        *reinterpret_cast<uint2*>(&oth[ob + (long)v * C_ + c0 + c4]) =
            *reinterpret_cast<const uint2*>(tmp);
    }
}

// ---------------------------------------------------------------------------
// fp16 GEMM core: O = A * W, 128x128 tile, inner = 1024, K-chunk 32,
// 3-stage cp.async pipeline, one syncthreads per chunk, ldmatrix.
// ---------------------------------------------------------------------------
#define GS 40
#define PARR 10240                   // 128 * GS * 2B
#define PSTG (2 * PARR)              // A + W per stage = 20480
#define GEMM_SMEM3 (3 * PSTG)        // 61440

#define GEMM_CORE(A_, Wh_)                                                   \
    const int tid = threadIdx.x;                                             \
    const int wid = tid >> 5, lane = tid & 31;                               \
    const int lq = lane >> 2, lr = lane & 3;                                 \
    const int wm = wid >> 1, wn = wid & 1;                                   \
    const int lane15 = lane & 15;                                            \
    const int aK = (lane >> 4) << 3;                                         \
    const int bN = ((lane >> 4) << 3) + (lane & 7);                          \
    const int bK = ((lane >> 3) & 1) << 3;                                   \
    const int r_a = tid >> 2, q_a = tid & 3;                                 \
    const int r_b = (tid + 256) >> 2, q_b = (tid + 256) & 3;                 \
    float acc[2][8][4];                                                      \
    _Pragma("unroll") for (int a = 0; a < 2; a++)                            \
    _Pragma("unroll") for (int b = 0; b < 8; b++)                            \
    _Pragma("unroll") for (int c = 0; c < 4; c++) acc[a][b][c] = 0.0f;       \
    auto issue = [&](int ck, int s) {                                        \
        const int m0 = ck << 5;                                              \
        const uint32_t base = sb + s * PSTG;                                 \
        CP_ASYNC16(base + r_a * 80 + q_a * 16,                               \
                   A_ + (long)(row0 + r_a) * 1024 + m0 + q_a * 8);           \
        CP_ASYNC16(base + r_b * 80 + q_b * 16,                               \
                   A_ + (long)(row0 + r_b) * 1024 + m0 + q_b * 8);           \
        CP_ASYNC16(base + PARR + r_a * 80 + q_a * 16,                        \
                   Wh_ + (long)r_a * 1024 + m0 + q_a * 8);                   \
        CP_ASYNC16(base + PARR + r_b * 80 + q_b * 16,                        \
                   Wh_ + (long)r_b * 1024 + m0 + q_b * 8);                   \
    };                                                                       \
    issue(0, 0); CP_COMMIT();                                                \
    issue(1, 1); CP_COMMIT();                                                \
    for (int it = 0; it < 32; it++) {                                        \
        if (it < 31) { CP_WAIT1(); } else { CP_WAIT0(); }                    \
        __syncthreads();                                                     \
        if (it + 2 < 32) { issue(it + 2, (it + 2) % 3); CP_COMMIT(); }       \
        const uint32_t cbase = sb + (it % 3) * PSTG;                         \
        _Pragma("unroll")                                                    \
        for (int ks = 0; ks < 2; ks++) {                                     \
            const int kA = ks * 16 + aK;                                     \
            const int kB = ks * 16 + bK;                                     \
            uint32_t ah[2][4];                                               \
            _Pragma("unroll")                                                \
            for (int mt = 0; mt < 2; mt++) {                                 \
                const uint32_t off =                                         \
                    (uint32_t)((wm * 32 + mt * 16 + lane15) * GS + kA) * 2;  \
                ldsm_x4(ah[mt], cbase + off);                                \
            }                                                                \
            _Pragma("unroll")                                                \
            for (int ntp = 0; ntp < 4; ntp++) {                              \
                const uint32_t off =                                         \
                    (uint32_t)((wn * 64 + ntp * 16 + bN) * GS + kB) * 2;     \
                uint32_t bhf[4];                                             \
                ldsm_x4(bhf, cbase + PARR + off);                            \
                _Pragma("unroll")                                            \
                for (int h2 = 0; h2 < 2; h2++) {                             \
                    const int nt = ntp * 2 + h2;                             \
                    _Pragma("unroll")                                        \
                    for (int mt = 0; mt < 2; mt++)                           \
                        mma16816(acc[mt][nt], ah[mt], bhf + h2 * 2);         \
                }                                                            \
            }                                                                \
        }                                                                    \
    }

// Merged Q + KV projections: grid (16, 24, 2). y<8: Q (2 heads/tile);
// y>=8: KV head y-8 (K cols 0-63, V cols 64-127).
__global__ void __launch_bounds__(256, 2)
proj_kernel(const __half* __restrict__ xq, const __half* __restrict__ xkv,
            const __half* __restrict__ wqh, const __half* __restrict__ wkvh,
            __half* __restrict__ q_out, __half* __restrict__ kv_h)
{
    const int z = blockIdx.z, y = blockIdx.y;
    const int row0 = blockIdx.x * 128;
    const long hs = (long)C_ * 64;
    const bool isQ = (y < 8);
    const __half *A, *Wh;
    __half* O;
    long oOff;
    if (isQ) {
        A  = xq + (long)z * C_ * M_;
        Wh = wqh + (long)y * 128 * M_;
        O  = q_out;
        oOff = (long)z * H_ * hs + (long)y * 2 * hs;
    } else {
        const int yk = y - 8;
        A  = xkv + (long)z * C_ * M_;
        Wh = wkvh + (long)yk * 128 * M_;
        O  = kv_h;
        oOff = (long)z * H_ * 2 * hs + (long)yk * 2 * hs;
    }

    extern __shared__ char smem[];
    const uint32_t sb = smem_u32(smem);
    GEMM_CORE(A, Wh)

#pragma unroll
    for (int mt = 0; mt < 2; mt++) {
        const int row_lo = row0 + wm * 32 + mt * 16 + lq;
        const int row_hi = row_lo + 8;
#pragma unroll
        for (int nt = 0; nt < 8; nt++) {
            const int col = wn * 64 + nt * 8 + lr * 2;
            const float* c = acc[mt][nt];
            const long hb = oOff + (long)(col >> 6) * hs + (col & 63);
            *reinterpret_cast<uint32_t*>(&O[hb + (long)row_lo * 64]) =
                packh2(c[0], c[1]);
            *reinterpret_cast<uint32_t*>(&O[hb + (long)row_hi * 64]) =
                packh2(c[2], c[3]);
        }
    }
}

// Output projection: out[4096][1024] = pre @ woT. grid (32, 8).
__global__ void __launch_bounds__(256, 2)
outproj_kernel(const __half* __restrict__ pre,
               const __half* __restrict__ woh,
               float* __restrict__ out)
{
    const int row0 = blockIdx.x * 128;
    const int col0 = blockIdx.y * 128;
    const __half* A  = pre;
    const __half* Wh = woh + (long)col0 * M_;

    extern __shared__ char smem[];
    const uint32_t sb = smem_u32(smem);
    GEMM_CORE(A, Wh)

#pragma unroll
    for (int mt = 0; mt < 2; mt++) {
        const int row_lo = row0 + wm * 32 + mt * 16 + lq;
        const int row_hi = row_lo + 8;
#pragma unroll
        for (int nt = 0; nt < 8; nt++) {
            const int col = col0 + wn * 64 + nt * 8 + lr * 2;
            const float* c = acc[mt][nt];
            *reinterpret_cast<float2*>(&out[(long)row_lo * M_ + col]) =
                make_float2(c[0], c[1]);
            *reinterpret_cast<float2*>(&out[(long)row_hi * M_ + col]) =
                make_float2(c[2], c[3]);
        }
    }
}

// ---------------------------------------------------------------------------
// Flash attention, pure fp16 operands, register softmax, mask-aware tile
// skipping, cp.async double-buffered K/V, ldmatrix.
// ---------------------------------------------------------------------------
#define ATA  9216                    // one 64x72 fp16 array
#define AT_KH 0                      // 2 stages
#define AT_VH (2 * ATA)              // 2 stages
#define AT_QH (4 * ATA)
#define AT_TOTAL (5 * ATA)           // 46080

__global__ void __launch_bounds__(128, 3)
attn_kernel(const __half* __restrict__ qh_g,
            const __half* __restrict__ kvh_g,
            const __half* __restrict__ vth_g,
            __half* __restrict__ pre_g)
{
    const int b = blockIdx.z, h = blockIdx.y;
    const int qb = blockIdx.x;
    const int d0 = qb * 64;
    const int bh = b * H_ + h;
    const int ntiles = C_ / 64;
    const int tstart = (qb == ntiles - 1) ? 0 : qb;

    extern __shared__ char smem[];
    const uint32_t sb = smem_u32(smem);
    __half* sQh = (__half*)(smem + AT_QH);

    const int tid = threadIdx.x;
    const int wid = tid >> 5, lane = tid & 31;
    const int lq = lane >> 2, lr = lane & 3;
    const int dtile = wid * 16;
    const int r0 = dtile + lq;

    const int lane15 = lane & 15;
    const int aK = (lane >> 4) << 3;
    const int bN = ((lane >> 4) << 3) + (lane & 7);
    const int bK = ((lane >> 3) & 1) << 3;

    const __half* Kh_g = kvh_g + ((long)bh * 2) * C_ * 64;
    const __half* Vh_g = vth_g + (long)bh * 64 * C_;

    // Q tile: 64 rows x 64 cols = 512 x 16B, 4 per thread
#pragma unroll
    for (int l = 0; l < 4; l++) {
        int e = tid + l * 128;
        int r = e >> 3, q = (e & 7) * 8;
        long g = ((long)bh * C_ + d0 + r) * 64 + q;
        *reinterpret_cast<uint4*>(&sQh[r * 72 + q]) =
            *reinterpret_cast<const uint4*>(&qh_g[g]);
    }

    auto issue = [&](int t, int s) {
        const int c0 = t * 64;
        const uint32_t kh_d = sb + AT_KH + s * ATA;
        const uint32_t vh_d = sb + AT_VH + s * ATA;
#pragma unroll
        for (int j = 0; j < 4; j++) {
            const int e = tid + j * 128;
            const int r = e >> 3, q = e & 7;
            CP_ASYNC16(kh_d + r * 144 + q * 16, Kh_g + (long)(c0 + r) * 64 + q * 8);
            CP_ASYNC16(vh_d + r * 144 + q * 16, Vh_g + (long)r * C_ + c0 + q * 8);
        }
    };

    issue(tstart, tstart & 1);
    CP_COMMIT();
    __syncthreads();

    // persistent Q fragments
    uint32_t qh[4][4];
#pragma unroll
    for (int ks = 0; ks < 4; ks++) {
        const uint32_t off = (uint32_t)((dtile + lane15) * 72 + ks * 16 + aK) * 2;
        ldsm_x4(qh[ks], sb + AT_QH + off);
    }

    float oacc[8][4];
#pragma unroll
    for (int i = 0; i < 8; i++)
#pragma unroll
        for (int j = 0; j < 4; j++) oacc[i][j] = 0.0f;
    float m0 = -1e30f, m1 = -1e30f, l0 = 0.0f, l1 = 0.0f;

    for (int t = tstart; t < ntiles; t++) {
        if (t + 1 < ntiles) {
            issue(t + 1, (t + 1) & 1);
            CP_COMMIT();
            CP_WAIT1();
        } else {
            CP_WAIT0();
        }
        __syncthreads();

        const int s = t & 1;
        const int c0 = t * 64;
        const uint32_t sKh_b = sb + AT_KH + s * ATA;
        const uint32_t sVh_b = sb + AT_VH + s * ATA;

        // ---- S = Q @ K^T ----
        float sacc[8][4];
#pragma unroll
        for (int i = 0; i < 8; i++)
#pragma unroll
            for (int j = 0; j < 4; j++) sacc[i][j] = 0.0f;
#pragma unroll
        for (int ks = 0; ks < 4; ks++) {
            const int kB = ks * 16 + bK;
#pragma unroll
            for (int ntp = 0; ntp < 4; ntp++) {
                const uint32_t off = (uint32_t)((ntp * 16 + bN) * 72 + kB) * 2;
                uint32_t bhf[4];
                ldsm_x4(bhf, sKh_b + off);
#pragma unroll
                for (int h2 = 0; h2 < 2; h2++)
                    mma16816(sacc[ntp * 2 + h2], qh[ks], bhf + h2 * 2);
            }
        }

        // ---- mask + scale in registers ----
        {
            const int dg0 = d0 + r0, dg1 = d0 + r0 + 8;
#pragma unroll
            for (int nt = 0; nt < 8; nt++) {
                const int cg = c0 + nt * 8 + lr * 2;
                if (cg     <= dg0) sacc[nt][0] -= 100.0f;
                if (cg + 1 <= dg0) sacc[nt][1] -= 100.0f;
                if (cg     <= dg1) sacc[nt][2] -= 100.0f;
                if (cg + 1 <= dg1) sacc[nt][3] -= 100.0f;
#pragma unroll
                for (int j = 0; j < 4; j++) sacc[nt][j] *= 0.125f;
            }
        }

        // ---- register softmax (quad shuffles) ----
        {
            float mt0 = sacc[0][0], mt1 = sacc[0][2];
#pragma unroll
            for (int nt = 0; nt < 8; nt++) {
                mt0 = fmaxf(mt0, fmaxf(sacc[nt][0], sacc[nt][1]));
                mt1 = fmaxf(mt1, fmaxf(sacc[nt][2], sacc[nt][3]));
            }
            mt0 = fmaxf(mt0, __shfl_xor_sync(0xffffffff, mt0, 1));
            mt0 = fmaxf(mt0, __shfl_xor_sync(0xffffffff, mt0, 2));
            mt1 = fmaxf(mt1, __shfl_xor_sync(0xffffffff, mt1, 1));
            mt1 = fmaxf(mt1, __shfl_xor_sync(0xffffffff, mt1, 2));
            const float mn0 = fmaxf(m0, mt0);
            const float mn1 = fmaxf(m1, mt1);
            const float a0 = __expf(m0 - mn0);
            const float a1 = __expf(m1 - mn1);
            float s0 = 0.0f, s1 = 0.0f;
#pragma unroll
            for (int nt = 0; nt < 8; nt++) {
                sacc[nt][0] = __expf(sacc[nt][0] - mn0); s0 += sacc[nt][0];
                sacc[nt][1] = __expf(sacc[nt][1] - mn0); s0 += sacc[nt][1];
                sacc[nt][2] = __expf(sacc[nt][2] - mn1); s1 += sacc[nt][2];
                sacc[nt][3] = __expf(sacc[nt][3] - mn1); s1 += sacc[nt][3];
            }
            s0 += __shfl_xor_sync(0xffffffff, s0, 1);
            s0 += __shfl_xor_sync(0xffffffff, s0, 2);
            s1 += __shfl_xor_sync(0xffffffff, s1, 1);
            s1 += __shfl_xor_sync(0xffffffff, s1, 2);
            l0 = l0 * a0 + s0;
            l1 = l1 * a1 + s1;
            m0 = mn0; m1 = mn1;
#pragma unroll
            for (int nt = 0; nt < 8; nt++) {
                oacc[nt][0] *= a0; oacc[nt][1] *= a0;
                oacc[nt][2] *= a1; oacc[nt][3] *= a1;
            }
        }

        // ---- O += P @ V ----
#pragma unroll
        for (int ks = 0; ks < 4; ks++) {
            uint32_t ph[4];
            ph[0] = packh2(sacc[2 * ks][0],     sacc[2 * ks][1]);
            ph[1] = packh2(sacc[2 * ks][2],     sacc[2 * ks][3]);
            ph[2] = packh2(sacc[2 * ks + 1][0], sacc[2 * ks + 1][1]);
            ph[3] = packh2(sacc[2 * ks + 1][2], sacc[2 * ks + 1][3]);
            const int kB = ks * 16 + bK;
#pragma unroll
            for (int ntp = 0; ntp < 4; ntp++) {
                const uint32_t off = (uint32_t)((ntp * 16 + bN) * 72 + kB) * 2;
                uint32_t bhf[4];
                ldsm_x4(bhf, sVh_b + off);
#pragma unroll
                for (int h2 = 0; h2 < 2; h2++)
                    mma16816(oacc[ntp * 2 + h2], ph, bhf + h2 * 2);
            }
        }
        __syncthreads();
    }

    // ---- epilogue -> pre, layout [b*C + d][h*64 + v] ----
    {
        const float il0 = 1.0f / l0;
        const float il1 = 1.0f / l1;
#pragma unroll
        for (int nt = 0; nt < 8; nt++) {
            const int col = h * 64 + nt * 8 + lr * 2;
            const long i0 = ((long)(b * C_ + d0 + r0)) * (H_ * V_) + col;
            const long i1 = ((long)(b * C_ + d0 + r0 + 8)) * (H_ * V_) + col;
            *reinterpret_cast<uint32_t*>(&pre_g[i0]) =
                packh2(oacc[nt][0] * il0, oacc[nt][1] * il0);
            *reinterpret_cast<uint32_t*>(&pre_g[i1]) =
                packh2(oacc[nt][2] * il1, oacc[nt][3] * il1);
        }
    }
}

// ---------------------------------------------------------------------------

extern "C" void kernel_launch(void* const* d_in, const int* in_sizes, int n_in,
                              void* d_out, int out_size)
{
    const float* kvinput = (const float*)d_in[0];
    const float* qinput  = (const float*)d_in[1];
    const float* wq      = (const float*)d_in[2];
    const float* wk      = (const float*)d_in[3];
    const float* wv      = (const float*)d_in[4];
    const float* wo      = (const float*)d_in[5];
    float* out = (float*)d_out;

    __half *xqh, *xkh, *wqh, *wkvh, *woh;
    __half *qh, *kvh, *vth, *prh;
    cudaGetSymbolAddress((void**)&xqh, s_xq_h);
    cudaGetSymbolAddress((void**)&xkh, s_xkv_h);
    cudaGetSymbolAddress((void**)&wqh, s_wqT_h);
    cudaGetSymbolAddress((void**)&wkvh, s_wkvT_h);
    cudaGetSymbolAddress((void**)&woh, s_woT_h);
    cudaGetSymbolAddress((void**)&qh,  s_q_h);
    cudaGetSymbolAddress((void**)&kvh, s_kv_h);
    cudaGetSymbolAddress((void**)&vth, s_vT_h);
    cudaGetSymbolAddress((void**)&prh, s_pre_h);

    cudaFuncSetAttribute(proj_kernel,
                         cudaFuncAttributeMaxDynamicSharedMemorySize, GEMM_SMEM3);
    cudaFuncSetAttribute(outproj_kernel,
                         cudaFuncAttributeMaxDynamicSharedMemorySize, GEMM_SMEM3);
    cudaFuncSetAttribute(attn_kernel,
                         cudaFuncAttributeMaxDynamicSharedMemorySize, AT_TOTAL);

    // launch 0: convert inputs to fp16
    {
        int n4 = B_ * C_ * M_ / 4;
        cvt2_kernel<<<(2 * n4 + 255) / 256, 256>>>(qinput, kvinput, xqh, xkh, n4);
    }
    // launch 1: all weight transposes
    {
        dim3 tb(32, 8);
        trans_all_kernel<<<4096, tb>>>(wq, wk, wv, wo, wqh, wkvh, woh);
    }
    // launch 2: merged Q + KV projections
    {
        dim3 pg(C_ / 128, 24, B_);
        proj_kernel<<<pg, 256, GEMM_SMEM3>>>(xqh, xkh, wqh, wkvh, qh, kvh);
    }
    // launch 3: V transpose
    {
        dim3 vg(C_ / 64, B_ * H_);
        vtrans_kernel<<<vg, 256>>>(kvh, vth);
    }
    // launch 4: attention
    {
        dim3 ag(C_ / 64, H_, B_);
        attn_kernel<<<ag, 128, AT_TOTAL>>>(qh, kvh, vth, prh);
    }
    // launch 5: output projection
    {
        dim3 og((B_ * C_) / 128, M_ / 128, 1);
        outproj_kernel<<<og, 256, GEMM_SMEM3>>>(prh, woh, out);
    }
}

// round 10
// speedup vs baseline: 8.7405x; 1.1054x over previous
#include <cuda_runtime.h>
#include <cuda_fp16.h>
#include <cstdint>
#include <math.h>

#define B_ 2
#define C_ 2048
#define M_ 1024
#define H_ 16
#define K_ 64
#define V_ 64

// ------------------------- scratch (no cudaMalloc) -------------------------
__device__ __half s_xq_h [(size_t)B_ * C_ * M_];
__device__ __half s_xkv_h[(size_t)B_ * C_ * M_];

__device__ __half s_wqT_h [(size_t)H_ * K_ * M_];
__device__ __half s_wkvT_h[(size_t)H_ * 128 * M_];      // rows 0-63 K, 64-127 V
__device__ __half s_woT_h [(size_t)M_ * (H_ * V_)];

__device__ __half s_q_h [(size_t)B_ * H_ * C_ * K_];
__device__ __half s_kv_h[(size_t)B_ * H_ * 2 * C_ * 64];// [bh][0]=K,[bh][1]=V
__device__ __half s_vT_h[(size_t)B_ * H_ * V_ * C_];

__device__ __half s_pre_h[(size_t)B_ * C_ * (H_ * V_)];

// ------------------------------ helpers ------------------------------------
__device__ __forceinline__ uint32_t packh2(float x, float y) {
    __half2 h = __floats2half2_rn(x, y);
    return *reinterpret_cast<uint32_t*>(&h);
}

__device__ __forceinline__ void mma16816(float* c, const uint32_t* a,
                                         const uint32_t* b) {
    asm volatile(
        "mma.sync.aligned.m16n8k16.row.col.f32.f16.f16.f32 "
        "{%0,%1,%2,%3}, {%4,%5,%6,%7}, {%8,%9}, {%0,%1,%2,%3};\n"
        : "+f"(c[0]), "+f"(c[1]), "+f"(c[2]), "+f"(c[3])
        : "r"(a[0]), "r"(a[1]), "r"(a[2]), "r"(a[3]), "r"(b[0]), "r"(b[1]));
}

__device__ __forceinline__ void ldsm_x4(uint32_t* r, uint32_t addr) {
    asm volatile(
        "ldmatrix.sync.aligned.m8n8.x4.shared.b16 {%0,%1,%2,%3}, [%4];\n"
        : "=r"(r[0]), "=r"(r[1]), "=r"(r[2]), "=r"(r[3]) : "r"(addr));
}

__device__ __forceinline__ uint32_t smem_u32(const void* p) {
    uint32_t a;
    asm("{ .reg .u64 t; cvta.to.shared.u64 t, %1; cvt.u32.u64 %0, t; }"
        : "=r"(a) : "l"(p));
    return a;
}
#define CP_ASYNC16(dst, src) \
    asm volatile("cp.async.ca.shared.global [%0], [%1], 16;\n" \
                 :: "r"(dst), "l"(src) : "memory")
#define CP_COMMIT() asm volatile("cp.async.commit_group;\n" ::: "memory")
#define CP_WAIT0()  asm volatile("cp.async.wait_group 0;\n" ::: "memory")
#define CP_WAIT1()  asm volatile("cp.async.wait_group 1;\n" ::: "memory")

// --------------------------- pre-pass kernels ------------------------------
__global__ void cvt2_kernel(const float* __restrict__ inq,
                            const float* __restrict__ inkv,
                            __half* __restrict__ oq, __half* __restrict__ okv,
                            int n4each) {
    int i = blockIdx.x * blockDim.x + threadIdx.x;
    const float* in;
    __half* o;
    int idx;
    if (i < n4each) { in = inq; o = oq; idx = i; }
    else if (i < 2 * n4each) { in = inkv; o = okv; idx = i - n4each; }
    else return;
    float4 v = reinterpret_cast<const float4*>(in)[idx];
    reinterpret_cast<uint2*>(o)[idx] =
        make_uint2(packh2(v.x, v.y), packh2(v.z, v.w));
}

// all 4 weight transposes (fp16) in one launch; 4096 blocks
__global__ void trans_all_kernel(const float* __restrict__ wq,
                                 const float* __restrict__ wk,
                                 const float* __restrict__ wv,
                                 const float* __restrict__ wo,
                                 __half* __restrict__ wqh,
                                 __half* __restrict__ wkvh,
                                 __half* __restrict__ woh) {
    __shared__ float t[32][33];
    const int bid = blockIdx.x;
    const float* in;
    __half* oh;
    int R, Cdim, c0, r0;
    long ib, ob;
    if (bid < 3072) {
        const int m = bid >> 10;
        const int r = bid & 1023;
        const int hh = r >> 6;
        const int rem = r & 63;
        const int gy = rem >> 1, gx = rem & 1;
        R = M_; Cdim = K_;
        c0 = gx * 32; r0 = gy * 32;
        if (m == 0) {
            in = wq;  oh = wqh;
            ib = (long)hh * M_ * K_; ob = (long)hh * K_ * M_;
        } else if (m == 1) {
            in = wk;  oh = wkvh;
            ib = (long)hh * M_ * K_; ob = (long)hh * 128 * M_;
        } else {
            in = wv;  oh = wkvh + (size_t)64 * M_;
            ib = (long)hh * M_ * V_; ob = (long)hh * 128 * M_;
        }
    } else {
        const int r = bid - 3072;
        R = H_ * V_; Cdim = M_;
        c0 = (r & 31) * 32; r0 = (r >> 5) * 32;
        in = wo; oh = woh; ib = 0; ob = 0;
    }
    in += ib;
#pragma unroll
    for (int i = threadIdx.y; i < 32; i += 8)
        t[i][threadIdx.x] = in[(long)(r0 + i) * Cdim + c0 + threadIdx.x];
    __syncthreads();
#pragma unroll
    for (int i = threadIdx.y; i < 32; i += 8) {
        long idx = ob + (long)(c0 + i) * R + r0 + threadIdx.x;
        oh[idx] = __float2half_rn(t[threadIdx.x][i]);
    }
}

// V (in combined KV) [bh][1][c][v] -> VT [bh][v][c]
__global__ void vtrans_kernel(const __half* __restrict__ kvh,
                              __half* __restrict__ oth) {
    const int bh = blockIdx.y;
    const int c0 = blockIdx.x * 64;
    const long ib = ((long)bh * 2 + 1) * C_ * 64;
    const long ob = (long)bh * 64 * C_;
    __shared__ __half t[64][68];
    const int tid = threadIdx.x;
#pragma unroll
    for (int l = 0; l < 4; l++) {
        int e = tid + l * 256;
        int c = e >> 4, v4 = (e & 15) * 4;
        *reinterpret_cast<uint2*>(&t[c][v4]) =
            *reinterpret_cast<const uint2*>(&kvh[ib + (long)(c0 + c) * 64 + v4]);
    }
    __syncthreads();
#pragma unroll
    for (int l = 0; l < 4; l++) {
        int e = tid + l * 256;
        int v = e >> 4, c4 = (e & 15) * 4;
        __half tmp[4] = {t[c4][v], t[c4 + 1][v], t[c4 + 2][v], t[c4 + 3][v]};
        *reinterpret_cast<uint2*>(&oth[ob + (long)v * C_ + c0 + c4]) =
            *reinterpret_cast<const uint2*>(tmp);
    }
}

// ---------------------------------------------------------------------------
// fp16 GEMM core: O = A * W, 128x128 block tile, 128 threads, 4 warps of
// 64x64 each (4x B-fragment reuse -> smem traffic 125B/MMA, MMA-bound).
// inner = 1024, K-chunk 32, 3-stage cp.async pipeline, ldmatrix.
// ---------------------------------------------------------------------------
#define GS 40
#define PARR 10240                   // 128 * GS * 2B
#define PSTG (2 * PARR)              // A + W per stage = 20480
#define GEMM_SMEM3 (3 * PSTG)        // 61440

#define GEMM_CORE(A_, Wh_)                                                   \
    const int tid = threadIdx.x;                                             \
    const int wid = tid >> 5, lane = tid & 31;                               \
    const int lq = lane >> 2, lr = lane & 3;                                 \
    const int wm = wid >> 1, wn = wid & 1;                                   \
    const int lane15 = lane & 15;                                            \
    const int aK = (lane >> 4) << 3;                                         \
    const int bN = ((lane >> 4) << 3) + (lane & 7);                          \
    const int bK = ((lane >> 3) & 1) << 3;                                   \
    float acc[4][8][4];                                                      \
    _Pragma("unroll") for (int a = 0; a < 4; a++)                            \
    _Pragma("unroll") for (int b = 0; b < 8; b++)                            \
    _Pragma("unroll") for (int c = 0; c < 4; c++) acc[a][b][c] = 0.0f;       \
    auto issue = [&](int ck, int s) {                                        \
        const int m0 = ck << 5;                                              \
        const uint32_t base = sb + s * PSTG;                                 \
        _Pragma("unroll")                                                    \
        for (int l = 0; l < 4; l++) {                                        \
            const int e = tid + l * 128;                                     \
            const int r = e >> 2, q = e & 3;                                 \
            CP_ASYNC16(base + r * 80 + q * 16,                               \
                       A_ + (long)r * 1024 + m0 + q * 8);                    \
            CP_ASYNC16(base + PARR + r * 80 + q * 16,                        \
                       Wh_ + (long)r * 1024 + m0 + q * 8);                   \
        }                                                                    \
    };                                                                       \
    issue(0, 0); CP_COMMIT();                                                \
    issue(1, 1); CP_COMMIT();                                                \
    for (int it = 0; it < 32; it++) {                                        \
        if (it < 31) { CP_WAIT1(); } else { CP_WAIT0(); }                    \
        __syncthreads();                                                     \
        if (it + 2 < 32) { issue(it + 2, (it + 2) % 3); CP_COMMIT(); }       \
        const uint32_t cbase = sb + (it % 3) * PSTG;                         \
        _Pragma("unroll")                                                    \
        for (int ks = 0; ks < 2; ks++) {                                     \
            const int kA = ks * 16 + aK;                                     \
            const int kB = ks * 16 + bK;                                     \
            uint32_t ah[4][4];                                               \
            _Pragma("unroll")                                                \
            for (int mt = 0; mt < 4; mt++) {                                 \
                const uint32_t off =                                         \
                    (uint32_t)((wm * 64 + mt * 16 + lane15) * GS + kA) * 2;  \
                ldsm_x4(ah[mt], cbase + off);                                \
            }                                                                \
            _Pragma("unroll")                                                \
            for (int ntp = 0; ntp < 4; ntp++) {                              \
                const uint32_t off =                                         \
                    (uint32_t)((wn * 64 + ntp * 16 + bN) * GS + kB) * 2;     \
                uint32_t bhf[4];                                             \
                ldsm_x4(bhf, cbase + PARR + off);                            \
                _Pragma("unroll")                                            \
                for (int h2 = 0; h2 < 2; h2++) {                             \
                    const int nt = ntp * 2 + h2;                             \
                    _Pragma("unroll")                                        \
                    for (int mt = 0; mt < 4; mt++)                           \
                        mma16816(acc[mt][nt], ah[mt], bhf + h2 * 2);         \
                }                                                            \
            }                                                                \
        }                                                                    \
    }

// Merged Q + KV projections: grid (16, 24, 2). y<8: Q (2 heads/tile);
// y>=8: KV head y-8 (K cols 0-63, V cols 64-127). 128 threads.
__global__ void __launch_bounds__(128, 2)
proj_kernel(const __half* __restrict__ xq, const __half* __restrict__ xkv,
            const __half* __restrict__ wqh, const __half* __restrict__ wkvh,
            __half* __restrict__ q_out, __half* __restrict__ kv_h)
{
    const int z = blockIdx.z, y = blockIdx.y;
    const int row0 = blockIdx.x * 128;
    const long hs = (long)C_ * 64;
    const bool isQ = (y < 8);
    const __half *A, *Wh;
    __half* O;
    long oOff;
    if (isQ) {
        A  = xq + (long)z * C_ * M_ + (long)row0 * M_;
        Wh = wqh + (long)y * 128 * M_;
        O  = q_out;
        oOff = (long)z * H_ * hs + (long)y * 2 * hs;
    } else {
        const int yk = y - 8;
        A  = xkv + (long)z * C_ * M_ + (long)row0 * M_;
        Wh = wkvh + (long)yk * 128 * M_;
        O  = kv_h;
        oOff = (long)z * H_ * 2 * hs + (long)yk * 2 * hs;
    }

    extern __shared__ char smem[];
    const uint32_t sb = smem_u32(smem);
    GEMM_CORE(A, Wh)

#pragma unroll
    for (int mt = 0; mt < 4; mt++) {
        const int row_lo = row0 + wm * 64 + mt * 16 + lq;
        const int row_hi = row_lo + 8;
#pragma unroll
        for (int nt = 0; nt < 8; nt++) {
            const int col = wn * 64 + nt * 8 + lr * 2;
            const float* c = acc[mt][nt];
            const long hb = oOff + (long)(col >> 6) * hs + (col & 63);
            *reinterpret_cast<uint32_t*>(&O[hb + (long)row_lo * 64]) =
                packh2(c[0], c[1]);
            *reinterpret_cast<uint32_t*>(&O[hb + (long)row_hi * 64]) =
                packh2(c[2], c[3]);
        }
    }
}

// Output projection: out[4096][1024] = pre @ woT. grid (32, 8). 128 threads.
__global__ void __launch_bounds__(128, 2)
outproj_kernel(const __half* __restrict__ pre,
               const __half* __restrict__ woh,
               float* __restrict__ out)
{
    const int row0 = blockIdx.x * 128;
    const int col0 = blockIdx.y * 128;
    const __half* A  = pre + (long)row0 * M_;
    const __half* Wh = woh + (long)col0 * M_;

    extern __shared__ char smem[];
    const uint32_t sb = smem_u32(smem);
    GEMM_CORE(A, Wh)

#pragma unroll
    for (int mt = 0; mt < 4; mt++) {
        const int row_lo = row0 + wm * 64 + mt * 16 + lq;
        const int row_hi = row_lo + 8;
#pragma unroll
        for (int nt = 0; nt < 8; nt++) {
            const int col = col0 + wn * 64 + nt * 8 + lr * 2;
            const float* c = acc[mt][nt];
            *reinterpret_cast<float2*>(&out[(long)row_lo * M_ + col]) =
                make_float2(c[0], c[1]);
            *reinterpret_cast<float2*>(&out[(long)row_hi * M_ + col]) =
                make_float2(c[2], c[3]);
        }
    }
}

// ---------------------------------------------------------------------------
// Flash attention, pure fp16 operands, register softmax, mask-aware tile
// skipping, cp.async double-buffered K/V, ldmatrix. (unchanged from R9)
// ---------------------------------------------------------------------------
#define ATA  9216                    // one 64x72 fp16 array
#define AT_KH 0                      // 2 stages
#define AT_VH (2 * ATA)              // 2 stages
#define AT_QH (4 * ATA)
#define AT_TOTAL (5 * ATA)           // 46080

__global__ void __launch_bounds__(128, 3)
attn_kernel(const __half* __restrict__ qh_g,
            const __half* __restrict__ kvh_g,
            const __half* __restrict__ vth_g,
            __half* __restrict__ pre_g)
{
    const int b = blockIdx.z, h = blockIdx.y;
    const int qb = blockIdx.x;
    const int d0 = qb * 64;
    const int bh = b * H_ + h;
    const int ntiles = C_ / 64;
    const int tstart = (qb == ntiles - 1) ? 0 : qb;

    extern __shared__ char smem[];
    const uint32_t sb = smem_u32(smem);
    __half* sQh = (__half*)(smem + AT_QH);

    const int tid = threadIdx.x;
    const int wid = tid >> 5, lane = tid & 31;
    const int lq = lane >> 2, lr = lane & 3;
    const int dtile = wid * 16;
    const int r0 = dtile + lq;

    const int lane15 = lane & 15;
    const int aK = (lane >> 4) << 3;
    const int bN = ((lane >> 4) << 3) + (lane & 7);
    const int bK = ((lane >> 3) & 1) << 3;

    const __half* Kh_g = kvh_g + ((long)bh * 2) * C_ * 64;
    const __half* Vh_g = vth_g + (long)bh * 64 * C_;

#pragma unroll
    for (int l = 0; l < 4; l++) {
        int e = tid + l * 128;
        int r = e >> 3, q = (e & 7) * 8;
        long g = ((long)bh * C_ + d0 + r) * 64 + q;
        *reinterpret_cast<uint4*>(&sQh[r * 72 + q]) =
            *reinterpret_cast<const uint4*>(&qh_g[g]);
    }

    auto issue = [&](int t, int s) {
        const int c0 = t * 64;
        const uint32_t kh_d = sb + AT_KH + s * ATA;
        const uint32_t vh_d = sb + AT_VH + s * ATA;
#pragma unroll
        for (int j = 0; j < 4; j++) {
            const int e = tid + j * 128;
            const int r = e >> 3, q = e & 7;
            CP_ASYNC16(kh_d + r * 144 + q * 16, Kh_g + (long)(c0 + r) * 64 + q * 8);
            CP_ASYNC16(vh_d + r * 144 + q * 16, Vh_g + (long)r * C_ + c0 + q * 8);
        }
    };

    issue(tstart, tstart & 1);
    CP_COMMIT();
    __syncthreads();

    uint32_t qh[4][4];
#pragma unroll
    for (int ks = 0; ks < 4; ks++) {
        const uint32_t off = (uint32_t)((dtile + lane15) * 72 + ks * 16 + aK) * 2;
        ldsm_x4(qh[ks], sb + AT_QH + off);
    }

    float oacc[8][4];
#pragma unroll
    for (int i = 0; i < 8; i++)
#pragma unroll
        for (int j = 0; j < 4; j++) oacc[i][j] = 0.0f;
    float m0 = -1e30f, m1 = -1e30f, l0 = 0.0f, l1 = 0.0f;

    for (int t = tstart; t < ntiles; t++) {
        if (t + 1 < ntiles) {
            issue(t + 1, (t + 1) & 1);
            CP_COMMIT();
            CP_WAIT1();
        } else {
            CP_WAIT0();
        }
        __syncthreads();

        const int s = t & 1;
        const int c0 = t * 64;
        const uint32_t sKh_b = sb + AT_KH + s * ATA;
        const uint32_t sVh_b = sb + AT_VH + s * ATA;

        // ---- S = Q @ K^T ----
        float sacc[8][4];
#pragma unroll
        for (int i = 0; i < 8; i++)
#pragma unroll
            for (int j = 0; j < 4; j++) sacc[i][j] = 0.0f;
#pragma unroll
        for (int ks = 0; ks < 4; ks++) {
            const int kB = ks * 16 + bK;
#pragma unroll
            for (int ntp = 0; ntp < 4; ntp++) {
                const uint32_t off = (uint32_t)((ntp * 16 + bN) * 72 + kB) * 2;
                uint32_t bhf[4];
                ldsm_x4(bhf, sKh_b + off);
#pragma unroll
                for (int h2 = 0; h2 < 2; h2++)
                    mma16816(sacc[ntp * 2 + h2], qh[ks], bhf + h2 * 2);
            }
        }

        // ---- mask + scale ----
        {
            const int dg0 = d0 + r0, dg1 = d0 + r0 + 8;
#pragma unroll
            for (int nt = 0; nt < 8; nt++) {
                const int cg = c0 + nt * 8 + lr * 2;
                if (cg     <= dg0) sacc[nt][0] -= 100.0f;
                if (cg + 1 <= dg0) sacc[nt][1] -= 100.0f;
                if (cg     <= dg1) sacc[nt][2] -= 100.0f;
                if (cg + 1 <= dg1) sacc[nt][3] -= 100.0f;
#pragma unroll
                for (int j = 0; j < 4; j++) sacc[nt][j] *= 0.125f;
            }
        }

        // ---- register softmax ----
        {
            float mt0 = sacc[0][0], mt1 = sacc[0][2];
#pragma unroll
            for (int nt = 0; nt < 8; nt++) {
                mt0 = fmaxf(mt0, fmaxf(sacc[nt][0], sacc[nt][1]));
                mt1 = fmaxf(mt1, fmaxf(sacc[nt][2], sacc[nt][3]));
            }
            mt0 = fmaxf(mt0, __shfl_xor_sync(0xffffffff, mt0, 1));
            mt0 = fmaxf(mt0, __shfl_xor_sync(0xffffffff, mt0, 2));
            mt1 = fmaxf(mt1, __shfl_xor_sync(0xffffffff, mt1, 1));
            mt1 = fmaxf(mt1, __shfl_xor_sync(0xffffffff, mt1, 2));
            const float mn0 = fmaxf(m0, mt0);
            const float mn1 = fmaxf(m1, mt1);
            const float a0 = __expf(m0 - mn0);
            const float a1 = __expf(m1 - mn1);
            float s0 = 0.0f, s1 = 0.0f;
#pragma unroll
            for (int nt = 0; nt < 8; nt++) {
                sacc[nt][0] = __expf(sacc[nt][0] - mn0); s0 += sacc[nt][0];
                sacc[nt][1] = __expf(sacc[nt][1] - mn0); s0 += sacc[nt][1];
                sacc[nt][2] = __expf(sacc[nt][2] - mn1); s1 += sacc[nt][2];
                sacc[nt][3] = __expf(sacc[nt][3] - mn1); s1 += sacc[nt][3];
            }
            s0 += __shfl_xor_sync(0xffffffff, s0, 1);
            s0 += __shfl_xor_sync(0xffffffff, s0, 2);
            s1 += __shfl_xor_sync(0xffffffff, s1, 1);
            s1 += __shfl_xor_sync(0xffffffff, s1, 2);
            l0 = l0 * a0 + s0;
            l1 = l1 * a1 + s1;
            m0 = mn0; m1 = mn1;
#pragma unroll
            for (int nt = 0; nt < 8; nt++) {
                oacc[nt][0] *= a0; oacc[nt][1] *= a0;
                oacc[nt][2] *= a1; oacc[nt][3] *= a1;
            }
        }

        // ---- O += P @ V ----
#pragma unroll
        for (int ks = 0; ks < 4; ks++) {
            uint32_t ph[4];
            ph[0] = packh2(sacc[2 * ks][0],     sacc[2 * ks][1]);
            ph[1] = packh2(sacc[2 * ks][2],     sacc[2 * ks][3]);
            ph[2] = packh2(sacc[2 * ks + 1][0], sacc[2 * ks + 1][1]);
            ph[3] = packh2(sacc[2 * ks + 1][2], sacc[2 * ks + 1][3]);
            const int kB = ks * 16 + bK;
#pragma unroll
            for (int ntp = 0; ntp < 4; ntp++) {
                const uint32_t off = (uint32_t)((ntp * 16 + bN) * 72 + kB) * 2;
                uint32_t bhf[4];
                ldsm_x4(bhf, sVh_b + off);
#pragma unroll
                for (int h2 = 0; h2 < 2; h2++)
                    mma16816(oacc[ntp * 2 + h2], ph, bhf + h2 * 2);
            }
        }
        __syncthreads();
    }

    // ---- epilogue -> pre, layout [b*C + d][h*64 + v] ----
    {
        const float il0 = 1.0f / l0;
        const float il1 = 1.0f / l1;
#pragma unroll
        for (int nt = 0; nt < 8; nt++) {
            const int col = h * 64 + nt * 8 + lr * 2;
            const long i0 = ((long)(b * C_ + d0 + r0)) * (H_ * V_) + col;
            const long i1 = ((long)(b * C_ + d0 + r0 + 8)) * (H_ * V_) + col;
            *reinterpret_cast<uint32_t*>(&pre_g[i0]) =
                packh2(oacc[nt][0] * il0, oacc[nt][1] * il0);
            *reinterpret_cast<uint32_t*>(&pre_g[i1]) =
                packh2(oacc[nt][2] * il1, oacc[nt][3] * il1);
        }
    }
}

// ---------------------------------------------------------------------------

extern "C" void kernel_launch(void* const* d_in, const int* in_sizes, int n_in,
                              void* d_out, int out_size)
{
    const float* kvinput = (const float*)d_in[0];
    const float* qinput  = (const float*)d_in[1];
    const float* wq      = (const float*)d_in[2];
    const float* wk      = (const float*)d_in[3];
    const float* wv      = (const float*)d_in[4];
    const float* wo      = (const float*)d_in[5];
    float* out = (float*)d_out;

    __half *xqh, *xkh, *wqh, *wkvh, *woh;
    __half *qh, *kvh, *vth, *prh;
    cudaGetSymbolAddress((void**)&xqh, s_xq_h);
    cudaGetSymbolAddress((void**)&xkh, s_xkv_h);
    cudaGetSymbolAddress((void**)&wqh, s_wqT_h);
    cudaGetSymbolAddress((void**)&wkvh, s_wkvT_h);
    cudaGetSymbolAddress((void**)&woh, s_woT_h);
    cudaGetSymbolAddress((void**)&qh,  s_q_h);
    cudaGetSymbolAddress((void**)&kvh, s_kv_h);
    cudaGetSymbolAddress((void**)&vth, s_vT_h);
    cudaGetSymbolAddress((void**)&prh, s_pre_h);

    cudaFuncSetAttribute(proj_kernel,
                         cudaFuncAttributeMaxDynamicSharedMemorySize, GEMM_SMEM3);
    cudaFuncSetAttribute(outproj_kernel,
                         cudaFuncAttributeMaxDynamicSharedMemorySize, GEMM_SMEM3);
    cudaFuncSetAttribute(attn_kernel,
                         cudaFuncAttributeMaxDynamicSharedMemorySize, AT_TOTAL);

    // launch 0: convert inputs to fp16
    {
        int n4 = B_ * C_ * M_ / 4;
        cvt2_kernel<<<(2 * n4 + 255) / 256, 256>>>(qinput, kvinput, xqh, xkh, n4);
    }
    // launch 1: all weight transposes
    {
        dim3 tb(32, 8);
        trans_all_kernel<<<4096, tb>>>(wq, wk, wv, wo, wqh, wkvh, woh);
    }
    // launch 2: merged Q + KV projections
    {
        dim3 pg(C_ / 128, 24, B_);
        proj_kernel<<<pg, 128, GEMM_SMEM3>>>(xqh, xkh, wqh, wkvh, qh, kvh);
    }
    // launch 3: V transpose
    {
        dim3 vg(C_ / 64, B_ * H_);
        vtrans_kernel<<<vg, 256>>>(kvh, vth);
    }
    // launch 4: attention
    {
        dim3 ag(C_ / 64, H_, B_);
        attn_kernel<<<ag, 128, AT_TOTAL>>>(qh, kvh, vth, prh);
    }
    // launch 5: output projection
    {
        dim3 og((B_ * C_) / 128, M_ / 128, 1);
        outproj_kernel<<<og, 128, GEMM_SMEM3>>>(prh, woh, out);
    }
}

// round 11
// speedup vs baseline: 8.9176x; 1.0203x over previous
#include <cuda_runtime.h>
#include <cuda_fp16.h>
#include <cstdint>
#include <math.h>

#define B_ 2
#define C_ 2048
#define M_ 1024
#define H_ 16
#define K_ 64
#define V_ 64

// ------------------------- scratch (no cudaMalloc) -------------------------
__device__ __half s_xq_h [(size_t)B_ * C_ * M_];
__device__ __half s_xkv_h[(size_t)B_ * C_ * M_];

__device__ __half s_wqT_h [(size_t)H_ * K_ * M_];
__device__ __half s_wkvT_h[(size_t)H_ * 128 * M_];      // rows 0-63 K, 64-127 V
__device__ __half s_woT_h [(size_t)M_ * (H_ * V_)];

__device__ __half s_q_h [(size_t)B_ * H_ * C_ * K_];
__device__ __half s_kv_h[(size_t)B_ * H_ * 2 * C_ * 64];// [bh][0]=K,[bh][1]=V
__device__ __half s_pre_h[(size_t)B_ * C_ * (H_ * V_)];

// ------------------------------ helpers ------------------------------------
__device__ __forceinline__ uint32_t packh2(float x, float y) {
    __half2 h = __floats2half2_rn(x, y);
    return *reinterpret_cast<uint32_t*>(&h);
}

__device__ __forceinline__ void mma16816(float* c, const uint32_t* a,
                                         const uint32_t* b) {
    asm volatile(
        "mma.sync.aligned.m16n8k16.row.col.f32.f16.f16.f32 "
        "{%0,%1,%2,%3}, {%4,%5,%6,%7}, {%8,%9}, {%0,%1,%2,%3};\n"
        : "+f"(c[0]), "+f"(c[1]), "+f"(c[2]), "+f"(c[3])
        : "r"(a[0]), "r"(a[1]), "r"(a[2]), "r"(a[3]), "r"(b[0]), "r"(b[1]));
}

__device__ __forceinline__ void ldsm_x4(uint32_t* r, uint32_t addr) {
    asm volatile(
        "ldmatrix.sync.aligned.m8n8.x4.shared.b16 {%0,%1,%2,%3}, [%4];\n"
        : "=r"(r[0]), "=r"(r[1]), "=r"(r[2]), "=r"(r[3]) : "r"(addr));
}
__device__ __forceinline__ void ldsm_x4_trans(uint32_t* r, uint32_t addr) {
    asm volatile(
        "ldmatrix.sync.aligned.m8n8.x4.trans.shared.b16 {%0,%1,%2,%3}, [%4];\n"
        : "=r"(r[0]), "=r"(r[1]), "=r"(r[2]), "=r"(r[3]) : "r"(addr));
}

__device__ __forceinline__ uint32_t smem_u32(const void* p) {
    uint32_t a;
    asm("{ .reg .u64 t; cvta.to.shared.u64 t, %1; cvt.u32.u64 %0, t; }"
        : "=r"(a) : "l"(p));
    return a;
}
#define CP_ASYNC16(dst, src) \
    asm volatile("cp.async.ca.shared.global [%0], [%1], 16;\n" \
                 :: "r"(dst), "l"(src) : "memory")
#define CP_COMMIT() asm volatile("cp.async.commit_group;\n" ::: "memory")
#define CP_WAIT0()  asm volatile("cp.async.wait_group 0;\n" ::: "memory")
#define CP_WAIT1()  asm volatile("cp.async.wait_group 1;\n" ::: "memory")

// --------------------------- pre-pass kernels ------------------------------
__global__ void cvt2_kernel(const float* __restrict__ inq,
                            const float* __restrict__ inkv,
                            __half* __restrict__ oq, __half* __restrict__ okv,
                            int n4each) {
    int i = blockIdx.x * blockDim.x + threadIdx.x;
    const float* in;
    __half* o;
    int idx;
    if (i < n4each) { in = inq; o = oq; idx = i; }
    else if (i < 2 * n4each) { in = inkv; o = okv; idx = i - n4each; }
    else return;
    float4 v = reinterpret_cast<const float4*>(in)[idx];
    reinterpret_cast<uint2*>(o)[idx] =
        make_uint2(packh2(v.x, v.y), packh2(v.z, v.w));
}

// all 4 weight transposes (fp16) in one launch; 4096 blocks
__global__ void trans_all_kernel(const float* __restrict__ wq,
                                 const float* __restrict__ wk,
                                 const float* __restrict__ wv,
                                 const float* __restrict__ wo,
                                 __half* __restrict__ wqh,
                                 __half* __restrict__ wkvh,
                                 __half* __restrict__ woh) {
    __shared__ float t[32][33];
    const int bid = blockIdx.x;
    const float* in;
    __half* oh;
    int R, Cdim, c0, r0;
    long ib, ob;
    if (bid < 3072) {
        const int m = bid >> 10;
        const int r = bid & 1023;
        const int hh = r >> 6;
        const int rem = r & 63;
        const int gy = rem >> 1, gx = rem & 1;
        R = M_; Cdim = K_;
        c0 = gx * 32; r0 = gy * 32;
        if (m == 0) {
            in = wq;  oh = wqh;
            ib = (long)hh * M_ * K_; ob = (long)hh * K_ * M_;
        } else if (m == 1) {
            in = wk;  oh = wkvh;
            ib = (long)hh * M_ * K_; ob = (long)hh * 128 * M_;
        } else {
            in = wv;  oh = wkvh + (size_t)64 * M_;
            ib = (long)hh * M_ * V_; ob = (long)hh * 128 * M_;
        }
    } else {
        const int r = bid - 3072;
        R = H_ * V_; Cdim = M_;
        c0 = (r & 31) * 32; r0 = (r >> 5) * 32;
        in = wo; oh = woh; ib = 0; ob = 0;
    }
    in += ib;
#pragma unroll
    for (int i = threadIdx.y; i < 32; i += 8)
        t[i][threadIdx.x] = in[(long)(r0 + i) * Cdim + c0 + threadIdx.x];
    __syncthreads();
#pragma unroll
    for (int i = threadIdx.y; i < 32; i += 8) {
        long idx = ob + (long)(c0 + i) * R + r0 + threadIdx.x;
        oh[idx] = __float2half_rn(t[threadIdx.x][i]);
    }
}

// ---------------------------------------------------------------------------
// fp16 GEMM core: O = A * W, 128x128 block tile, 128 threads, 4 warps of
// 64x64 each. inner = 1024, K-chunk 32, 3-stage cp.async pipeline, ldmatrix.
// ---------------------------------------------------------------------------
#define GS 40
#define PARR 10240                   // 128 * GS * 2B
#define PSTG (2 * PARR)              // A + W per stage = 20480
#define GEMM_SMEM3 (3 * PSTG)        // 61440

#define GEMM_CORE(A_, Wh_)                                                   \
    const int tid = threadIdx.x;                                             \
    const int wid = tid >> 5, lane = tid & 31;                               \
    const int lq = lane >> 2, lr = lane & 3;                                 \
    const int wm = wid >> 1, wn = wid & 1;                                   \
    const int lane15 = lane & 15;                                            \
    const int aK = (lane >> 4) << 3;                                         \
    const int bN = ((lane >> 4) << 3) + (lane & 7);                          \
    const int bK = ((lane >> 3) & 1) << 3;                                   \
    float acc[4][8][4];                                                      \
    _Pragma("unroll") for (int a = 0; a < 4; a++)                            \
    _Pragma("unroll") for (int b = 0; b < 8; b++)                            \
    _Pragma("unroll") for (int c = 0; c < 4; c++) acc[a][b][c] = 0.0f;       \
    auto issue = [&](int ck, int s) {                                        \
        const int m0 = ck << 5;                                              \
        const uint32_t base = sb + s * PSTG;                                 \
        _Pragma("unroll")                                                    \
        for (int l = 0; l < 4; l++) {                                        \
            const int e = tid + l * 128;                                     \
            const int r = e >> 2, q = e & 3;                                 \
            CP_ASYNC16(base + r * 80 + q * 16,                               \
                       A_ + (long)r * 1024 + m0 + q * 8);                    \
            CP_ASYNC16(base + PARR + r * 80 + q * 16,                        \
                       Wh_ + (long)r * 1024 + m0 + q * 8);                   \
        }                                                                    \
    };                                                                       \
    issue(0, 0); CP_COMMIT();                                                \
    issue(1, 1); CP_COMMIT();                                                \
    for (int it = 0; it < 32; it++) {                                        \
        if (it < 31) { CP_WAIT1(); } else { CP_WAIT0(); }                    \
        __syncthreads();                                                     \
        if (it + 2 < 32) { issue(it + 2, (it + 2) % 3); CP_COMMIT(); }       \
        const uint32_t cbase = sb + (it % 3) * PSTG;                         \
        _Pragma("unroll")                                                    \
        for (int ks = 0; ks < 2; ks++) {                                     \
            const int kA = ks * 16 + aK;                                     \
            const int kB = ks * 16 + bK;                                     \
            uint32_t ah[4][4];                                               \
            _Pragma("unroll")                                                \
            for (int mt = 0; mt < 4; mt++) {                                 \
                const uint32_t off =                                         \
                    (uint32_t)((wm * 64 + mt * 16 + lane15) * GS + kA) * 2;  \
                ldsm_x4(ah[mt], cbase + off);                                \
            }                                                                \
            _Pragma("unroll")                                                \
            for (int ntp = 0; ntp < 4; ntp++) {                              \
                const uint32_t off =                                         \
                    (uint32_t)((wn * 64 + ntp * 16 + bN) * GS + kB) * 2;     \
                uint32_t bhf[4];                                             \
                ldsm_x4(bhf, cbase + PARR + off);                            \
                _Pragma("unroll")                                            \
                for (int h2 = 0; h2 < 2; h2++) {                             \
                    const int nt = ntp * 2 + h2;                             \
                    _Pragma("unroll")                                        \
                    for (int mt = 0; mt < 4; mt++)                           \
                        mma16816(acc[mt][nt], ah[mt], bhf + h2 * 2);         \
                }                                                            \
            }                                                                \
        }                                                                    \
    }

// Merged Q + KV projections: grid (16, 24, 2). y<8: Q (2 heads/tile);
// y>=8: KV head y-8 (K cols 0-63, V cols 64-127). 128 threads.
__global__ void __launch_bounds__(128, 2)
proj_kernel(const __half* __restrict__ xq, const __half* __restrict__ xkv,
            const __half* __restrict__ wqh, const __half* __restrict__ wkvh,
            __half* __restrict__ q_out, __half* __restrict__ kv_h)
{
    const int z = blockIdx.z, y = blockIdx.y;
    const int row0 = blockIdx.x * 128;
    const long hs = (long)C_ * 64;
    const bool isQ = (y < 8);
    const __half *A, *Wh;
    __half* O;
    long oOff;
    if (isQ) {
        A  = xq + (long)z * C_ * M_ + (long)row0 * M_;
        Wh = wqh + (long)y * 128 * M_;
        O  = q_out;
        oOff = (long)z * H_ * hs + (long)y * 2 * hs;
    } else {
        const int yk = y - 8;
        A  = xkv + (long)z * C_ * M_ + (long)row0 * M_;
        Wh = wkvh + (long)yk * 128 * M_;
        O  = kv_h;
        oOff = (long)z * H_ * 2 * hs + (long)yk * 2 * hs;
    }

    extern __shared__ char smem[];
    const uint32_t sb = smem_u32(smem);
    GEMM_CORE(A, Wh)

#pragma unroll
    for (int mt = 0; mt < 4; mt++) {
        const int row_lo = row0 + wm * 64 + mt * 16 + lq;
        const int row_hi = row_lo + 8;
#pragma unroll
        for (int nt = 0; nt < 8; nt++) {
            const int col = wn * 64 + nt * 8 + lr * 2;
            const float* c = acc[mt][nt];
            const long hb = oOff + (long)(col >> 6) * hs + (col & 63);
            *reinterpret_cast<uint32_t*>(&O[hb + (long)row_lo * 64]) =
                packh2(c[0], c[1]);
            *reinterpret_cast<uint32_t*>(&O[hb + (long)row_hi * 64]) =
                packh2(c[2], c[3]);
        }
    }
}

// Output projection: out[4096][1024] = pre @ woT. grid (32, 8). 128 threads.
__global__ void __launch_bounds__(128, 2)
outproj_kernel(const __half* __restrict__ pre,
               const __half* __restrict__ woh,
               float* __restrict__ out)
{
    const int row0 = blockIdx.x * 128;
    const int col0 = blockIdx.y * 128;
    const __half* A  = pre + (long)row0 * M_;
    const __half* Wh = woh + (long)col0 * M_;

    extern __shared__ char smem[];
    const uint32_t sb = smem_u32(smem);
    GEMM_CORE(A, Wh)

#pragma unroll
    for (int mt = 0; mt < 4; mt++) {
        const int row_lo = row0 + wm * 64 + mt * 16 + lq;
        const int row_hi = row_lo + 8;
#pragma unroll
        for (int nt = 0; nt < 8; nt++) {
            const int col = col0 + wn * 64 + nt * 8 + lr * 2;
            const float* c = acc[mt][nt];
            *reinterpret_cast<float2*>(&out[(long)row_lo * M_ + col]) =
                make_float2(c[0], c[1]);
            *reinterpret_cast<float2*>(&out[(long)row_hi * M_ + col]) =
                make_float2(c[2], c[3]);
        }
    }
}

// ---------------------------------------------------------------------------
// Flash attention: 128 queries/block, 4 warps x 32 query rows, pure fp16,
// register softmax, mask-aware tile skipping, cp.async double-buffered K/V,
// V fragments via ldmatrix.trans straight from [c][v] layout (no vtrans).
// ---------------------------------------------------------------------------
#define ATA  9216                    // one 64x72 fp16 array
#define AT_KH 0                      // 2 stages
#define AT_VH (2 * ATA)              // 2 stages
#define AT_QH (4 * ATA)              // Q: 128x72 fp16 = 18432
#define AT_TOTAL (AT_QH + 18432)     // 55296

__global__ void __launch_bounds__(128, 2)
attn_kernel(const __half* __restrict__ qh_g,
            const __half* __restrict__ kvh_g,
            __half* __restrict__ pre_g)
{
    const int b = blockIdx.z, h = blockIdx.y;
    const int qb = blockIdx.x;               // 0..15, 128 queries each
    const int d0 = qb * 128;
    const int bh = b * H_ + h;
    const int ntiles = C_ / 64;
    const int tstart = (qb == 15) ? 0 : 2 * qb;

    extern __shared__ char smem[];
    const uint32_t sb = smem_u32(smem);
    __half* sQh = (__half*)(smem + AT_QH);

    const int tid = threadIdx.x;
    const int wid = tid >> 5, lane = tid & 31;
    const int lq = lane >> 2, lr = lane & 3;
    const int dtile = wid * 32;              // 32 query rows per warp

    const int lane15 = lane & 15;
    const int aK = (lane >> 4) << 3;
    const int bN = ((lane >> 4) << 3) + (lane & 7);
    const int bK = ((lane >> 3) & 1) << 3;
    // trans-ldsm lane geometry for V [c][v]
    const int tRow = (lane & 7) | (((lane >> 3) & 1) << 3);
    const int tN   = (lane >> 4) << 3;

    const __half* Kh_g = kvh_g + ((long)bh * 2) * C_ * 64;
    const __half* Vh_g = kvh_g + ((long)bh * 2 + 1) * C_ * 64;

    // Q tile: 128 rows x 64 cols = 1024 x 16B, 8 per thread
#pragma unroll
    for (int l = 0; l < 8; l++) {
        int e = tid + l * 128;
        int r = e >> 3, q = (e & 7) * 8;
        long g = ((long)bh * C_ + d0 + r) * 64 + q;
        *reinterpret_cast<uint4*>(&sQh[r * 72 + q]) =
            *reinterpret_cast<const uint4*>(&qh_g[g]);
    }

    auto issue = [&](int t, int s) {
        const int c0 = t * 64;
        const uint32_t kh_d = sb + AT_KH + s * ATA;
        const uint32_t vh_d = sb + AT_VH + s * ATA;
#pragma unroll
        for (int j = 0; j < 4; j++) {
            const int e = tid + j * 128;
            const int r = e >> 3, q = e & 7;
            CP_ASYNC16(kh_d + r * 144 + q * 16, Kh_g + (long)(c0 + r) * 64 + q * 8);
            CP_ASYNC16(vh_d + r * 144 + q * 16, Vh_g + (long)(c0 + r) * 64 + q * 8);
        }
    };

    issue(tstart, tstart & 1);
    CP_COMMIT();
    __syncthreads();

    // persistent Q fragments: [ks][mt][4]
    uint32_t qh[4][2][4];
#pragma unroll
    for (int ks = 0; ks < 4; ks++)
#pragma unroll
        for (int mt = 0; mt < 2; mt++) {
            const uint32_t off =
                (uint32_t)((dtile + mt * 16 + lane15) * 72 + ks * 16 + aK) * 2;
            ldsm_x4(qh[ks][mt], sb + AT_QH + off);
        }

    float oacc[2][8][4];
#pragma unroll
    for (int mt = 0; mt < 2; mt++)
#pragma unroll
        for (int i = 0; i < 8; i++)
#pragma unroll
            for (int j = 0; j < 4; j++) oacc[mt][i][j] = 0.0f;
    float mrow[4] = {-1e30f, -1e30f, -1e30f, -1e30f};
    float lrow[4] = {0.0f, 0.0f, 0.0f, 0.0f};

    for (int t = tstart; t < ntiles; t++) {
        if (t + 1 < ntiles) {
            issue(t + 1, (t + 1) & 1);
            CP_COMMIT();
            CP_WAIT1();
        } else {
            CP_WAIT0();
        }
        __syncthreads();

        const int s = t & 1;
        const int c0 = t * 64;
        const uint32_t sKh_b = sb + AT_KH + s * ATA;
        const uint32_t sVh_b = sb + AT_VH + s * ATA;

        // ---- S = Q @ K^T (32 rows x 64 keys per warp) ----
        float sacc[2][8][4];
#pragma unroll
        for (int mt = 0; mt < 2; mt++)
#pragma unroll
            for (int i = 0; i < 8; i++)
#pragma unroll
                for (int j = 0; j < 4; j++) sacc[mt][i][j] = 0.0f;
#pragma unroll
        for (int ks = 0; ks < 4; ks++) {
            const int kB = ks * 16 + bK;
#pragma unroll
            for (int ntp = 0; ntp < 4; ntp++) {
                const uint32_t off = (uint32_t)((ntp * 16 + bN) * 72 + kB) * 2;
                uint32_t bhf[4];
                ldsm_x4(bhf, sKh_b + off);
#pragma unroll
                for (int h2 = 0; h2 < 2; h2++)
#pragma unroll
                    for (int mt = 0; mt < 2; mt++)
                        mma16816(sacc[mt][ntp * 2 + h2], qh[ks][mt], bhf + h2 * 2);
            }
        }

        // ---- mask + scale ----
#pragma unroll
        for (int mt = 0; mt < 2; mt++) {
            const int dg0 = d0 + dtile + mt * 16 + lq;
            const int dg1 = dg0 + 8;
#pragma unroll
            for (int nt = 0; nt < 8; nt++) {
                const int cg = c0 + nt * 8 + lr * 2;
                if (cg     <= dg0) sacc[mt][nt][0] -= 100.0f;
                if (cg + 1 <= dg0) sacc[mt][nt][1] -= 100.0f;
                if (cg     <= dg1) sacc[mt][nt][2] -= 100.0f;
                if (cg + 1 <= dg1) sacc[mt][nt][3] -= 100.0f;
#pragma unroll
                for (int j = 0; j < 4; j++) sacc[mt][nt][j] *= 0.125f;
            }
        }

        // ---- register softmax (quad shuffles; 4 rows per thread) ----
#pragma unroll
        for (int mt = 0; mt < 2; mt++) {
            float mt0 = sacc[mt][0][0], mt1 = sacc[mt][0][2];
#pragma unroll
            for (int nt = 0; nt < 8; nt++) {
                mt0 = fmaxf(mt0, fmaxf(sacc[mt][nt][0], sacc[mt][nt][1]));
                mt1 = fmaxf(mt1, fmaxf(sacc[mt][nt][2], sacc[mt][nt][3]));
            }
            mt0 = fmaxf(mt0, __shfl_xor_sync(0xffffffff, mt0, 1));
            mt0 = fmaxf(mt0, __shfl_xor_sync(0xffffffff, mt0, 2));
            mt1 = fmaxf(mt1, __shfl_xor_sync(0xffffffff, mt1, 1));
            mt1 = fmaxf(mt1, __shfl_xor_sync(0xffffffff, mt1, 2));
            const int u0 = mt * 2, u1 = mt * 2 + 1;
            const float mn0 = fmaxf(mrow[u0], mt0);
            const float mn1 = fmaxf(mrow[u1], mt1);
            const float a0 = __expf(mrow[u0] - mn0);
            const float a1 = __expf(mrow[u1] - mn1);
            float s0 = 0.0f, s1 = 0.0f;
#pragma unroll
            for (int nt = 0; nt < 8; nt++) {
                sacc[mt][nt][0] = __expf(sacc[mt][nt][0] - mn0); s0 += sacc[mt][nt][0];
                sacc[mt][nt][1] = __expf(sacc[mt][nt][1] - mn0); s0 += sacc[mt][nt][1];
                sacc[mt][nt][2] = __expf(sacc[mt][nt][2] - mn1); s1 += sacc[mt][nt][2];
                sacc[mt][nt][3] = __expf(sacc[mt][nt][3] - mn1); s1 += sacc[mt][nt][3];
            }
            s0 += __shfl_xor_sync(0xffffffff, s0, 1);
            s0 += __shfl_xor_sync(0xffffffff, s0, 2);
            s1 += __shfl_xor_sync(0xffffffff, s1, 1);
            s1 += __shfl_xor_sync(0xffffffff, s1, 2);
            lrow[u0] = lrow[u0] * a0 + s0;
            lrow[u1] = lrow[u1] * a1 + s1;
            mrow[u0] = mn0; mrow[u1] = mn1;
#pragma unroll
            for (int nt = 0; nt < 8; nt++) {
                oacc[mt][nt][0] *= a0; oacc[mt][nt][1] *= a0;
                oacc[mt][nt][2] *= a1; oacc[mt][nt][3] *= a1;
            }
        }

        // ---- O += P @ V ; V fragments via trans-ldsm from [c][v] ----
#pragma unroll
        for (int ks = 0; ks < 4; ks++) {
            uint32_t ph[2][4];
#pragma unroll
            for (int mt = 0; mt < 2; mt++) {
                ph[mt][0] = packh2(sacc[mt][2 * ks][0],     sacc[mt][2 * ks][1]);
                ph[mt][1] = packh2(sacc[mt][2 * ks][2],     sacc[mt][2 * ks][3]);
                ph[mt][2] = packh2(sacc[mt][2 * ks + 1][0], sacc[mt][2 * ks + 1][1]);
                ph[mt][3] = packh2(sacc[mt][2 * ks + 1][2], sacc[mt][2 * ks + 1][3]);
            }
#pragma unroll
            for (int ntp = 0; ntp < 4; ntp++) {
                const uint32_t off =
                    (uint32_t)((ks * 16 + tRow) * 72 + ntp * 16 + tN) * 2;
                uint32_t bhf[4];
                ldsm_x4_trans(bhf, sVh_b + off);
#pragma unroll
                for (int h2 = 0; h2 < 2; h2++)
#pragma unroll
                    for (int mt = 0; mt < 2; mt++)
                        mma16816(oacc[mt][ntp * 2 + h2], ph[mt], bhf + h2 * 2);
            }
        }
        __syncthreads();
    }

    // ---- epilogue -> pre, layout [b*C + d][h*64 + v] ----
#pragma unroll
    for (int mt = 0; mt < 2; mt++) {
        const float il0 = 1.0f / lrow[mt * 2];
        const float il1 = 1.0f / lrow[mt * 2 + 1];
        const int row0g = d0 + dtile + mt * 16 + lq;
#pragma unroll
        for (int nt = 0; nt < 8; nt++) {
            const int col = h * 64 + nt * 8 + lr * 2;
            const long i0 = ((long)(b * C_ + row0g)) * (H_ * V_) + col;
            const long i1 = ((long)(b * C_ + row0g + 8)) * (H_ * V_) + col;
            *reinterpret_cast<uint32_t*>(&pre_g[i0]) =
                packh2(oacc[mt][nt][0] * il0, oacc[mt][nt][1] * il0);
            *reinterpret_cast<uint32_t*>(&pre_g[i1]) =
                packh2(oacc[mt][nt][2] * il1, oacc[mt][nt][3] * il1);
        }
    }
}

// ---------------------------------------------------------------------------

extern "C" void kernel_launch(void* const* d_in, const int* in_sizes, int n_in,
                              void* d_out, int out_size)
{
    const float* kvinput = (const float*)d_in[0];
    const float* qinput  = (const float*)d_in[1];
    const float* wq      = (const float*)d_in[2];
    const float* wk      = (const float*)d_in[3];
    const float* wv      = (const float*)d_in[4];
    const float* wo      = (const float*)d_in[5];
    float* out = (float*)d_out;

    __half *xqh, *xkh, *wqh, *wkvh, *woh;
    __half *qh, *kvh, *prh;
    cudaGetSymbolAddress((void**)&xqh, s_xq_h);
    cudaGetSymbolAddress((void**)&xkh, s_xkv_h);
    cudaGetSymbolAddress((void**)&wqh, s_wqT_h);
    cudaGetSymbolAddress((void**)&wkvh, s_wkvT_h);
    cudaGetSymbolAddress((void**)&woh, s_woT_h);
    cudaGetSymbolAddress((void**)&qh,  s_q_h);
    cudaGetSymbolAddress((void**)&kvh, s_kv_h);
    cudaGetSymbolAddress((void**)&prh, s_pre_h);

    cudaFuncSetAttribute(proj_kernel,
                         cudaFuncAttributeMaxDynamicSharedMemorySize, GEMM_SMEM3);
    cudaFuncSetAttribute(outproj_kernel,
                         cudaFuncAttributeMaxDynamicSharedMemorySize, GEMM_SMEM3);
    cudaFuncSetAttribute(attn_kernel,
                         cudaFuncAttributeMaxDynamicSharedMemorySize, AT_TOTAL);

    // launch 0: convert inputs to fp16
    {
        int n4 = B_ * C_ * M_ / 4;
        cvt2_kernel<<<(2 * n4 + 255) / 256, 256>>>(qinput, kvinput, xqh, xkh, n4);
    }
    // launch 1: all weight transposes
    {
        dim3 tb(32, 8);
        trans_all_kernel<<<4096, tb>>>(wq, wk, wv, wo, wqh, wkvh, woh);
    }
    // launch 2: merged Q + KV projections
    {
        dim3 pg(C_ / 128, 24, B_);
        proj_kernel<<<pg, 128, GEMM_SMEM3>>>(xqh, xkh, wqh, wkvh, qh, kvh);
    }
    // launch 3: attention (128 queries per block; V via trans-ldsm)
    {
        dim3 ag(C_ / 128, H_, B_);
        attn_kernel<<<ag, 128, AT_TOTAL>>>(qh, kvh, prh);
    }
    // launch 4: output projection
    {
        dim3 og((B_ * C_) / 128, M_ / 128, 1);
        outproj_kernel<<<og, 128, GEMM_SMEM3>>>(prh, woh, out);
    }
}

// round 13
// speedup vs baseline: 10.0369x; 1.1255x over previous
#include <cuda_runtime.h>
#include <cuda_fp16.h>
#include <cstdint>
#include <math.h>

#define B_ 2
#define C_ 2048
#define M_ 1024
#define H_ 16
#define K_ 64
#define V_ 64

// ------------------------- scratch (no cudaMalloc) -------------------------
__device__ __half s_xq_h [(size_t)B_ * C_ * M_];
__device__ __half s_xkv_h[(size_t)B_ * C_ * M_];

__device__ __half s_wqT_h [(size_t)H_ * K_ * M_];
__device__ __half s_wkvT_h[(size_t)H_ * 128 * M_];      // rows 0-63 K, 64-127 V
__device__ __half s_woT_h [(size_t)M_ * (H_ * V_)];

__device__ __half s_q_h [(size_t)B_ * H_ * C_ * K_];
__device__ __half s_kv_h[(size_t)B_ * H_ * 2 * C_ * 64];// [bh][0]=K,[bh][1]=V
__device__ __half s_pre_h[(size_t)B_ * C_ * (H_ * V_)];

// ------------------------------ helpers ------------------------------------
__device__ __forceinline__ uint32_t packh2(float x, float y) {
    __half2 h = __floats2half2_rn(x, y);
    return *reinterpret_cast<uint32_t*>(&h);
}

__device__ __forceinline__ void mma16816(float* c, const uint32_t* a,
                                         const uint32_t* b) {
    asm volatile(
        "mma.sync.aligned.m16n8k16.row.col.f32.f16.f16.f32 "
        "{%0,%1,%2,%3}, {%4,%5,%6,%7}, {%8,%9}, {%0,%1,%2,%3};\n"
        : "+f"(c[0]), "+f"(c[1]), "+f"(c[2]), "+f"(c[3])
        : "r"(a[0]), "r"(a[1]), "r"(a[2]), "r"(a[3]), "r"(b[0]), "r"(b[1]));
}

__device__ __forceinline__ void ldsm_x4(uint32_t* r, uint32_t addr) {
    asm volatile(
        "ldmatrix.sync.aligned.m8n8.x4.shared.b16 {%0,%1,%2,%3}, [%4];\n"
        : "=r"(r[0]), "=r"(r[1]), "=r"(r[2]), "=r"(r[3]) : "r"(addr));
}
__device__ __forceinline__ void ldsm_x4_trans(uint32_t* r, uint32_t addr) {
    asm volatile(
        "ldmatrix.sync.aligned.m8n8.x4.trans.shared.b16 {%0,%1,%2,%3}, [%4];\n"
        : "=r"(r[0]), "=r"(r[1]), "=r"(r[2]), "=r"(r[3]) : "r"(addr));
}

__device__ __forceinline__ uint32_t smem_u32(const void* p) {
    uint32_t a;
    asm("{ .reg .u64 t; cvta.to.shared.u64 t, %1; cvt.u32.u64 %0, t; }"
        : "=r"(a) : "l"(p));
    return a;
}
#define CP_ASYNC16(dst, src) \
    asm volatile("cp.async.ca.shared.global [%0], [%1], 16;\n" \
                 :: "r"(dst), "l"(src) : "memory")
#define CP_COMMIT() asm volatile("cp.async.commit_group;\n" ::: "memory")
#define CP_WAIT0()  asm volatile("cp.async.wait_group 0;\n" ::: "memory")
#define CP_WAIT1()  asm volatile("cp.async.wait_group 1;\n" ::: "memory")

// --------------------------- pre-pass kernels ------------------------------
__global__ void cvt2_kernel(const float* __restrict__ inq,
                            const float* __restrict__ inkv,
                            __half* __restrict__ oq, __half* __restrict__ okv,
                            int n4each) {
    int i = blockIdx.x * blockDim.x + threadIdx.x;
    const float* in;
    __half* o;
    int idx;
    if (i < n4each) { in = inq; o = oq; idx = i; }
    else if (i < 2 * n4each) { in = inkv; o = okv; idx = i - n4each; }
    else return;
    float4 v = reinterpret_cast<const float4*>(in)[idx];
    reinterpret_cast<uint2*>(o)[idx] =
        make_uint2(packh2(v.x, v.y), packh2(v.z, v.w));
}

// all 4 weight transposes (fp16) in one launch; 4096 blocks
__global__ void trans_all_kernel(const float* __restrict__ wq,
                                 const float* __restrict__ wk,
                                 const float* __restrict__ wv,
                                 const float* __restrict__ wo,
                                 __half* __restrict__ wqh,
                                 __half* __restrict__ wkvh,
                                 __half* __restrict__ woh) {
    __shared__ float t[32][33];
    const int bid = blockIdx.x;
    const float* in;
    __half* oh;
    int R, Cdim, c0, r0;
    long ib, ob;
    if (bid < 3072) {
        const int m = bid >> 10;
        const int r = bid & 1023;
        const int hh = r >> 6;
        const int rem = r & 63;
        const int gy = rem >> 1, gx = rem & 1;
        R = M_; Cdim = K_;
        c0 = gx * 32; r0 = gy * 32;
        if (m == 0) {
            in = wq;  oh = wqh;
            ib = (long)hh * M_ * K_; ob = (long)hh * K_ * M_;
        } else if (m == 1) {
            in = wk;  oh = wkvh;
            ib = (long)hh * M_ * K_; ob = (long)hh * 128 * M_;
        } else {
            in = wv;  oh = wkvh + (size_t)64 * M_;
            ib = (long)hh * M_ * V_; ob = (long)hh * 128 * M_;
        }
    } else {
        const int r = bid - 3072;
        R = H_ * V_; Cdim = M_;
        c0 = (r & 31) * 32; r0 = (r >> 5) * 32;
        in = wo; oh = woh; ib = 0; ob = 0;
    }
    in += ib;
#pragma unroll
    for (int i = threadIdx.y; i < 32; i += 8)
        t[i][threadIdx.x] = in[(long)(r0 + i) * Cdim + c0 + threadIdx.x];
    __syncthreads();
#pragma unroll
    for (int i = threadIdx.y; i < 32; i += 8) {
        long idx = ob + (long)(c0 + i) * R + r0 + threadIdx.x;
        oh[idx] = __float2half_rn(t[threadIdx.x][i]);
    }
}

// ---------------------------------------------------------------------------
// fp16 GEMM core (unchanged)
// ---------------------------------------------------------------------------
#define GS 40
#define PARR 10240
#define PSTG (2 * PARR)
#define GEMM_SMEM3 (3 * PSTG)

#define GEMM_CORE(A_, Wh_)                                                   \
    const int tid = threadIdx.x;                                             \
    const int wid = tid >> 5, lane = tid & 31;                               \
    const int lq = lane >> 2, lr = lane & 3;                                 \
    const int wm = wid >> 1, wn = wid & 1;                                   \
    const int lane15 = lane & 15;                                            \
    const int aK = (lane >> 4) << 3;                                         \
    const int bN = ((lane >> 4) << 3) + (lane & 7);                          \
    const int bK = ((lane >> 3) & 1) << 3;                                   \
    float acc[4][8][4];                                                      \
    _Pragma("unroll") for (int a = 0; a < 4; a++)                            \
    _Pragma("unroll") for (int b = 0; b < 8; b++)                            \
    _Pragma("unroll") for (int c = 0; c < 4; c++) acc[a][b][c] = 0.0f;       \
    auto issue = [&](int ck, int s) {                                        \
        const int m0 = ck << 5;                                              \
        const uint32_t base = sb + s * PSTG;                                 \
        _Pragma("unroll")                                                    \
        for (int l = 0; l < 4; l++) {                                        \
            const int e = tid + l * 128;                                     \
            const int r = e >> 2, q = e & 3;                                 \
            CP_ASYNC16(base + r * 80 + q * 16,                               \
                       A_ + (long)r * 1024 + m0 + q * 8);                    \
            CP_ASYNC16(base + PARR + r * 80 + q * 16,                        \
                       Wh_ + (long)r * 1024 + m0 + q * 8);                   \
        }                                                                    \
    };                                                                       \
    issue(0, 0); CP_COMMIT();                                                \
    issue(1, 1); CP_COMMIT();                                                \
    for (int it = 0; it < 32; it++) {                                        \
        if (it < 31) { CP_WAIT1(); } else { CP_WAIT0(); }                    \
        __syncthreads();                                                     \
        if (it + 2 < 32) { issue(it + 2, (it + 2) % 3); CP_COMMIT(); }       \
        const uint32_t cbase = sb + (it % 3) * PSTG;                         \
        _Pragma("unroll")                                                    \
        for (int ks = 0; ks < 2; ks++) {                                     \
            const int kA = ks * 16 + aK;                                     \
            const int kB = ks * 16 + bK;                                     \
            uint32_t ah[4][4];                                               \
            _Pragma("unroll")                                                \
            for (int mt = 0; mt < 4; mt++) {                                 \
                const uint32_t off =                                         \
                    (uint32_t)((wm * 64 + mt * 16 + lane15) * GS + kA) * 2;  \
                ldsm_x4(ah[mt], cbase + off);                                \
            }                                                                \
            _Pragma("unroll")                                                \
            for (int ntp = 0; ntp < 4; ntp++) {                              \
                const uint32_t off =                                         \
                    (uint32_t)((wn * 64 + ntp * 16 + bN) * GS + kB) * 2;     \
                uint32_t bhf[4];                                             \
                ldsm_x4(bhf, cbase + PARR + off);                            \
                _Pragma("unroll")                                            \
                for (int h2 = 0; h2 < 2; h2++) {                             \
                    const int nt = ntp * 2 + h2;                             \
                    _Pragma("unroll")                                        \
                    for (int mt = 0; mt < 4; mt++)                           \
                        mma16816(acc[mt][nt], ah[mt], bhf + h2 * 2);         \
                }                                                            \
            }                                                                \
        }                                                                    \
    }

__global__ void __launch_bounds__(128, 2)
proj_kernel(const __half* __restrict__ xq, const __half* __restrict__ xkv,
            const __half* __restrict__ wqh, const __half* __restrict__ wkvh,
            __half* __restrict__ q_out, __half* __restrict__ kv_h)
{
    const int z = blockIdx.z, y = blockIdx.y;
    const int row0 = blockIdx.x * 128;
    const long hs = (long)C_ * 64;
    const bool isQ = (y < 8);
    const __half *A, *Wh;
    __half* O;
    long oOff;
    if (isQ) {
        A  = xq + (long)z * C_ * M_ + (long)row0 * M_;
        Wh = wqh + (long)y * 128 * M_;
        O  = q_out;
        oOff = (long)z * H_ * hs + (long)y * 2 * hs;
    } else {
        const int yk = y - 8;
        A  = xkv + (long)z * C_ * M_ + (long)row0 * M_;
        Wh = wkvh + (long)yk * 128 * M_;
        O  = kv_h;
        oOff = (long)z * H_ * 2 * hs + (long)yk * 2 * hs;
    }

    extern __shared__ char smem[];
    const uint32_t sb = smem_u32(smem);
    GEMM_CORE(A, Wh)

#pragma unroll
    for (int mt = 0; mt < 4; mt++) {
        const int row_lo = row0 + wm * 64 + mt * 16 + lq;
        const int row_hi = row_lo + 8;
#pragma unroll
        for (int nt = 0; nt < 8; nt++) {
            const int col = wn * 64 + nt * 8 + lr * 2;
            const float* c = acc[mt][nt];
            const long hb = oOff + (long)(col >> 6) * hs + (col & 63);
            *reinterpret_cast<uint32_t*>(&O[hb + (long)row_lo * 64]) =
                packh2(c[0], c[1]);
            *reinterpret_cast<uint32_t*>(&O[hb + (long)row_hi * 64]) =
                packh2(c[2], c[3]);
        }
    }
}

__global__ void __launch_bounds__(128, 2)
outproj_kernel(const __half* __restrict__ pre,
               const __half* __restrict__ woh,
               float* __restrict__ out)
{
    const int row0 = blockIdx.x * 128;
    const int col0 = blockIdx.y * 128;
    const __half* A  = pre + (long)row0 * M_;
    const __half* Wh = woh + (long)col0 * M_;

    extern __shared__ char smem[];
    const uint32_t sb = smem_u32(smem);
    GEMM_CORE(A, Wh)

#pragma unroll
    for (int mt = 0; mt < 4; mt++) {
        const int row_lo = row0 + wm * 64 + mt * 16 + lq;
        const int row_hi = row_lo + 8;
#pragma unroll
        for (int nt = 0; nt < 8; nt++) {
            const int col = col0 + wn * 64 + nt * 8 + lr * 2;
            const float* c = acc[mt][nt];
            *reinterpret_cast<float2*>(&out[(long)row_lo * M_ + col]) =
                make_float2(c[0], c[1]);
            *reinterpret_cast<float2*>(&out[(long)row_hi * M_ + col]) =
                make_float2(c[2], c[3]);
        }
    }
}

// ---------------------------------------------------------------------------
// Flash attention, 9 balanced work-units per (b,h):
//   x=0 -> {qb=0} (32 tiles), x=8 -> {qb=15, tstart=0, full masking} (32),
//   x=1..7 -> {qb=x, qb=15-x} (34 tiles total). 288 blocks = single wave.
// Mask applied on tiles t <= 2qb+1 (exact). exp2 softmax.
// ---------------------------------------------------------------------------
#define ATA  9216                    // one 64x72 fp16 array
#define AT_KH 0                      // 2 stages
#define AT_VH (2 * ATA)              // 2 stages
#define AT_QH (4 * ATA)              // Q: 128x72 fp16 = 18432
#define AT_TOTAL (AT_QH + 18432)     // 55296

#define R2_  0.18033688f             // 0.125 / ln2
#define MB2_ 18.0336881f             // 100 * 0.125 / ln2

__global__ void __launch_bounds__(128, 2)
attn_kernel(const __half* __restrict__ qh_g,
            const __half* __restrict__ kvh_g,
            __half* __restrict__ pre_g)
{
    const int b = blockIdx.z, h = blockIdx.y;
    const int bh = b * H_ + h;
    const int ntiles = C_ / 64;
    const int x = blockIdx.x;        // 0..8

    int qlist[2];
    int nq;
    if (x == 0)      { qlist[0] = 0;  nq = 1; }
    else if (x == 8) { qlist[0] = 15; nq = 1; }
    else             { qlist[0] = x; qlist[1] = 15 - x; nq = 2; }

    extern __shared__ char smem[];
    const uint32_t sb = smem_u32(smem);
    __half* sQh = (__half*)(smem + AT_QH);

    const int tid = threadIdx.x;
    const int wid = tid >> 5, lane = tid & 31;
    const int lq = lane >> 2, lr = lane & 3;
    const int dtile = wid * 32;

    const int lane15 = lane & 15;
    const int aK = (lane >> 4) << 3;
    const int bN = ((lane >> 4) << 3) + (lane & 7);
    const int bK = ((lane >> 3) & 1) << 3;
    const int tRow = (lane & 7) | (((lane >> 3) & 1) << 3);
    const int tN   = (lane >> 4) << 3;

    const __half* Kh_g = kvh_g + ((long)bh * 2) * C_ * 64;
    const __half* Vh_g = kvh_g + ((long)bh * 2 + 1) * C_ * 64;

    auto issue = [&](int t, int s) {
        const int c0 = t * 64;
        const uint32_t kh_d = sb + AT_KH + s * ATA;
        const uint32_t vh_d = sb + AT_VH + s * ATA;
#pragma unroll
        for (int j = 0; j < 4; j++) {
            const int e = tid + j * 128;
            const int r = e >> 3, q = e & 7;
            CP_ASYNC16(kh_d + r * 144 + q * 16, Kh_g + (long)(c0 + r) * 64 + q * 8);
            CP_ASYNC16(vh_d + r * 144 + q * 16, Vh_g + (long)(c0 + r) * 64 + q * 8);
        }
    };

#pragma unroll 1
    for (int phase = 0; phase < nq; phase++) {
        const int qb = qlist[phase];
        const int d0 = qb * 128;
        const int tstart = (qb == 15) ? 0 : 2 * qb;
        const int mlast = 2 * qb + 1;    // tiles t <= mlast need masking

        // Q tile: 128 rows x 64 cols
#pragma unroll
        for (int l = 0; l < 8; l++) {
            int e = tid + l * 128;
            int r = e >> 3, q = (e & 7) * 8;
            long g = ((long)bh * C_ + d0 + r) * 64 + q;
            *reinterpret_cast<uint4*>(&sQh[r * 72 + q]) =
                *reinterpret_cast<const uint4*>(&qh_g[g]);
        }
        issue(tstart, tstart & 1);
        CP_COMMIT();
        __syncthreads();

        uint32_t qh[4][2][4];
#pragma unroll
        for (int ks = 0; ks < 4; ks++)
#pragma unroll
            for (int mt = 0; mt < 2; mt++) {
                const uint32_t off =
                    (uint32_t)((dtile + mt * 16 + lane15) * 72 + ks * 16 + aK) * 2;
                ldsm_x4(qh[ks][mt], sb + AT_QH + off);
            }

        float oacc[2][8][4];
#pragma unroll
        for (int mt = 0; mt < 2; mt++)
#pragma unroll
            for (int i = 0; i < 8; i++)
#pragma unroll
                for (int j = 0; j < 4; j++) oacc[mt][i][j] = 0.0f;
        float mrow[4] = {-1e30f, -1e30f, -1e30f, -1e30f};
        float lrow[4] = {0.0f, 0.0f, 0.0f, 0.0f};

        for (int t = tstart; t < ntiles; t++) {
            if (t + 1 < ntiles) {
                issue(t + 1, (t + 1) & 1);
                CP_COMMIT();
                CP_WAIT1();
            } else {
                CP_WAIT0();
            }
            __syncthreads();

            const int s = t & 1;
            const uint32_t sKh_b = sb + AT_KH + s * ATA;
            const uint32_t sVh_b = sb + AT_VH + s * ATA;

            // ---- S = Q @ K^T ----
            float sacc[2][8][4];
#pragma unroll
            for (int mt = 0; mt < 2; mt++)
#pragma unroll
                for (int i = 0; i < 8; i++)
#pragma unroll
                    for (int j = 0; j < 4; j++) sacc[mt][i][j] = 0.0f;
#pragma unroll
            for (int ks = 0; ks < 4; ks++) {
                const int kB = ks * 16 + bK;
#pragma unroll
                for (int ntp = 0; ntp < 4; ntp++) {
                    const uint32_t off = (uint32_t)((ntp * 16 + bN) * 72 + kB) * 2;
                    uint32_t bhf[4];
                    ldsm_x4(bhf, sKh_b + off);
#pragma unroll
                    for (int h2 = 0; h2 < 2; h2++)
#pragma unroll
                        for (int mt = 0; mt < 2; mt++)
                            mma16816(sacc[mt][ntp * 2 + h2], qh[ks][mt],
                                     bhf + h2 * 2);
                }
            }

            // ---- scale (base-2) always; mask on tiles t <= 2qb+1 ----
#pragma unroll
            for (int mt = 0; mt < 2; mt++)
#pragma unroll
                for (int nt = 0; nt < 8; nt++)
#pragma unroll
                    for (int j = 0; j < 4; j++) sacc[mt][nt][j] *= R2_;
            if (t <= mlast) {
                const int c0 = t * 64;
#pragma unroll
                for (int mt = 0; mt < 2; mt++) {
                    const int dg0 = d0 + dtile + mt * 16 + lq;
                    const int dg1 = dg0 + 8;
#pragma unroll
                    for (int nt = 0; nt < 8; nt++) {
                        const int cg = c0 + nt * 8 + lr * 2;
                        if (cg     <= dg0) sacc[mt][nt][0] -= MB2_;
                        if (cg + 1 <= dg0) sacc[mt][nt][1] -= MB2_;
                        if (cg     <= dg1) sacc[mt][nt][2] -= MB2_;
                        if (cg + 1 <= dg1) sacc[mt][nt][3] -= MB2_;
                    }
                }
            }

            // ---- register softmax (base-2, quad shuffles) ----
#pragma unroll
            for (int mt = 0; mt < 2; mt++) {
                float mt0 = sacc[mt][0][0], mt1 = sacc[mt][0][2];
#pragma unroll
                for (int nt = 0; nt < 8; nt++) {
                    mt0 = fmaxf(mt0, fmaxf(sacc[mt][nt][0], sacc[mt][nt][1]));
                    mt1 = fmaxf(mt1, fmaxf(sacc[mt][nt][2], sacc[mt][nt][3]));
                }
                mt0 = fmaxf(mt0, __shfl_xor_sync(0xffffffff, mt0, 1));
                mt0 = fmaxf(mt0, __shfl_xor_sync(0xffffffff, mt0, 2));
                mt1 = fmaxf(mt1, __shfl_xor_sync(0xffffffff, mt1, 1));
                mt1 = fmaxf(mt1, __shfl_xor_sync(0xffffffff, mt1, 2));
                const int u0 = mt * 2, u1 = mt * 2 + 1;
                const float mn0 = fmaxf(mrow[u0], mt0);
                const float mn1 = fmaxf(mrow[u1], mt1);
                const float a0 = exp2f(mrow[u0] - mn0);
                const float a1 = exp2f(mrow[u1] - mn1);
                float s0 = 0.0f, s1 = 0.0f;
#pragma unroll
                for (int nt = 0; nt < 8; nt++) {
                    sacc[mt][nt][0] = exp2f(sacc[mt][nt][0] - mn0); s0 += sacc[mt][nt][0];
                    sacc[mt][nt][1] = exp2f(sacc[mt][nt][1] - mn0); s0 += sacc[mt][nt][1];
                    sacc[mt][nt][2] = exp2f(sacc[mt][nt][2] - mn1); s1 += sacc[mt][nt][2];
                    sacc[mt][nt][3] = exp2f(sacc[mt][nt][3] - mn1); s1 += sacc[mt][nt][3];
                }
                s0 += __shfl_xor_sync(0xffffffff, s0, 1);
                s0 += __shfl_xor_sync(0xffffffff, s0, 2);
                s1 += __shfl_xor_sync(0xffffffff, s1, 1);
                s1 += __shfl_xor_sync(0xffffffff, s1, 2);
                lrow[u0] = lrow[u0] * a0 + s0;
                lrow[u1] = lrow[u1] * a1 + s1;
                mrow[u0] = mn0; mrow[u1] = mn1;
#pragma unroll
                for (int nt = 0; nt < 8; nt++) {
                    oacc[mt][nt][0] *= a0; oacc[mt][nt][1] *= a0;
                    oacc[mt][nt][2] *= a1; oacc[mt][nt][3] *= a1;
                }
            }

            // ---- O += P @ V (V via trans-ldsm from [c][v]) ----
#pragma unroll
            for (int ks = 0; ks < 4; ks++) {
                uint32_t ph[2][4];
#pragma unroll
                for (int mt = 0; mt < 2; mt++) {
                    ph[mt][0] = packh2(sacc[mt][2 * ks][0],     sacc[mt][2 * ks][1]);
                    ph[mt][1] = packh2(sacc[mt][2 * ks][2],     sacc[mt][2 * ks][3]);
                    ph[mt][2] = packh2(sacc[mt][2 * ks + 1][0], sacc[mt][2 * ks + 1][1]);
                    ph[mt][3] = packh2(sacc[mt][2 * ks + 1][2], sacc[mt][2 * ks + 1][3]);
                }
#pragma unroll
                for (int ntp = 0; ntp < 4; ntp++) {
                    const uint32_t off =
                        (uint32_t)((ks * 16 + tRow) * 72 + ntp * 16 + tN) * 2;
                    uint32_t bhf[4];
                    ldsm_x4_trans(bhf, sVh_b + off);
#pragma unroll
                    for (int h2 = 0; h2 < 2; h2++)
#pragma unroll
                        for (int mt = 0; mt < 2; mt++)
                            mma16816(oacc[mt][ntp * 2 + h2], ph[mt], bhf + h2 * 2);
                }
            }
            __syncthreads();
        }

        // ---- epilogue -> pre ----
#pragma unroll
        for (int mt = 0; mt < 2; mt++) {
            const float il0 = 1.0f / lrow[mt * 2];
            const float il1 = 1.0f / lrow[mt * 2 + 1];
            const int row0g = d0 + dtile + mt * 16 + lq;
#pragma unroll
            for (int nt = 0; nt < 8; nt++) {
                const int col = h * 64 + nt * 8 + lr * 2;
                const long i0 = ((long)(b * C_ + row0g)) * (H_ * V_) + col;
                const long i1 = ((long)(b * C_ + row0g + 8)) * (H_ * V_) + col;
                *reinterpret_cast<uint32_t*>(&pre_g[i0]) =
                    packh2(oacc[mt][nt][0] * il0, oacc[mt][nt][1] * il0);
                *reinterpret_cast<uint32_t*>(&pre_g[i1]) =
                    packh2(oacc[mt][nt][2] * il1, oacc[mt][nt][3] * il1);
            }
        }
    }
}

// ---------------------------------------------------------------------------

extern "C" void kernel_launch(void* const* d_in, const int* in_sizes, int n_in,
                              void* d_out, int out_size)
{
    const float* kvinput = (const float*)d_in[0];
    const float* qinput  = (const float*)d_in[1];
    const float* wq      = (const float*)d_in[2];
    const float* wk      = (const float*)d_in[3];
    const float* wv      = (const float*)d_in[4];
    const float* wo      = (const float*)d_in[5];
    float* out = (float*)d_out;

    __half *xqh, *xkh, *wqh, *wkvh, *woh;
    __half *qh, *kvh, *prh;
    cudaGetSymbolAddress((void**)&xqh, s_xq_h);
    cudaGetSymbolAddress((void**)&xkh, s_xkv_h);
    cudaGetSymbolAddress((void**)&wqh, s_wqT_h);
    cudaGetSymbolAddress((void**)&wkvh, s_wkvT_h);
    cudaGetSymbolAddress((void**)&woh, s_woT_h);
    cudaGetSymbolAddress((void**)&qh,  s_q_h);
    cudaGetSymbolAddress((void**)&kvh, s_kv_h);
    cudaGetSymbolAddress((void**)&prh, s_pre_h);

    cudaFuncSetAttribute(proj_kernel,
                         cudaFuncAttributeMaxDynamicSharedMemorySize, GEMM_SMEM3);
    cudaFuncSetAttribute(outproj_kernel,
                         cudaFuncAttributeMaxDynamicSharedMemorySize, GEMM_SMEM3);
    cudaFuncSetAttribute(attn_kernel,
                         cudaFuncAttributeMaxDynamicSharedMemorySize, AT_TOTAL);

    // launch 0: convert inputs to fp16
    {
        int n4 = B_ * C_ * M_ / 4;
        cvt2_kernel<<<(2 * n4 + 255) / 256, 256>>>(qinput, kvinput, xqh, xkh, n4);
    }
    // launch 1: all weight transposes
    {
        dim3 tb(32, 8);
        trans_all_kernel<<<4096, tb>>>(wq, wk, wv, wo, wqh, wkvh, woh);
    }
    // launch 2: merged Q + KV projections
    {
        dim3 pg(C_ / 128, 24, B_);
        proj_kernel<<<pg, 128, GEMM_SMEM3>>>(xqh, xkh, wqh, wkvh, qh, kvh);
    }
    // launch 3: attention (9 balanced work-units per (b,h))
    {
        dim3 ag(9, H_, B_);
        attn_kernel<<<ag, 128, AT_TOTAL>>>(qh, kvh, prh);
    }
    // launch 4: output projection
    {
        dim3 og((B_ * C_) / 128, M_ / 128, 1);
        outproj_kernel<<<og, 128, GEMM_SMEM3>>>(prh, woh, out);
    }
}